// round 6
// baseline (speedup 1.0000x reference)
#include <cuda_runtime.h>
#include <cuda_bf16.h>
#include <math.h>
#include <stdint.h>

#define S_LEN 8704
#define DIMV  1024
#define NH    16
#define HD    64
#define SD    4608   // dilated stream length (incl. zero padding block)
#define SREAL 4352   // real tokens per stream
#define WIN   512
#define BQ    128
#define BK    64

// fp32 activation buffers
__device__ float g_q[S_LEN * DIMV];
__device__ float g_k[S_LEN * DIMV];

// bf16 split activations
__device__ __nv_bfloat16 g_ahi[S_LEN * DIMV];
__device__ __nv_bfloat16 g_alo[S_LEN * DIMV];
__device__ __nv_bfloat16 g_qhi[S_LEN * DIMV];
__device__ __nv_bfloat16 g_qlo[S_LEN * DIMV];
__device__ __nv_bfloat16 g_khi[S_LEN * DIMV];
__device__ __nv_bfloat16 g_klo[S_LEN * DIMV];
__device__ __nv_bfloat16 g_vhi[S_LEN * DIMV];
__device__ __nv_bfloat16 g_vlo[S_LEN * DIMV];

// bf16 split transposed weights [N][K]
__device__ __nv_bfloat16 g_wqT_hi[DIMV * DIMV];
__device__ __nv_bfloat16 g_wqT_lo[DIMV * DIMV];
__device__ __nv_bfloat16 g_wkT_hi[DIMV * DIMV];
__device__ __nv_bfloat16 g_wkT_lo[DIMV * DIMV];
__device__ __nv_bfloat16 g_wvT_hi[DIMV * DIMV];
__device__ __nv_bfloat16 g_wvT_lo[DIMV * DIMV];
__device__ __nv_bfloat16 g_woT_hi[DIMV * DIMV];
__device__ __nv_bfloat16 g_woT_lo[DIMV * DIMV];

__device__ __forceinline__ int dil2orig(int d, int p) {
    return ((p >> 8) << 9) + (d << 8) + (p & 255);
}

__device__ __forceinline__ uint32_t smem_to_u32(const void* smem_ptr) {
    uint32_t addr;
    asm("{ .reg .u64 tmp; cvta.to.shared.u64 tmp, %1; cvt.u32.u64 %0, tmp; }"
        : "=r"(addr) : "l"(smem_ptr));
    return addr;
}

// ===========================================================================
// family-generic tensor-core primitives
// ===========================================================================
__device__ __forceinline__ void ldsm4(uint32_t* r, uint32_t addr) {
    asm volatile("ldmatrix.sync.aligned.m8n8.x4.shared.b16 {%0,%1,%2,%3}, [%4];\n"
                 : "=r"(r[0]), "=r"(r[1]), "=r"(r[2]), "=r"(r[3]) : "r"(addr));
}
__device__ __forceinline__ void ldsm4t(uint32_t* r, uint32_t addr) {
    asm volatile("ldmatrix.sync.aligned.m8n8.x4.trans.shared.b16 {%0,%1,%2,%3}, [%4];\n"
                 : "=r"(r[0]), "=r"(r[1]), "=r"(r[2]), "=r"(r[3]) : "r"(addr));
}
__device__ __forceinline__ void mma16816(float* c, const uint32_t* a,
                                         uint32_t b0, uint32_t b1) {
    asm volatile(
        "mma.sync.aligned.m16n8k16.row.col.f32.bf16.bf16.f32 "
        "{%0,%1,%2,%3}, {%4,%5,%6,%7}, {%8,%9}, {%0,%1,%2,%3};\n"
        : "+f"(c[0]), "+f"(c[1]), "+f"(c[2]), "+f"(c[3])
        : "r"(a[0]), "r"(a[1]), "r"(a[2]), "r"(a[3]), "r"(b0), "r"(b1));
}
__device__ __forceinline__ void cp_async16(uint32_t saddr, const void* gptr) {
    asm volatile("cp.async.cg.shared.global [%0], [%1], 16;\n"
                 :: "r"(saddr), "l"(gptr));
}
__device__ __forceinline__ void cp_async16z(uint32_t saddr, const void* gptr, int srcbytes) {
    asm volatile("cp.async.cg.shared.global [%0], [%1], 16, %2;\n"
                 :: "r"(saddr), "l"(gptr), "r"(srcbytes));
}
#define CP_COMMIT() asm volatile("cp.async.commit_group;\n" ::: "memory")
#define CP_WAIT0()  asm volatile("cp.async.wait_group 0;\n" ::: "memory")

// gemm smem tile layout: 128 rows x 32 bf16 (4 x 16B chunks/row)
__device__ __forceinline__ uint32_t sw_off(int r, int c) {
    return (uint32_t)(((r >> 1) << 7) + ((r & 1) << 6) +
                      (((c ^ ((r >> 1) & 3)) & 3) << 4));
}
// attn smem tile layout: rows x 64 bf16 (8 x 16B chunks/row), xor swizzle
__device__ __forceinline__ uint32_t att_off(int r, int ch) {
    return (uint32_t)((r << 7) + (((ch ^ (r & 7)) & 7) << 4));
}

__device__ __forceinline__ uint32_t pack_bf16x2(float a, float b) {
    __nv_bfloat162 t = __floats2bfloat162_rn(a, b);
    return *(uint32_t*)&t;
}

// ===========================================================================
// bf16 split helpers
// ===========================================================================
__device__ __forceinline__ void bsplit(float f, __nv_bfloat16& h, __nv_bfloat16& l) {
    h = __float2bfloat16(f);
    l = __float2bfloat16(f - __bfloat162float(h));
}

struct __align__(8) B4 { __nv_bfloat16 v[4]; };

__global__ __launch_bounds__(256) void split_kernel(
    const float* __restrict__ src, __nv_bfloat16* __restrict__ hi,
    __nv_bfloat16* __restrict__ lo) {
    const int idx = blockIdx.x * 256 + threadIdx.x;
    float4 v = ((const float4*)src)[idx];
    B4 h, l;
    bsplit(v.x, h.v[0], l.v[0]);
    bsplit(v.y, h.v[1], l.v[1]);
    bsplit(v.z, h.v[2], l.v[2]);
    bsplit(v.w, h.v[3], l.v[3]);
    ((B4*)hi)[idx] = h;
    ((B4*)lo)[idx] = l;
}

// transpose + split: w[K][N] fp32 -> hiT/loT [N][K] bf16
__global__ __launch_bounds__(256) void wsplit_kernel(
    const float* __restrict__ w, __nv_bfloat16* __restrict__ hiT,
    __nv_bfloat16* __restrict__ loT) {
    __shared__ float t[32][33];
    const int bx = blockIdx.x << 5;
    const int by = blockIdx.y << 5;
    const int tx = threadIdx.x, ty = threadIdx.y;
#pragma unroll
    for (int i = 0; i < 32; i += 8)
        t[ty + i][tx] = w[(size_t)(by + ty + i) * DIMV + bx + tx];
    __syncthreads();
#pragma unroll
    for (int i = 0; i < 32; i += 8) {
        const float f = t[tx][ty + i];
        __nv_bfloat16 h, l;
        bsplit(f, h, l);
        const size_t o = (size_t)(bx + ty + i) * DIMV + by + tx;
        hiT[o] = h;
        loT[o] = l;
    }
}

// ===========================================================================
// HMMA split-precision GEMM. Optional split-bf16 output (Chi/Clo non-null).
// ===========================================================================
#define STAGE_BYTES 32768
#define GEMM_SMEM_REQ (2 * STAGE_BYTES)

__device__ __forceinline__ void load_stage(
    uint32_t sbase, const __nv_bfloat16* __restrict__ Ahi,
    const __nv_bfloat16* __restrict__ Alo,
    const __nv_bfloat16* __restrict__ Bhi,
    const __nv_bfloat16* __restrict__ Blo,
    int bm, int bn, int k0, int tid) {
#pragma unroll
    for (int j = 0; j < 8; j++) {
        const int chunk = tid + (j << 8);
        const int tile = chunk >> 9;
        const int idx = chunk & 511;
        const int r = idx >> 2, c = idx & 3;
        const uint32_t saddr = sbase + (uint32_t)(tile << 13) + sw_off(r, c);
        const __nv_bfloat16* gp;
        if (tile == 0)      gp = Ahi + (size_t)(bm + r) * DIMV + k0 + c * 8;
        else if (tile == 1) gp = Alo + (size_t)(bm + r) * DIMV + k0 + c * 8;
        else if (tile == 2) gp = Bhi + (size_t)(bn + r) * DIMV + k0 + c * 8;
        else                gp = Blo + (size_t)(bn + r) * DIMV + k0 + c * 8;
        cp_async16(saddr, gp);
    }
}

__global__ __launch_bounds__(256, 2)
void gemm_mma_kernel(const __nv_bfloat16* __restrict__ Ahi,
                     const __nv_bfloat16* __restrict__ Alo,
                     const __nv_bfloat16* __restrict__ Bhi,
                     const __nv_bfloat16* __restrict__ Blo,
                     const float* __restrict__ bias,
                     float* __restrict__ C,
                     __nv_bfloat16* __restrict__ Chi,
                     __nv_bfloat16* __restrict__ Clo) {
    extern __shared__ char smem[];
    const uint32_t sb = smem_to_u32(smem);
    const int tid = threadIdx.x;
    const int bn = blockIdx.x << 7;
    const int bm = blockIdx.y << 7;
    const int wid = tid >> 5, lane = tid & 31;
    const int wm = (wid & 1) << 6;
    const int wn = (wid >> 1) << 5;
    const int lr = lane & 15;
    const int lhalf = lane >> 4;

    float acc[4][4][4];
#pragma unroll
    for (int i = 0; i < 4; i++)
#pragma unroll
        for (int j = 0; j < 4; j++)
#pragma unroll
            for (int k = 0; k < 4; k++) acc[i][j][k] = 0.f;

    load_stage(sb, Ahi, Alo, Bhi, Blo, bm, bn, 0, tid);
    CP_COMMIT();

    for (int s = 0; s < 32; s++) {
        CP_WAIT0();
        __syncthreads();
        if (s + 1 < 32) {
            load_stage(sb + ((s + 1) & 1) * STAGE_BYTES, Ahi, Alo, Bhi, Blo,
                       bm, bn, (s + 1) << 5, tid);
            CP_COMMIT();
        }

        const uint32_t buf = sb + (s & 1) * STAGE_BYTES;
#pragma unroll
        for (int kk = 0; kk < 2; kk++) {
            const int cb = (kk << 1) + lhalf;
            uint32_t a[4][4], b[2][4];
#pragma unroll
            for (int mi = 0; mi < 4; mi++)
                ldsm4(a[mi], buf + sw_off(wm + (mi << 4) + lr, cb));
#pragma unroll
            for (int np = 0; np < 2; np++)
                ldsm4(b[np], buf + 16384 + sw_off(wn + (np << 4) + lr, cb));
#pragma unroll
            for (int mi = 0; mi < 4; mi++) {
                mma16816(acc[mi][0], a[mi], b[0][0], b[0][2]);
                mma16816(acc[mi][1], a[mi], b[0][1], b[0][3]);
                mma16816(acc[mi][2], a[mi], b[1][0], b[1][2]);
                mma16816(acc[mi][3], a[mi], b[1][1], b[1][3]);
            }
            // Ahi x Blo
#pragma unroll
            for (int np = 0; np < 2; np++)
                ldsm4(b[np], buf + 24576 + sw_off(wn + (np << 4) + lr, cb));
#pragma unroll
            for (int mi = 0; mi < 4; mi++) {
                mma16816(acc[mi][0], a[mi], b[0][0], b[0][2]);
                mma16816(acc[mi][1], a[mi], b[0][1], b[0][3]);
                mma16816(acc[mi][2], a[mi], b[1][0], b[1][2]);
                mma16816(acc[mi][3], a[mi], b[1][1], b[1][3]);
            }
            // Alo x Bhi
#pragma unroll
            for (int mi = 0; mi < 4; mi++)
                ldsm4(a[mi], buf + 8192 + sw_off(wm + (mi << 4) + lr, cb));
#pragma unroll
            for (int np = 0; np < 2; np++)
                ldsm4(b[np], buf + 16384 + sw_off(wn + (np << 4) + lr, cb));
#pragma unroll
            for (int mi = 0; mi < 4; mi++) {
                mma16816(acc[mi][0], a[mi], b[0][0], b[0][2]);
                mma16816(acc[mi][1], a[mi], b[0][1], b[0][3]);
                mma16816(acc[mi][2], a[mi], b[1][0], b[1][2]);
                mma16816(acc[mi][3], a[mi], b[1][1], b[1][3]);
            }
        }
        __syncthreads();
    }

    const int crow = lane >> 2;
    const int ccol = (lane & 3) << 1;
#pragma unroll
    for (int ni = 0; ni < 4; ni++) {
        const int col = bn + wn + (ni << 3) + ccol;
        const float2 bv = *(const float2*)&bias[col];
#pragma unroll
        for (int mi = 0; mi < 4; mi++) {
            const int row = bm + wm + (mi << 4) + crow;
            const float v00 = acc[mi][ni][0] + bv.x, v01 = acc[mi][ni][1] + bv.y;
            const float v10 = acc[mi][ni][2] + bv.x, v11 = acc[mi][ni][3] + bv.y;
            if (Chi) {
                const float h00 = __bfloat162float(__float2bfloat16(v00));
                const float h01 = __bfloat162float(__float2bfloat16(v01));
                const float h10 = __bfloat162float(__float2bfloat16(v10));
                const float h11 = __bfloat162float(__float2bfloat16(v11));
                *(uint32_t*)&Chi[(size_t)row * DIMV + col] = pack_bf16x2(h00, h01);
                *(uint32_t*)&Clo[(size_t)row * DIMV + col] = pack_bf16x2(v00 - h00, v01 - h01);
                *(uint32_t*)&Chi[(size_t)(row + 8) * DIMV + col] = pack_bf16x2(h10, h11);
                *(uint32_t*)&Clo[(size_t)(row + 8) * DIMV + col] = pack_bf16x2(v10 - h10, v11 - h11);
            } else {
                *(float2*)&C[(size_t)row * DIMV + col] = make_float2(v00, v01);
                *(float2*)&C[(size_t)(row + 8) * DIMV + col] = make_float2(v10, v11);
            }
        }
    }
}

// ---------------------------------------------------------------------------
// Fused RMSNorm + RoPE, writes bf16 hi/lo (scale folded in). 1 block/token.
// ---------------------------------------------------------------------------
__global__ __launch_bounds__(256) void normrope_split_kernel(
    const float* __restrict__ src, const float* __restrict__ g,
    const float* __restrict__ cs, const float* __restrict__ sn,
    __nv_bfloat16* __restrict__ hi, __nv_bfloat16* __restrict__ lo,
    float scale) {
    const int s = blockIdx.x;
    const int tid = threadIdx.x;

    float4 v = *(const float4*)&src[(size_t)s * DIMV + (tid << 2)];
    float ss = v.x * v.x + v.y * v.y + v.z * v.z + v.w * v.w;
#pragma unroll
    for (int o = 16; o; o >>= 1) ss += __shfl_xor_sync(0xffffffffu, ss, o);

    __shared__ float red[8];
    __shared__ float rtot;
    if ((tid & 31) == 0) red[tid >> 5] = ss;
    __syncthreads();
    if (tid == 0) {
        float t = 0.f;
#pragma unroll
        for (int i = 0; i < 8; i++) t += red[i];
        rtot = rsqrtf(t * (1.0f / 1024.0f) + 1e-6f);
    }
    __syncthreads();
    const float r = rtot;

    float4 gv = *(const float4*)&g[tid << 2];
    const float a0 = v.x * r * gv.x, b0 = v.y * r * gv.y;
    const float a1 = v.z * r * gv.z, b1 = v.w * r * gv.w;

    const int p0 = tid << 1;
    const int r0 = p0 & 31, r1 = (p0 + 1) & 31;
    const float c0 = cs[s * 32 + r0], s0 = sn[s * 32 + r0];
    const float c1 = cs[s * 32 + r1], s1 = sn[s * 32 + r1];

    float o0 = (a0 * c0 - b0 * s0) * scale;
    float o1 = (a0 * s0 + b0 * c0) * scale;
    float o2 = (a1 * c1 - b1 * s1) * scale;
    float o3 = (a1 * s1 + b1 * c1) * scale;

    B4 h, l;
    bsplit(o0, h.v[0], l.v[0]);
    bsplit(o1, h.v[1], l.v[1]);
    bsplit(o2, h.v[2], l.v[2]);
    bsplit(o3, h.v[3], l.v[3]);
    const size_t idx = (size_t)s * (DIMV / 4) + tid;
    ((B4*)hi)[idx] = h;
    ((B4*)lo)[idx] = l;
}

// ===========================================================================
// Tensor-core flash attention. Grid (34, 16, 2), 256 threads (8 warps),
// 128 queries/CTA, K/V tiles of 64.
// ===========================================================================
#define ATT_STAGE 32768
#define ATT_SMEM  (32768 + 2 * ATT_STAGE)

__global__ __launch_bounds__(256)
void attn_tc_kernel(const __nv_bfloat16* __restrict__ qhi, const __nv_bfloat16* __restrict__ qlo,
                    const __nv_bfloat16* __restrict__ khi, const __nv_bfloat16* __restrict__ klo,
                    const __nv_bfloat16* __restrict__ vhi, const __nv_bfloat16* __restrict__ vlo,
                    __nv_bfloat16* __restrict__ ohi, __nv_bfloat16* __restrict__ olo) {
    extern __shared__ char smem[];
    const uint32_t sb = smem_to_u32(smem);
    const int d = blockIdx.z, h = blockIdx.y;
    const int q0 = blockIdx.x << 7;
    const int tid = threadIdx.x;
    const int warp = tid >> 5, lane = tid & 31;
    const int wq = warp << 4;
    const int lr = lane & 15, lhf = lane >> 4;
    const int qr = lane >> 2, qc = (lane & 3) << 1;

    // --- load Q hi/lo tiles (128 x 64) into smem once ---
#pragma unroll
    for (int t = 0; t < 4; t++) {
        const int idx = tid + (t << 8);
        const int r = idx >> 3, ch = idx & 7;
        const int tok = dil2orig(d, q0 + r);
        const size_t go = (size_t)tok * DIMV + h * HD + (ch << 3);
        *(uint4*)(smem + att_off(r, ch)) = *(const uint4*)&qhi[go];
        *(uint4*)(smem + 16384 + att_off(r, ch)) = *(const uint4*)&qlo[go];
    }
    __syncthreads();

    uint32_t qh[4][4], ql[4][4];
#pragma unroll
    for (int s = 0; s < 4; s++) {
        ldsm4(qh[s], sb + att_off(wq + lr, (s << 1) + lhf));
        ldsm4(ql[s], sb + 16384 + att_off(wq + lr, (s << 1) + lhf));
    }

    float m0 = -1e30f, m1 = -1e30f, l0 = 0.f, l1 = 0.f;
    float o[8][4];
#pragma unroll
    for (int j = 0; j < 8; j++)
#pragma unroll
        for (int k = 0; k < 4; k++) o[j][k] = 0.f;

    const int kt_lo = (q0 >= WIN) ? (q0 - WIN) : 0;
    const int kt_hi = min(SD, q0 + BQ + WIN);
    const int row0 = q0 + wq + qr, row1 = row0 + 8;

    auto stage_load = [&](int st, int kt) {
        const uint32_t stg = sb + 32768 + st * ATT_STAGE;
#pragma unroll
        for (int t = 0; t < 8; t++) {
            const int cid = tid + (t << 8);
            const int buf = cid >> 9;
            const int idx = cid & 511;
            const int r = idx >> 3, ch = idx & 7;
            const int pk = kt + r;
            const int ok = pk < SREAL;
            const int tok = ok ? dil2orig(d, pk) : 0;
            const size_t go = (size_t)tok * DIMV + h * HD + (ch << 3);
            const __nv_bfloat16* src = (buf == 0) ? khi : (buf == 1) ? klo
                                      : (buf == 2) ? vhi : vlo;
            cp_async16z(stg + (buf << 13) + att_off(r, ch), src + go, ok ? 16 : 0);
        }
    };

    stage_load(0, kt_lo);
    CP_COMMIT();

    int st = 0;
    for (int kt = kt_lo; kt < kt_hi; kt += BK, st ^= 1) {
        CP_WAIT0();
        __syncthreads();
        if (kt + BK < kt_hi) { stage_load(st ^ 1, kt + BK); CP_COMMIT(); }

        const uint32_t sK  = sb + 32768 + st * ATT_STAGE;
        const uint32_t sKl = sK + 8192, sV = sK + 16384, sVl = sK + 24576;

        // --- scores ---
        float c[8][4];
#pragma unroll
        for (int j = 0; j < 8; j++)
#pragma unroll
            for (int k = 0; k < 4; k++) c[j][k] = 0.f;

#pragma unroll
        for (int s = 0; s < 4; s++) {
#pragma unroll
            for (int g = 0; g < 4; g++) {
                uint32_t bh[4], bl[4];
                ldsm4(bh, sK + att_off((g << 4) + lr, (s << 1) + lhf));
                ldsm4(bl, sKl + att_off((g << 4) + lr, (s << 1) + lhf));
                mma16816(c[2 * g],     qh[s], bh[0], bh[2]);
                mma16816(c[2 * g + 1], qh[s], bh[1], bh[3]);
                mma16816(c[2 * g],     ql[s], bh[0], bh[2]);
                mma16816(c[2 * g + 1], ql[s], bh[1], bh[3]);
                mma16816(c[2 * g],     qh[s], bl[0], bl[2]);
                mma16816(c[2 * g + 1], qh[s], bl[1], bl[3]);
            }
        }

        // --- window mask (edge tiles only) ---
        const bool edge = (kt < q0 + BQ - 1 - WIN) || (kt + BK - 1 > q0 + WIN);
        if (edge) {
#pragma unroll
            for (int j = 0; j < 8; j++) {
                const int pk = kt + (j << 3) + qc;
                if (abs(row0 - pk) > WIN)       c[j][0] = -1e9f;
                if (abs(row0 - pk - 1) > WIN)   c[j][1] = -1e9f;
                if (abs(row1 - pk) > WIN)       c[j][2] = -1e9f;
                if (abs(row1 - pk - 1) > WIN)   c[j][3] = -1e9f;
            }
        }

        // --- online softmax ---
        float tm0 = -1e30f, tm1 = -1e30f;
#pragma unroll
        for (int j = 0; j < 8; j++) {
            tm0 = fmaxf(tm0, fmaxf(c[j][0], c[j][1]));
            tm1 = fmaxf(tm1, fmaxf(c[j][2], c[j][3]));
        }
        tm0 = fmaxf(tm0, __shfl_xor_sync(0xffffffffu, tm0, 1));
        tm0 = fmaxf(tm0, __shfl_xor_sync(0xffffffffu, tm0, 2));
        tm1 = fmaxf(tm1, __shfl_xor_sync(0xffffffffu, tm1, 1));
        tm1 = fmaxf(tm1, __shfl_xor_sync(0xffffffffu, tm1, 2));

        const float mn0 = fmaxf(m0, tm0), mn1 = fmaxf(m1, tm1);
        const float cor0 = __expf(m0 - mn0), cor1 = __expf(m1 - mn1);
        m0 = mn0; m1 = mn1;

        float s0 = 0.f, s1 = 0.f;
#pragma unroll
        for (int j = 0; j < 8; j++) {
            c[j][0] = __expf(c[j][0] - mn0);
            c[j][1] = __expf(c[j][1] - mn0);
            c[j][2] = __expf(c[j][2] - mn1);
            c[j][3] = __expf(c[j][3] - mn1);
            s0 += c[j][0] + c[j][1];
            s1 += c[j][2] + c[j][3];
        }
        s0 += __shfl_xor_sync(0xffffffffu, s0, 1);
        s0 += __shfl_xor_sync(0xffffffffu, s0, 2);
        s1 += __shfl_xor_sync(0xffffffffu, s1, 1);
        s1 += __shfl_xor_sync(0xffffffffu, s1, 2);
        l0 = l0 * cor0 + s0;
        l1 = l1 * cor1 + s1;
#pragma unroll
        for (int j = 0; j < 8; j++) {
            o[j][0] *= cor0; o[j][1] *= cor0;
            o[j][2] *= cor1; o[j][3] *= cor1;
        }

        // --- PV ---
#pragma unroll
        for (int s = 0; s < 4; s++) {
            uint32_t ah[4], al[4];
#pragma unroll
            for (int half = 0; half < 2; half++) {
                const int j = 2 * s + half;
                const float p0 = c[j][0], p1 = c[j][1];
                const float p2 = c[j][2], p3 = c[j][3];
                const float h0 = __bfloat162float(__float2bfloat16(p0));
                const float h1 = __bfloat162float(__float2bfloat16(p1));
                const float h2 = __bfloat162float(__float2bfloat16(p2));
                const float h3 = __bfloat162float(__float2bfloat16(p3));
                ah[2 * half]     = pack_bf16x2(h0, h1);
                ah[2 * half + 1] = pack_bf16x2(h2, h3);
                al[2 * half]     = pack_bf16x2(p0 - h0, p1 - h1);
                al[2 * half + 1] = pack_bf16x2(p2 - h2, p3 - h3);
            }
#pragma unroll
            for (int g = 0; g < 4; g++) {
                uint32_t bh[4], bl[4];
                ldsm4t(bh, sV + att_off((s << 4) + lr, (g << 1) + lhf));
                ldsm4t(bl, sVl + att_off((s << 4) + lr, (g << 1) + lhf));
                mma16816(o[2 * g],     ah, bh[0], bh[1]);
                mma16816(o[2 * g + 1], ah, bh[2], bh[3]);
                mma16816(o[2 * g],     al, bh[0], bh[1]);
                mma16816(o[2 * g + 1], al, bh[2], bh[3]);
                mma16816(o[2 * g],     ah, bl[0], bl[1]);
                mma16816(o[2 * g + 1], ah, bl[2], bl[3]);
            }
        }
        __syncthreads();
    }

    // --- epilogue: normalize, split to bf16 hi/lo, store ---
    const float inv0 = 1.0f / l0, inv1 = 1.0f / l1;
    const int tok0 = dil2orig(d, row0);
    const int tok1 = dil2orig(d, row1);
#pragma unroll
    for (int j = 0; j < 8; j++) {
        const int col = h * HD + (j << 3) + qc;
        const float a0 = o[j][0] * inv0, a1 = o[j][1] * inv0;
        const float b0 = o[j][2] * inv1, b1 = o[j][3] * inv1;
        const float a0h = __bfloat162float(__float2bfloat16(a0));
        const float a1h = __bfloat162float(__float2bfloat16(a1));
        const float b0h = __bfloat162float(__float2bfloat16(b0));
        const float b1h = __bfloat162float(__float2bfloat16(b1));
        *(uint32_t*)&ohi[(size_t)tok0 * DIMV + col] = pack_bf16x2(a0h, a1h);
        *(uint32_t*)&olo[(size_t)tok0 * DIMV + col] = pack_bf16x2(a0 - a0h, a1 - a1h);
        *(uint32_t*)&ohi[(size_t)tok1 * DIMV + col] = pack_bf16x2(b0h, b1h);
        *(uint32_t*)&olo[(size_t)tok1 * DIMV + col] = pack_bf16x2(b0 - b0h, b1 - b1h);
    }
}

// ---------------------------------------------------------------------------
extern "C" void kernel_launch(void* const* d_in, const int* in_sizes, int n_in,
                              void* d_out, int out_size) {
    (void)in_sizes; (void)n_in; (void)out_size;
    const float* x  = (const float*)d_in[0];
    const float* fc = (const float*)d_in[1];
    const float* fs = (const float*)d_in[2];
    const float* wq = (const float*)d_in[3];
    const float* bq = (const float*)d_in[4];
    const float* wk = (const float*)d_in[5];
    const float* bk = (const float*)d_in[6];
    const float* wv = (const float*)d_in[7];
    const float* bv = (const float*)d_in[8];
    const float* wo = (const float*)d_in[9];
    const float* bo = (const float*)d_in[10];
    const float* gq = (const float*)d_in[11];
    const float* gk = (const float*)d_in[12];
    float* out = (float*)d_out;

    float *qb, *kb;
    cudaGetSymbolAddress((void**)&qb, g_q);
    cudaGetSymbolAddress((void**)&kb, g_k);
    __nv_bfloat16 *ahi, *alo, *qhi, *qlo, *khi, *klo, *vhi, *vlo;
    cudaGetSymbolAddress((void**)&ahi, g_ahi);
    cudaGetSymbolAddress((void**)&alo, g_alo);
    cudaGetSymbolAddress((void**)&qhi, g_qhi);
    cudaGetSymbolAddress((void**)&qlo, g_qlo);
    cudaGetSymbolAddress((void**)&khi, g_khi);
    cudaGetSymbolAddress((void**)&klo, g_klo);
    cudaGetSymbolAddress((void**)&vhi, g_vhi);
    cudaGetSymbolAddress((void**)&vlo, g_vlo);
    __nv_bfloat16 *wqh, *wql, *wkh, *wkl, *wvh, *wvl, *woh, *wol;
    cudaGetSymbolAddress((void**)&wqh, g_wqT_hi);
    cudaGetSymbolAddress((void**)&wql, g_wqT_lo);
    cudaGetSymbolAddress((void**)&wkh, g_wkT_hi);
    cudaGetSymbolAddress((void**)&wkl, g_wkT_lo);
    cudaGetSymbolAddress((void**)&wvh, g_wvT_hi);
    cudaGetSymbolAddress((void**)&wvl, g_wvT_lo);
    cudaGetSymbolAddress((void**)&woh, g_woT_hi);
    cudaGetSymbolAddress((void**)&wol, g_woT_lo);

    cudaFuncSetAttribute(gemm_mma_kernel,
                         cudaFuncAttributeMaxDynamicSharedMemorySize, GEMM_SMEM_REQ);
    cudaFuncSetAttribute(attn_tc_kernel,
                         cudaFuncAttributeMaxDynamicSharedMemorySize, ATT_SMEM);

    const dim3 wgrid(32, 32);
    const dim3 wblk(32, 8);
    wsplit_kernel<<<wgrid, wblk>>>(wq, wqh, wql);
    wsplit_kernel<<<wgrid, wblk>>>(wk, wkh, wkl);
    wsplit_kernel<<<wgrid, wblk>>>(wv, wvh, wvl);
    wsplit_kernel<<<wgrid, wblk>>>(wo, woh, wol);

    split_kernel<<<(S_LEN * DIMV) / 1024, 256>>>(x, ahi, alo);

    const dim3 ggrid(DIMV / 128, S_LEN / 128);
    gemm_mma_kernel<<<ggrid, 256, GEMM_SMEM_REQ>>>(ahi, alo, wqh, wql, bq, qb, nullptr, nullptr);
    gemm_mma_kernel<<<ggrid, 256, GEMM_SMEM_REQ>>>(ahi, alo, wkh, wkl, bk, kb, nullptr, nullptr);
    gemm_mma_kernel<<<ggrid, 256, GEMM_SMEM_REQ>>>(ahi, alo, wvh, wvl, bv, nullptr, vhi, vlo);

    normrope_split_kernel<<<S_LEN, 256>>>(qb, gq, fc, fs, qhi, qlo, 0.125f);
    normrope_split_kernel<<<S_LEN, 256>>>(kb, gk, fc, fs, khi, klo, 1.0f);

    attn_tc_kernel<<<dim3(SREAL / BQ, NH, 2), 256, ATT_SMEM>>>(
        qhi, qlo, khi, klo, vhi, vlo, ahi, alo);

    gemm_mma_kernel<<<ggrid, 256, GEMM_SMEM_REQ>>>(ahi, alo, woh, wol, bo, out, nullptr, nullptr);
}

// round 7
// speedup vs baseline: 1.1161x; 1.1161x over previous
#include <cuda_runtime.h>
#include <cuda_bf16.h>
#include <math.h>
#include <stdint.h>

#define S_LEN 8704
#define DIMV  1024
#define NH    16
#define HD    64
#define SD    4608   // dilated stream length (incl. zero padding block)
#define SREAL 4352   // real tokens per stream
#define WIN   512
#define BQ    64
#define BK    64

// fp32 activation buffers
__device__ float g_q[S_LEN * DIMV];
__device__ float g_k[S_LEN * DIMV];

// bf16 split activations
__device__ __nv_bfloat16 g_ahi[S_LEN * DIMV];
__device__ __nv_bfloat16 g_alo[S_LEN * DIMV];
__device__ __nv_bfloat16 g_qhi[S_LEN * DIMV];
__device__ __nv_bfloat16 g_qlo[S_LEN * DIMV];
__device__ __nv_bfloat16 g_khi[S_LEN * DIMV];
__device__ __nv_bfloat16 g_klo[S_LEN * DIMV];
__device__ __nv_bfloat16 g_vhi[S_LEN * DIMV];
__device__ __nv_bfloat16 g_vlo[S_LEN * DIMV];

// bf16 split transposed weights [N][K]
__device__ __nv_bfloat16 g_wqT_hi[DIMV * DIMV];
__device__ __nv_bfloat16 g_wqT_lo[DIMV * DIMV];
__device__ __nv_bfloat16 g_wkT_hi[DIMV * DIMV];
__device__ __nv_bfloat16 g_wkT_lo[DIMV * DIMV];
__device__ __nv_bfloat16 g_wvT_hi[DIMV * DIMV];
__device__ __nv_bfloat16 g_wvT_lo[DIMV * DIMV];
__device__ __nv_bfloat16 g_woT_hi[DIMV * DIMV];
__device__ __nv_bfloat16 g_woT_lo[DIMV * DIMV];

__device__ __forceinline__ int dil2orig(int d, int p) {
    return ((p >> 8) << 9) + (d << 8) + (p & 255);
}

__device__ __forceinline__ uint32_t smem_to_u32(const void* smem_ptr) {
    uint32_t addr;
    asm("{ .reg .u64 tmp; cvta.to.shared.u64 tmp, %1; cvt.u32.u64 %0, tmp; }"
        : "=r"(addr) : "l"(smem_ptr));
    return addr;
}

// ===========================================================================
// family-generic tensor-core primitives
// ===========================================================================
__device__ __forceinline__ void ldsm4(uint32_t* r, uint32_t addr) {
    asm volatile("ldmatrix.sync.aligned.m8n8.x4.shared.b16 {%0,%1,%2,%3}, [%4];\n"
                 : "=r"(r[0]), "=r"(r[1]), "=r"(r[2]), "=r"(r[3]) : "r"(addr));
}
__device__ __forceinline__ void ldsm4t(uint32_t* r, uint32_t addr) {
    asm volatile("ldmatrix.sync.aligned.m8n8.x4.trans.shared.b16 {%0,%1,%2,%3}, [%4];\n"
                 : "=r"(r[0]), "=r"(r[1]), "=r"(r[2]), "=r"(r[3]) : "r"(addr));
}
__device__ __forceinline__ void mma16816(float* c, const uint32_t* a,
                                         uint32_t b0, uint32_t b1) {
    asm volatile(
        "mma.sync.aligned.m16n8k16.row.col.f32.bf16.bf16.f32 "
        "{%0,%1,%2,%3}, {%4,%5,%6,%7}, {%8,%9}, {%0,%1,%2,%3};\n"
        : "+f"(c[0]), "+f"(c[1]), "+f"(c[2]), "+f"(c[3])
        : "r"(a[0]), "r"(a[1]), "r"(a[2]), "r"(a[3]), "r"(b0), "r"(b1));
}
__device__ __forceinline__ void cp_async16(uint32_t saddr, const void* gptr) {
    asm volatile("cp.async.cg.shared.global [%0], [%1], 16;\n"
                 :: "r"(saddr), "l"(gptr));
}
__device__ __forceinline__ void cp_async16z(uint32_t saddr, const void* gptr, int srcbytes) {
    asm volatile("cp.async.cg.shared.global [%0], [%1], 16, %2;\n"
                 :: "r"(saddr), "l"(gptr), "r"(srcbytes));
}
#define CP_COMMIT() asm volatile("cp.async.commit_group;\n" ::: "memory")
#define CP_WAIT0()  asm volatile("cp.async.wait_group 0;\n" ::: "memory")

// gemm smem tile layout: 128 rows x 32 bf16 (4 x 16B chunks/row)
__device__ __forceinline__ uint32_t sw_off(int r, int c) {
    return (uint32_t)(((r >> 1) << 7) + ((r & 1) << 6) +
                      (((c ^ ((r >> 1) & 3)) & 3) << 4));
}
// attn smem tile layout: rows x 64 bf16 (8 x 16B chunks/row), xor swizzle
__device__ __forceinline__ uint32_t att_off(int r, int ch) {
    return (uint32_t)((r << 7) + (((ch ^ (r & 7)) & 7) << 4));
}

__device__ __forceinline__ uint32_t pack_bf16x2(float a, float b) {
    __nv_bfloat162 t = __floats2bfloat162_rn(a, b);
    return *(uint32_t*)&t;
}

// ===========================================================================
// bf16 split helpers
// ===========================================================================
__device__ __forceinline__ void bsplit(float f, __nv_bfloat16& h, __nv_bfloat16& l) {
    h = __float2bfloat16(f);
    l = __float2bfloat16(f - __bfloat162float(h));
}

struct __align__(8) B4 { __nv_bfloat16 v[4]; };

__global__ __launch_bounds__(256) void split_kernel(
    const float* __restrict__ src, __nv_bfloat16* __restrict__ hi,
    __nv_bfloat16* __restrict__ lo) {
    const int idx = blockIdx.x * 256 + threadIdx.x;
    float4 v = ((const float4*)src)[idx];
    B4 h, l;
    bsplit(v.x, h.v[0], l.v[0]);
    bsplit(v.y, h.v[1], l.v[1]);
    bsplit(v.z, h.v[2], l.v[2]);
    bsplit(v.w, h.v[3], l.v[3]);
    ((B4*)hi)[idx] = h;
    ((B4*)lo)[idx] = l;
}

// transpose + split all 4 weights in one launch; blockIdx.z selects weight.
__global__ __launch_bounds__(256) void wsplit_all_kernel(
    const float* __restrict__ wq, const float* __restrict__ wk,
    const float* __restrict__ wv, const float* __restrict__ wo) {
    const int z = blockIdx.z;
    const float* w = (z == 0) ? wq : (z == 1) ? wk : (z == 2) ? wv : wo;
    __nv_bfloat16* hiT = (z == 0) ? g_wqT_hi : (z == 1) ? g_wkT_hi
                        : (z == 2) ? g_wvT_hi : g_woT_hi;
    __nv_bfloat16* loT = (z == 0) ? g_wqT_lo : (z == 1) ? g_wkT_lo
                        : (z == 2) ? g_wvT_lo : g_woT_lo;

    __shared__ float t[32][33];
    const int bx = blockIdx.x << 5;
    const int by = blockIdx.y << 5;
    const int tx = threadIdx.x & 31, ty = threadIdx.x >> 5;
#pragma unroll
    for (int i = 0; i < 32; i += 8)
        t[ty + i][tx] = w[(size_t)(by + ty + i) * DIMV + bx + tx];
    __syncthreads();
#pragma unroll
    for (int i = 0; i < 32; i += 8) {
        const float f = t[tx][ty + i];
        __nv_bfloat16 h, l;
        bsplit(f, h, l);
        const size_t o = (size_t)(bx + ty + i) * DIMV + by + tx;
        hiT[o] = h;
        loT[o] = l;
    }
}

// ===========================================================================
// HMMA split-precision GEMM core (shared by qkv-fused and out-proj kernels)
// ===========================================================================
#define STAGE_BYTES 32768
#define GEMM_SMEM_REQ (2 * STAGE_BYTES)

__device__ __forceinline__ void load_stage(
    uint32_t sbase, const __nv_bfloat16* __restrict__ Ahi,
    const __nv_bfloat16* __restrict__ Alo,
    const __nv_bfloat16* __restrict__ Bhi,
    const __nv_bfloat16* __restrict__ Blo,
    int bm, int bn, int k0, int tid) {
#pragma unroll
    for (int j = 0; j < 8; j++) {
        const int chunk = tid + (j << 8);
        const int tile = chunk >> 9;
        const int idx = chunk & 511;
        const int r = idx >> 2, c = idx & 3;
        const uint32_t saddr = sbase + (uint32_t)(tile << 13) + sw_off(r, c);
        const __nv_bfloat16* gp;
        if (tile == 0)      gp = Ahi + (size_t)(bm + r) * DIMV + k0 + c * 8;
        else if (tile == 1) gp = Alo + (size_t)(bm + r) * DIMV + k0 + c * 8;
        else if (tile == 2) gp = Bhi + (size_t)(bn + r) * DIMV + k0 + c * 8;
        else                gp = Blo + (size_t)(bn + r) * DIMV + k0 + c * 8;
        cp_async16(saddr, gp);
    }
}

__device__ __forceinline__ void gemm_core(
    const __nv_bfloat16* __restrict__ Ahi, const __nv_bfloat16* __restrict__ Alo,
    const __nv_bfloat16* __restrict__ Bhi, const __nv_bfloat16* __restrict__ Blo,
    const float* __restrict__ bias, float* __restrict__ C,
    __nv_bfloat16* __restrict__ Chi, __nv_bfloat16* __restrict__ Clo,
    uint32_t sb, int bm, int bn) {
    const int tid = threadIdx.x;
    const int wid = tid >> 5, lane = tid & 31;
    const int wm = (wid & 1) << 6;
    const int wn = (wid >> 1) << 5;
    const int lr = lane & 15;
    const int lhalf = lane >> 4;

    float acc[4][4][4];
#pragma unroll
    for (int i = 0; i < 4; i++)
#pragma unroll
        for (int j = 0; j < 4; j++)
#pragma unroll
            for (int k = 0; k < 4; k++) acc[i][j][k] = 0.f;

    load_stage(sb, Ahi, Alo, Bhi, Blo, bm, bn, 0, tid);
    CP_COMMIT();

    for (int s = 0; s < 32; s++) {
        CP_WAIT0();
        __syncthreads();
        if (s + 1 < 32) {
            load_stage(sb + ((s + 1) & 1) * STAGE_BYTES, Ahi, Alo, Bhi, Blo,
                       bm, bn, (s + 1) << 5, tid);
            CP_COMMIT();
        }

        const uint32_t buf = sb + (s & 1) * STAGE_BYTES;
#pragma unroll
        for (int kk = 0; kk < 2; kk++) {
            const int cb = (kk << 1) + lhalf;
            uint32_t a[4][4], bh[2][4], bl[2][4];
            // load Ahi, Bhi, Blo once; keep Bhi alive for pass 3
#pragma unroll
            for (int mi = 0; mi < 4; mi++)
                ldsm4(a[mi], buf + sw_off(wm + (mi << 4) + lr, cb));
#pragma unroll
            for (int np = 0; np < 2; np++) {
                ldsm4(bh[np], buf + 16384 + sw_off(wn + (np << 4) + lr, cb));
                ldsm4(bl[np], buf + 24576 + sw_off(wn + (np << 4) + lr, cb));
            }
            // pass 1: Ahi x Bhi
#pragma unroll
            for (int mi = 0; mi < 4; mi++) {
                mma16816(acc[mi][0], a[mi], bh[0][0], bh[0][2]);
                mma16816(acc[mi][1], a[mi], bh[0][1], bh[0][3]);
                mma16816(acc[mi][2], a[mi], bh[1][0], bh[1][2]);
                mma16816(acc[mi][3], a[mi], bh[1][1], bh[1][3]);
            }
            // pass 2: Ahi x Blo
#pragma unroll
            for (int mi = 0; mi < 4; mi++) {
                mma16816(acc[mi][0], a[mi], bl[0][0], bl[0][2]);
                mma16816(acc[mi][1], a[mi], bl[0][1], bl[0][3]);
                mma16816(acc[mi][2], a[mi], bl[1][0], bl[1][2]);
                mma16816(acc[mi][3], a[mi], bl[1][1], bl[1][3]);
            }
            // pass 3: Alo x Bhi (reuse bh regs)
#pragma unroll
            for (int mi = 0; mi < 4; mi++)
                ldsm4(a[mi], buf + 8192 + sw_off(wm + (mi << 4) + lr, cb));
#pragma unroll
            for (int mi = 0; mi < 4; mi++) {
                mma16816(acc[mi][0], a[mi], bh[0][0], bh[0][2]);
                mma16816(acc[mi][1], a[mi], bh[0][1], bh[0][3]);
                mma16816(acc[mi][2], a[mi], bh[1][0], bh[1][2]);
                mma16816(acc[mi][3], a[mi], bh[1][1], bh[1][3]);
            }
        }
        __syncthreads();
    }

    const int crow = lane >> 2;
    const int ccol = (lane & 3) << 1;
#pragma unroll
    for (int ni = 0; ni < 4; ni++) {
        const int col = bn + wn + (ni << 3) + ccol;
        const float2 bv = *(const float2*)&bias[col];
#pragma unroll
        for (int mi = 0; mi < 4; mi++) {
            const int row = bm + wm + (mi << 4) + crow;
            const float v00 = acc[mi][ni][0] + bv.x, v01 = acc[mi][ni][1] + bv.y;
            const float v10 = acc[mi][ni][2] + bv.x, v11 = acc[mi][ni][3] + bv.y;
            if (Chi) {
                const float h00 = __bfloat162float(__float2bfloat16(v00));
                const float h01 = __bfloat162float(__float2bfloat16(v01));
                const float h10 = __bfloat162float(__float2bfloat16(v10));
                const float h11 = __bfloat162float(__float2bfloat16(v11));
                *(uint32_t*)&Chi[(size_t)row * DIMV + col] = pack_bf16x2(h00, h01);
                *(uint32_t*)&Clo[(size_t)row * DIMV + col] = pack_bf16x2(v00 - h00, v01 - h01);
                *(uint32_t*)&Chi[(size_t)(row + 8) * DIMV + col] = pack_bf16x2(h10, h11);
                *(uint32_t*)&Clo[(size_t)(row + 8) * DIMV + col] = pack_bf16x2(v10 - h10, v11 - h11);
            } else {
                *(float2*)&C[(size_t)row * DIMV + col] = make_float2(v00, v01);
                *(float2*)&C[(size_t)(row + 8) * DIMV + col] = make_float2(v10, v11);
            }
        }
    }
}

// fused Q/K/V projection: grid (8, 68, 3)
__global__ __launch_bounds__(256, 2)
void gemm_qkv_kernel(const __nv_bfloat16* __restrict__ Ahi,
                     const __nv_bfloat16* __restrict__ Alo,
                     const float* __restrict__ bq,
                     const float* __restrict__ bk,
                     const float* __restrict__ bv) {
    extern __shared__ char smem[];
    const uint32_t sb = smem_to_u32(smem);
    const int z = blockIdx.z;
    const __nv_bfloat16* Bh = (z == 0) ? g_wqT_hi : (z == 1) ? g_wkT_hi : g_wvT_hi;
    const __nv_bfloat16* Bl = (z == 0) ? g_wqT_lo : (z == 1) ? g_wkT_lo : g_wvT_lo;
    const float* bias = (z == 0) ? bq : (z == 1) ? bk : bv;
    float* C = (z == 0) ? g_q : (z == 1) ? g_k : nullptr;
    __nv_bfloat16* Chi = (z == 2) ? g_vhi : nullptr;
    __nv_bfloat16* Clo = (z == 2) ? g_vlo : nullptr;
    gemm_core(Ahi, Alo, Bh, Bl, bias, C, Chi, Clo, sb,
              blockIdx.y << 7, blockIdx.x << 7);
}

// output projection
__global__ __launch_bounds__(256, 2)
void gemm_out_kernel(const __nv_bfloat16* __restrict__ Ahi,
                     const __nv_bfloat16* __restrict__ Alo,
                     const float* __restrict__ bias,
                     float* __restrict__ C) {
    extern __shared__ char smem[];
    const uint32_t sb = smem_to_u32(smem);
    gemm_core(Ahi, Alo, g_woT_hi, g_woT_lo, bias, C, nullptr, nullptr, sb,
              blockIdx.y << 7, blockIdx.x << 7);
}

// ---------------------------------------------------------------------------
// Fused RMSNorm + RoPE, writes bf16 hi/lo (scale folded in). 1 block/token.
// ---------------------------------------------------------------------------
__global__ __launch_bounds__(256) void normrope_split_kernel(
    const float* __restrict__ src, const float* __restrict__ g,
    const float* __restrict__ cs, const float* __restrict__ sn,
    __nv_bfloat16* __restrict__ hi, __nv_bfloat16* __restrict__ lo,
    float scale) {
    const int s = blockIdx.x;
    const int tid = threadIdx.x;

    float4 v = *(const float4*)&src[(size_t)s * DIMV + (tid << 2)];
    float ss = v.x * v.x + v.y * v.y + v.z * v.z + v.w * v.w;
#pragma unroll
    for (int o = 16; o; o >>= 1) ss += __shfl_xor_sync(0xffffffffu, ss, o);

    __shared__ float red[8];
    __shared__ float rtot;
    if ((tid & 31) == 0) red[tid >> 5] = ss;
    __syncthreads();
    if (tid == 0) {
        float t = 0.f;
#pragma unroll
        for (int i = 0; i < 8; i++) t += red[i];
        rtot = rsqrtf(t * (1.0f / 1024.0f) + 1e-6f);
    }
    __syncthreads();
    const float r = rtot;

    float4 gv = *(const float4*)&g[tid << 2];
    const float a0 = v.x * r * gv.x, b0 = v.y * r * gv.y;
    const float a1 = v.z * r * gv.z, b1 = v.w * r * gv.w;

    const int p0 = tid << 1;
    const int r0 = p0 & 31, r1 = (p0 + 1) & 31;
    const float c0 = cs[s * 32 + r0], s0 = sn[s * 32 + r0];
    const float c1 = cs[s * 32 + r1], s1 = sn[s * 32 + r1];

    float o0 = (a0 * c0 - b0 * s0) * scale;
    float o1 = (a0 * s0 + b0 * c0) * scale;
    float o2 = (a1 * c1 - b1 * s1) * scale;
    float o3 = (a1 * s1 + b1 * c1) * scale;

    B4 h, l;
    bsplit(o0, h.v[0], l.v[0]);
    bsplit(o1, h.v[1], l.v[1]);
    bsplit(o2, h.v[2], l.v[2]);
    bsplit(o3, h.v[3], l.v[3]);
    const size_t idx = (size_t)s * (DIMV / 4) + tid;
    ((B4*)hi)[idx] = h;
    ((B4*)lo)[idx] = l;
}

// ===========================================================================
// Tensor-core flash attention (R5 config: 64 q/CTA, 4 warps, BK=64)
// ===========================================================================
#define ATT_STAGE 32768
#define ATT_SMEM  (16384 + 2 * ATT_STAGE)

__global__ __launch_bounds__(128)
void attn_tc_kernel(const __nv_bfloat16* __restrict__ qhi, const __nv_bfloat16* __restrict__ qlo,
                    const __nv_bfloat16* __restrict__ khi, const __nv_bfloat16* __restrict__ klo,
                    const __nv_bfloat16* __restrict__ vhi, const __nv_bfloat16* __restrict__ vlo,
                    __nv_bfloat16* __restrict__ ohi, __nv_bfloat16* __restrict__ olo) {
    extern __shared__ char smem[];
    const uint32_t sb = smem_to_u32(smem);
    const int d = blockIdx.z, h = blockIdx.y;
    const int q0 = blockIdx.x << 6;
    const int tid = threadIdx.x;
    const int warp = tid >> 5, lane = tid & 31;
    const int wq = warp << 4;
    const int lr = lane & 15, lhf = lane >> 4;
    const int qr = lane >> 2, qc = (lane & 3) << 1;

    // --- load Q hi/lo tiles into smem (once) ---
#pragma unroll
    for (int t = 0; t < 4; t++) {
        const int idx = tid + (t << 7);
        const int r = idx >> 3, ch = idx & 7;
        const int tok = dil2orig(d, q0 + r);
        const size_t go = (size_t)tok * DIMV + h * HD + (ch << 3);
        *(uint4*)(smem + att_off(r, ch)) = *(const uint4*)&qhi[go];
        *(uint4*)(smem + 8192 + att_off(r, ch)) = *(const uint4*)&qlo[go];
    }
    __syncthreads();

    uint32_t qh[4][4], ql[4][4];
#pragma unroll
    for (int s = 0; s < 4; s++) {
        ldsm4(qh[s], sb + att_off(wq + lr, (s << 1) + lhf));
        ldsm4(ql[s], sb + 8192 + att_off(wq + lr, (s << 1) + lhf));
    }

    float m0 = -1e30f, m1 = -1e30f, l0 = 0.f, l1 = 0.f;
    float o[8][4];
#pragma unroll
    for (int j = 0; j < 8; j++)
#pragma unroll
        for (int k = 0; k < 4; k++) o[j][k] = 0.f;

    const int kt_lo = (q0 >= WIN) ? (q0 - WIN) : 0;
    const int kt_hi = min(SD, q0 + BQ + WIN);
    const int row0 = q0 + wq + qr, row1 = row0 + 8;

    auto stage_load = [&](int st, int kt) {
        const uint32_t stg = sb + 16384 + st * ATT_STAGE;
#pragma unroll
        for (int t = 0; t < 16; t++) {
            const int cid = tid + (t << 7);
            const int buf = cid >> 9;
            const int idx = cid & 511;
            const int r = idx >> 3, ch = idx & 7;
            const int pk = kt + r;
            const int ok = pk < SREAL;
            const int tok = ok ? dil2orig(d, pk) : 0;
            const size_t go = (size_t)tok * DIMV + h * HD + (ch << 3);
            const __nv_bfloat16* src = (buf == 0) ? khi : (buf == 1) ? klo
                                      : (buf == 2) ? vhi : vlo;
            cp_async16z(stg + (buf << 13) + att_off(r, ch), src + go, ok ? 16 : 0);
        }
    };

    stage_load(0, kt_lo);
    CP_COMMIT();

    int st = 0;
    for (int kt = kt_lo; kt < kt_hi; kt += BK, st ^= 1) {
        CP_WAIT0();
        __syncthreads();
        if (kt + BK < kt_hi) { stage_load(st ^ 1, kt + BK); CP_COMMIT(); }

        const uint32_t sK  = sb + 16384 + st * ATT_STAGE;
        const uint32_t sKl = sK + 8192, sV = sK + 16384, sVl = sK + 24576;

        // --- scores ---
        float c[8][4];
#pragma unroll
        for (int j = 0; j < 8; j++)
#pragma unroll
            for (int k = 0; k < 4; k++) c[j][k] = 0.f;

#pragma unroll
        for (int s = 0; s < 4; s++) {
#pragma unroll
            for (int g = 0; g < 4; g++) {
                uint32_t bh[4], bl[4];
                ldsm4(bh, sK + att_off((g << 4) + lr, (s << 1) + lhf));
                ldsm4(bl, sKl + att_off((g << 4) + lr, (s << 1) + lhf));
                mma16816(c[2 * g],     qh[s], bh[0], bh[2]);
                mma16816(c[2 * g + 1], qh[s], bh[1], bh[3]);
                mma16816(c[2 * g],     ql[s], bh[0], bh[2]);
                mma16816(c[2 * g + 1], ql[s], bh[1], bh[3]);
                mma16816(c[2 * g],     qh[s], bl[0], bl[2]);
                mma16816(c[2 * g + 1], qh[s], bl[1], bl[3]);
            }
        }

        // --- window mask (edge tiles only) ---
        const bool edge = (kt < q0 - WIN + BK) || (kt >= q0 + WIN);
        if (edge) {
#pragma unroll
            for (int j = 0; j < 8; j++) {
                const int pk = kt + (j << 3) + qc;
                if (abs(row0 - pk) > WIN)       c[j][0] = -1e9f;
                if (abs(row0 - pk - 1) > WIN)   c[j][1] = -1e9f;
                if (abs(row1 - pk) > WIN)       c[j][2] = -1e9f;
                if (abs(row1 - pk - 1) > WIN)   c[j][3] = -1e9f;
            }
        }

        // --- online softmax ---
        float tm0 = -1e30f, tm1 = -1e30f;
#pragma unroll
        for (int j = 0; j < 8; j++) {
            tm0 = fmaxf(tm0, fmaxf(c[j][0], c[j][1]));
            tm1 = fmaxf(tm1, fmaxf(c[j][2], c[j][3]));
        }
        tm0 = fmaxf(tm0, __shfl_xor_sync(0xffffffffu, tm0, 1));
        tm0 = fmaxf(tm0, __shfl_xor_sync(0xffffffffu, tm0, 2));
        tm1 = fmaxf(tm1, __shfl_xor_sync(0xffffffffu, tm1, 1));
        tm1 = fmaxf(tm1, __shfl_xor_sync(0xffffffffu, tm1, 2));

        const float mn0 = fmaxf(m0, tm0), mn1 = fmaxf(m1, tm1);
        const float cor0 = __expf(m0 - mn0), cor1 = __expf(m1 - mn1);
        m0 = mn0; m1 = mn1;

        float s0 = 0.f, s1 = 0.f;
#pragma unroll
        for (int j = 0; j < 8; j++) {
            c[j][0] = __expf(c[j][0] - mn0);
            c[j][1] = __expf(c[j][1] - mn0);
            c[j][2] = __expf(c[j][2] - mn1);
            c[j][3] = __expf(c[j][3] - mn1);
            s0 += c[j][0] + c[j][1];
            s1 += c[j][2] + c[j][3];
        }
        s0 += __shfl_xor_sync(0xffffffffu, s0, 1);
        s0 += __shfl_xor_sync(0xffffffffu, s0, 2);
        s1 += __shfl_xor_sync(0xffffffffu, s1, 1);
        s1 += __shfl_xor_sync(0xffffffffu, s1, 2);
        l0 = l0 * cor0 + s0;
        l1 = l1 * cor1 + s1;
#pragma unroll
        for (int j = 0; j < 8; j++) {
            o[j][0] *= cor0; o[j][1] *= cor0;
            o[j][2] *= cor1; o[j][3] *= cor1;
        }

        // --- PV ---
#pragma unroll
        for (int s = 0; s < 4; s++) {
            uint32_t ah[4], al[4];
#pragma unroll
            for (int half = 0; half < 2; half++) {
                const int j = 2 * s + half;
                const float p0 = c[j][0], p1 = c[j][1];
                const float p2 = c[j][2], p3 = c[j][3];
                const float h0 = __bfloat162float(__float2bfloat16(p0));
                const float h1 = __bfloat162float(__float2bfloat16(p1));
                const float h2 = __bfloat162float(__float2bfloat16(p2));
                const float h3 = __bfloat162float(__float2bfloat16(p3));
                ah[2 * half]     = pack_bf16x2(h0, h1);
                ah[2 * half + 1] = pack_bf16x2(h2, h3);
                al[2 * half]     = pack_bf16x2(p0 - h0, p1 - h1);
                al[2 * half + 1] = pack_bf16x2(p2 - h2, p3 - h3);
            }
#pragma unroll
            for (int g = 0; g < 4; g++) {
                uint32_t bh[4], bl[4];
                ldsm4t(bh, sV + att_off((s << 4) + lr, (g << 1) + lhf));
                ldsm4t(bl, sVl + att_off((s << 4) + lr, (g << 1) + lhf));
                mma16816(o[2 * g],     ah, bh[0], bh[1]);
                mma16816(o[2 * g + 1], ah, bh[2], bh[3]);
                mma16816(o[2 * g],     al, bh[0], bh[1]);
                mma16816(o[2 * g + 1], al, bh[2], bh[3]);
                mma16816(o[2 * g],     ah, bl[0], bl[1]);
                mma16816(o[2 * g + 1], ah, bl[2], bl[3]);
            }
        }
        __syncthreads();
    }

    // --- epilogue: normalize, split to bf16 hi/lo, store ---
    const float inv0 = 1.0f / l0, inv1 = 1.0f / l1;
    const int tok0 = dil2orig(d, row0);
    const int tok1 = dil2orig(d, row1);
#pragma unroll
    for (int j = 0; j < 8; j++) {
        const int col = h * HD + (j << 3) + qc;
        const float a0 = o[j][0] * inv0, a1 = o[j][1] * inv0;
        const float b0 = o[j][2] * inv1, b1 = o[j][3] * inv1;
        const float a0h = __bfloat162float(__float2bfloat16(a0));
        const float a1h = __bfloat162float(__float2bfloat16(a1));
        const float b0h = __bfloat162float(__float2bfloat16(b0));
        const float b1h = __bfloat162float(__float2bfloat16(b1));
        *(uint32_t*)&ohi[(size_t)tok0 * DIMV + col] = pack_bf16x2(a0h, a1h);
        *(uint32_t*)&olo[(size_t)tok0 * DIMV + col] = pack_bf16x2(a0 - a0h, a1 - a1h);
        *(uint32_t*)&ohi[(size_t)tok1 * DIMV + col] = pack_bf16x2(b0h, b1h);
        *(uint32_t*)&olo[(size_t)tok1 * DIMV + col] = pack_bf16x2(b0 - b0h, b1 - b1h);
    }
}

// ---------------------------------------------------------------------------
extern "C" void kernel_launch(void* const* d_in, const int* in_sizes, int n_in,
                              void* d_out, int out_size) {
    (void)in_sizes; (void)n_in; (void)out_size;
    const float* x  = (const float*)d_in[0];
    const float* fc = (const float*)d_in[1];
    const float* fs = (const float*)d_in[2];
    const float* wq = (const float*)d_in[3];
    const float* bq = (const float*)d_in[4];
    const float* wk = (const float*)d_in[5];
    const float* bk = (const float*)d_in[6];
    const float* wv = (const float*)d_in[7];
    const float* bv = (const float*)d_in[8];
    const float* wo = (const float*)d_in[9];
    const float* bo = (const float*)d_in[10];
    const float* gq = (const float*)d_in[11];
    const float* gk = (const float*)d_in[12];
    float* out = (float*)d_out;

    float *qb, *kb;
    cudaGetSymbolAddress((void**)&qb, g_q);
    cudaGetSymbolAddress((void**)&kb, g_k);
    __nv_bfloat16 *ahi, *alo, *qhi, *qlo, *khi, *klo, *vhi, *vlo;
    cudaGetSymbolAddress((void**)&ahi, g_ahi);
    cudaGetSymbolAddress((void**)&alo, g_alo);
    cudaGetSymbolAddress((void**)&qhi, g_qhi);
    cudaGetSymbolAddress((void**)&qlo, g_qlo);
    cudaGetSymbolAddress((void**)&khi, g_khi);
    cudaGetSymbolAddress((void**)&klo, g_klo);
    cudaGetSymbolAddress((void**)&vhi, g_vhi);
    cudaGetSymbolAddress((void**)&vlo, g_vlo);

    cudaFuncSetAttribute(gemm_qkv_kernel,
                         cudaFuncAttributeMaxDynamicSharedMemorySize, GEMM_SMEM_REQ);
    cudaFuncSetAttribute(gemm_out_kernel,
                         cudaFuncAttributeMaxDynamicSharedMemorySize, GEMM_SMEM_REQ);
    cudaFuncSetAttribute(attn_tc_kernel,
                         cudaFuncAttributeMaxDynamicSharedMemorySize, ATT_SMEM);

    // launch 0: all weight transpose+splits
    wsplit_all_kernel<<<dim3(32, 32, 4), 256>>>(wq, wk, wv, wo);
    // launch 1: x split
    split_kernel<<<(S_LEN * DIMV) / 1024, 256>>>(x, ahi, alo);
    // launch 2: fused Q/K/V projections
    gemm_qkv_kernel<<<dim3(DIMV / 128, S_LEN / 128, 3), 256, GEMM_SMEM_REQ>>>(
        ahi, alo, bq, bk, bv);
    // launches 3,4: norm+rope+split for Q and K
    normrope_split_kernel<<<S_LEN, 256>>>(qb, gq, fc, fs, qhi, qlo, 0.125f);
    normrope_split_kernel<<<S_LEN, 256>>>(kb, gk, fc, fs, khi, klo, 1.0f);
    // launch 5: attention (profiled by ncu -s 5 -c 1)
    attn_tc_kernel<<<dim3(SREAL / BQ, NH, 2), 128, ATT_SMEM>>>(
        qhi, qlo, khi, klo, vhi, vlo, ahi, alo);
    // launch 6: output projection
    gemm_out_kernel<<<dim3(DIMV / 128, S_LEN / 128), 256, GEMM_SMEM_REQ>>>(
        ahi, alo, bo, out);
}

// round 8
// speedup vs baseline: 1.1444x; 1.0254x over previous
#include <cuda_runtime.h>
#include <cuda_bf16.h>
#include <math.h>
#include <stdint.h>

#define S_LEN 8704
#define DIMV  1024
#define NH    16
#define HD    64
#define SD    4608   // dilated stream length (incl. zero padding block)
#define SREAL 4352   // real tokens per stream
#define WIN   512
#define BQ    64
#define BK    64

// fp32 activation buffers
__device__ float g_q[S_LEN * DIMV];
__device__ float g_k[S_LEN * DIMV];

// bf16 split activations
__device__ __nv_bfloat16 g_ahi[S_LEN * DIMV];
__device__ __nv_bfloat16 g_alo[S_LEN * DIMV];
__device__ __nv_bfloat16 g_qhi[S_LEN * DIMV];
__device__ __nv_bfloat16 g_qlo[S_LEN * DIMV];
__device__ __nv_bfloat16 g_khi[S_LEN * DIMV];
__device__ __nv_bfloat16 g_klo[S_LEN * DIMV];
__device__ __nv_bfloat16 g_vhi[S_LEN * DIMV];
__device__ __nv_bfloat16 g_vlo[S_LEN * DIMV];

// bf16 split transposed weights [N][K]
__device__ __nv_bfloat16 g_wqT_hi[DIMV * DIMV];
__device__ __nv_bfloat16 g_wqT_lo[DIMV * DIMV];
__device__ __nv_bfloat16 g_wkT_hi[DIMV * DIMV];
__device__ __nv_bfloat16 g_wkT_lo[DIMV * DIMV];
__device__ __nv_bfloat16 g_wvT_hi[DIMV * DIMV];
__device__ __nv_bfloat16 g_wvT_lo[DIMV * DIMV];
__device__ __nv_bfloat16 g_woT_hi[DIMV * DIMV];
__device__ __nv_bfloat16 g_woT_lo[DIMV * DIMV];

__device__ __forceinline__ int dil2orig(int d, int p) {
    return ((p >> 8) << 9) + (d << 8) + (p & 255);
}

__device__ __forceinline__ uint32_t smem_to_u32(const void* smem_ptr) {
    uint32_t addr;
    asm("{ .reg .u64 tmp; cvta.to.shared.u64 tmp, %1; cvt.u32.u64 %0, tmp; }"
        : "=r"(addr) : "l"(smem_ptr));
    return addr;
}

// ===========================================================================
// family-generic tensor-core primitives
// ===========================================================================
__device__ __forceinline__ void ldsm4(uint32_t* r, uint32_t addr) {
    asm volatile("ldmatrix.sync.aligned.m8n8.x4.shared.b16 {%0,%1,%2,%3}, [%4];\n"
                 : "=r"(r[0]), "=r"(r[1]), "=r"(r[2]), "=r"(r[3]) : "r"(addr));
}
__device__ __forceinline__ void ldsm4t(uint32_t* r, uint32_t addr) {
    asm volatile("ldmatrix.sync.aligned.m8n8.x4.trans.shared.b16 {%0,%1,%2,%3}, [%4];\n"
                 : "=r"(r[0]), "=r"(r[1]), "=r"(r[2]), "=r"(r[3]) : "r"(addr));
}
__device__ __forceinline__ void mma16816(float* c, const uint32_t* a,
                                         uint32_t b0, uint32_t b1) {
    asm volatile(
        "mma.sync.aligned.m16n8k16.row.col.f32.bf16.bf16.f32 "
        "{%0,%1,%2,%3}, {%4,%5,%6,%7}, {%8,%9}, {%0,%1,%2,%3};\n"
        : "+f"(c[0]), "+f"(c[1]), "+f"(c[2]), "+f"(c[3])
        : "r"(a[0]), "r"(a[1]), "r"(a[2]), "r"(a[3]), "r"(b0), "r"(b1));
}
__device__ __forceinline__ void cp_async16(uint32_t saddr, const void* gptr) {
    asm volatile("cp.async.cg.shared.global [%0], [%1], 16;\n"
                 :: "r"(saddr), "l"(gptr));
}
__device__ __forceinline__ void cp_async16z(uint32_t saddr, const void* gptr, int srcbytes) {
    asm volatile("cp.async.cg.shared.global [%0], [%1], 16, %2;\n"
                 :: "r"(saddr), "l"(gptr), "r"(srcbytes));
}
#define CP_COMMIT() asm volatile("cp.async.commit_group;\n" ::: "memory")
#define CP_WAIT0()  asm volatile("cp.async.wait_group 0;\n" ::: "memory")

// gemm smem tile layout: 128 rows x 32 bf16 (4 x 16B chunks/row)
__device__ __forceinline__ uint32_t sw_off(int r, int c) {
    return (uint32_t)(((r >> 1) << 7) + ((r & 1) << 6) +
                      (((c ^ ((r >> 1) & 3)) & 3) << 4));
}
// attn smem tile layout: rows x 64 bf16 (8 x 16B chunks/row), xor swizzle
__device__ __forceinline__ uint32_t att_off(int r, int ch) {
    return (uint32_t)((r << 7) + (((ch ^ (r & 7)) & 7) << 4));
}

__device__ __forceinline__ uint32_t pack_bf16x2(float a, float b) {
    __nv_bfloat162 t = __floats2bfloat162_rn(a, b);
    return *(uint32_t*)&t;
}

// ===========================================================================
// bf16 split helpers
// ===========================================================================
__device__ __forceinline__ void bsplit(float f, __nv_bfloat16& h, __nv_bfloat16& l) {
    h = __float2bfloat16(f);
    l = __float2bfloat16(f - __bfloat162float(h));
}

struct __align__(8) B4 { __nv_bfloat16 v[4]; };

__global__ __launch_bounds__(256) void split_kernel(
    const float* __restrict__ src, __nv_bfloat16* __restrict__ hi,
    __nv_bfloat16* __restrict__ lo) {
    const int idx = blockIdx.x * 256 + threadIdx.x;
    float4 v = ((const float4*)src)[idx];
    B4 h, l;
    bsplit(v.x, h.v[0], l.v[0]);
    bsplit(v.y, h.v[1], l.v[1]);
    bsplit(v.z, h.v[2], l.v[2]);
    bsplit(v.w, h.v[3], l.v[3]);
    ((B4*)hi)[idx] = h;
    ((B4*)lo)[idx] = l;
}

// transpose + split all 4 weights in one launch; blockIdx.z selects weight.
__global__ __launch_bounds__(256) void wsplit_all_kernel(
    const float* __restrict__ wq, const float* __restrict__ wk,
    const float* __restrict__ wv, const float* __restrict__ wo) {
    const int z = blockIdx.z;
    const float* w = (z == 0) ? wq : (z == 1) ? wk : (z == 2) ? wv : wo;
    __nv_bfloat16* hiT = (z == 0) ? g_wqT_hi : (z == 1) ? g_wkT_hi
                        : (z == 2) ? g_wvT_hi : g_woT_hi;
    __nv_bfloat16* loT = (z == 0) ? g_wqT_lo : (z == 1) ? g_wkT_lo
                        : (z == 2) ? g_wvT_lo : g_woT_lo;

    __shared__ float t[32][33];
    const int bx = blockIdx.x << 5;
    const int by = blockIdx.y << 5;
    const int tx = threadIdx.x & 31, ty = threadIdx.x >> 5;
#pragma unroll
    for (int i = 0; i < 32; i += 8)
        t[ty + i][tx] = w[(size_t)(by + ty + i) * DIMV + bx + tx];
    __syncthreads();
#pragma unroll
    for (int i = 0; i < 32; i += 8) {
        const float f = t[tx][ty + i];
        __nv_bfloat16 h, l;
        bsplit(f, h, l);
        const size_t o = (size_t)(bx + ty + i) * DIMV + by + tx;
        hiT[o] = h;
        loT[o] = l;
    }
}

// ===========================================================================
// HMMA split-precision GEMM core
// ===========================================================================
#define STAGE_BYTES 32768
#define GEMM_SMEM_REQ (2 * STAGE_BYTES)

__device__ __forceinline__ void load_stage(
    uint32_t sbase, const __nv_bfloat16* __restrict__ Ahi,
    const __nv_bfloat16* __restrict__ Alo,
    const __nv_bfloat16* __restrict__ Bhi,
    const __nv_bfloat16* __restrict__ Blo,
    int bm, int bn, int k0, int tid) {
#pragma unroll
    for (int j = 0; j < 8; j++) {
        const int chunk = tid + (j << 8);
        const int tile = chunk >> 9;
        const int idx = chunk & 511;
        const int r = idx >> 2, c = idx & 3;
        const uint32_t saddr = sbase + (uint32_t)(tile << 13) + sw_off(r, c);
        const __nv_bfloat16* gp;
        if (tile == 0)      gp = Ahi + (size_t)(bm + r) * DIMV + k0 + c * 8;
        else if (tile == 1) gp = Alo + (size_t)(bm + r) * DIMV + k0 + c * 8;
        else if (tile == 2) gp = Bhi + (size_t)(bn + r) * DIMV + k0 + c * 8;
        else                gp = Blo + (size_t)(bn + r) * DIMV + k0 + c * 8;
        cp_async16(saddr, gp);
    }
}

__device__ __forceinline__ void gemm_core(
    const __nv_bfloat16* __restrict__ Ahi, const __nv_bfloat16* __restrict__ Alo,
    const __nv_bfloat16* __restrict__ Bhi, const __nv_bfloat16* __restrict__ Blo,
    const float* __restrict__ bias, float* __restrict__ C,
    __nv_bfloat16* __restrict__ Chi, __nv_bfloat16* __restrict__ Clo,
    uint32_t sb, int bm, int bn) {
    const int tid = threadIdx.x;
    const int wid = tid >> 5, lane = tid & 31;
    const int wm = (wid & 1) << 6;
    const int wn = (wid >> 1) << 5;
    const int lr = lane & 15;
    const int lhalf = lane >> 4;

    float acc[4][4][4];
#pragma unroll
    for (int i = 0; i < 4; i++)
#pragma unroll
        for (int j = 0; j < 4; j++)
#pragma unroll
            for (int k = 0; k < 4; k++) acc[i][j][k] = 0.f;

    load_stage(sb, Ahi, Alo, Bhi, Blo, bm, bn, 0, tid);
    CP_COMMIT();

    for (int s = 0; s < 32; s++) {
        CP_WAIT0();
        __syncthreads();
        if (s + 1 < 32) {
            load_stage(sb + ((s + 1) & 1) * STAGE_BYTES, Ahi, Alo, Bhi, Blo,
                       bm, bn, (s + 1) << 5, tid);
            CP_COMMIT();
        }

        const uint32_t buf = sb + (s & 1) * STAGE_BYTES;
#pragma unroll
        for (int kk = 0; kk < 2; kk++) {
            const int cb = (kk << 1) + lhalf;
            uint32_t a[4][4], bh[2][4], bl[2][4];
#pragma unroll
            for (int mi = 0; mi < 4; mi++)
                ldsm4(a[mi], buf + sw_off(wm + (mi << 4) + lr, cb));
#pragma unroll
            for (int np = 0; np < 2; np++) {
                ldsm4(bh[np], buf + 16384 + sw_off(wn + (np << 4) + lr, cb));
                ldsm4(bl[np], buf + 24576 + sw_off(wn + (np << 4) + lr, cb));
            }
#pragma unroll
            for (int mi = 0; mi < 4; mi++) {
                mma16816(acc[mi][0], a[mi], bh[0][0], bh[0][2]);
                mma16816(acc[mi][1], a[mi], bh[0][1], bh[0][3]);
                mma16816(acc[mi][2], a[mi], bh[1][0], bh[1][2]);
                mma16816(acc[mi][3], a[mi], bh[1][1], bh[1][3]);
            }
#pragma unroll
            for (int mi = 0; mi < 4; mi++) {
                mma16816(acc[mi][0], a[mi], bl[0][0], bl[0][2]);
                mma16816(acc[mi][1], a[mi], bl[0][1], bl[0][3]);
                mma16816(acc[mi][2], a[mi], bl[1][0], bl[1][2]);
                mma16816(acc[mi][3], a[mi], bl[1][1], bl[1][3]);
            }
#pragma unroll
            for (int mi = 0; mi < 4; mi++)
                ldsm4(a[mi], buf + 8192 + sw_off(wm + (mi << 4) + lr, cb));
#pragma unroll
            for (int mi = 0; mi < 4; mi++) {
                mma16816(acc[mi][0], a[mi], bh[0][0], bh[0][2]);
                mma16816(acc[mi][1], a[mi], bh[0][1], bh[0][3]);
                mma16816(acc[mi][2], a[mi], bh[1][0], bh[1][2]);
                mma16816(acc[mi][3], a[mi], bh[1][1], bh[1][3]);
            }
        }
        __syncthreads();
    }

    const int crow = lane >> 2;
    const int ccol = (lane & 3) << 1;
#pragma unroll
    for (int ni = 0; ni < 4; ni++) {
        const int col = bn + wn + (ni << 3) + ccol;
        const float2 bv = *(const float2*)&bias[col];
#pragma unroll
        for (int mi = 0; mi < 4; mi++) {
            const int row = bm + wm + (mi << 4) + crow;
            const float v00 = acc[mi][ni][0] + bv.x, v01 = acc[mi][ni][1] + bv.y;
            const float v10 = acc[mi][ni][2] + bv.x, v11 = acc[mi][ni][3] + bv.y;
            if (Chi) {
                const float h00 = __bfloat162float(__float2bfloat16(v00));
                const float h01 = __bfloat162float(__float2bfloat16(v01));
                const float h10 = __bfloat162float(__float2bfloat16(v10));
                const float h11 = __bfloat162float(__float2bfloat16(v11));
                *(uint32_t*)&Chi[(size_t)row * DIMV + col] = pack_bf16x2(h00, h01);
                *(uint32_t*)&Clo[(size_t)row * DIMV + col] = pack_bf16x2(v00 - h00, v01 - h01);
                *(uint32_t*)&Chi[(size_t)(row + 8) * DIMV + col] = pack_bf16x2(h10, h11);
                *(uint32_t*)&Clo[(size_t)(row + 8) * DIMV + col] = pack_bf16x2(v10 - h10, v11 - h11);
            } else {
                *(float2*)&C[(size_t)row * DIMV + col] = make_float2(v00, v01);
                *(float2*)&C[(size_t)(row + 8) * DIMV + col] = make_float2(v10, v11);
            }
        }
    }
}

// fused Q/K/V projection: grid (8, 68, 3)
__global__ __launch_bounds__(256, 2)
void gemm_qkv_kernel(const __nv_bfloat16* __restrict__ Ahi,
                     const __nv_bfloat16* __restrict__ Alo,
                     const float* __restrict__ bq,
                     const float* __restrict__ bk,
                     const float* __restrict__ bv) {
    extern __shared__ char smem[];
    const uint32_t sb = smem_to_u32(smem);
    const int z = blockIdx.z;
    const __nv_bfloat16* Bh = (z == 0) ? g_wqT_hi : (z == 1) ? g_wkT_hi : g_wvT_hi;
    const __nv_bfloat16* Bl = (z == 0) ? g_wqT_lo : (z == 1) ? g_wkT_lo : g_wvT_lo;
    const float* bias = (z == 0) ? bq : (z == 1) ? bk : bv;
    float* C = (z == 0) ? g_q : (z == 1) ? g_k : nullptr;
    __nv_bfloat16* Chi = (z == 2) ? g_vhi : nullptr;
    __nv_bfloat16* Clo = (z == 2) ? g_vlo : nullptr;
    gemm_core(Ahi, Alo, Bh, Bl, bias, C, Chi, Clo, sb,
              blockIdx.y << 7, blockIdx.x << 7);
}

// output projection
__global__ __launch_bounds__(256, 2)
void gemm_out_kernel(const __nv_bfloat16* __restrict__ Ahi,
                     const __nv_bfloat16* __restrict__ Alo,
                     const float* __restrict__ bias,
                     float* __restrict__ C) {
    extern __shared__ char smem[];
    const uint32_t sb = smem_to_u32(smem);
    gemm_core(Ahi, Alo, g_woT_hi, g_woT_lo, bias, C, nullptr, nullptr, sb,
              blockIdx.y << 7, blockIdx.x << 7);
}

// ---------------------------------------------------------------------------
// Fused RMSNorm + RoPE, writes bf16 hi/lo (scale folded in). 1 block/token.
// ---------------------------------------------------------------------------
__global__ __launch_bounds__(256) void normrope_split_kernel(
    const float* __restrict__ src, const float* __restrict__ g,
    const float* __restrict__ cs, const float* __restrict__ sn,
    __nv_bfloat16* __restrict__ hi, __nv_bfloat16* __restrict__ lo,
    float scale) {
    const int s = blockIdx.x;
    const int tid = threadIdx.x;

    float4 v = *(const float4*)&src[(size_t)s * DIMV + (tid << 2)];
    float ss = v.x * v.x + v.y * v.y + v.z * v.z + v.w * v.w;
#pragma unroll
    for (int o = 16; o; o >>= 1) ss += __shfl_xor_sync(0xffffffffu, ss, o);

    __shared__ float red[8];
    __shared__ float rtot;
    if ((tid & 31) == 0) red[tid >> 5] = ss;
    __syncthreads();
    if (tid == 0) {
        float t = 0.f;
#pragma unroll
        for (int i = 0; i < 8; i++) t += red[i];
        rtot = rsqrtf(t * (1.0f / 1024.0f) + 1e-6f);
    }
    __syncthreads();
    const float r = rtot;

    float4 gv = *(const float4*)&g[tid << 2];
    const float a0 = v.x * r * gv.x, b0 = v.y * r * gv.y;
    const float a1 = v.z * r * gv.z, b1 = v.w * r * gv.w;

    const int p0 = tid << 1;
    const int r0 = p0 & 31, r1 = (p0 + 1) & 31;
    const float c0 = cs[s * 32 + r0], s0 = sn[s * 32 + r0];
    const float c1 = cs[s * 32 + r1], s1 = sn[s * 32 + r1];

    float o0 = (a0 * c0 - b0 * s0) * scale;
    float o1 = (a0 * s0 + b0 * c0) * scale;
    float o2 = (a1 * c1 - b1 * s1) * scale;
    float o3 = (a1 * s1 + b1 * c1) * scale;

    B4 h, l;
    bsplit(o0, h.v[0], l.v[0]);
    bsplit(o1, h.v[1], l.v[1]);
    bsplit(o2, h.v[2], l.v[2]);
    bsplit(o3, h.v[3], l.v[3]);
    const size_t idx = (size_t)s * (DIMV / 4) + tid;
    ((B4*)hi)[idx] = h;
    ((B4*)lo)[idx] = l;
}

// ===========================================================================
// Tensor-core flash attention: 64 q/CTA, 4 warps, BK=64.
// Smem = 2 x 32KB stages only (Q borrows stage 0 during prologue) -> 3 CTA/SM.
// ===========================================================================
#define ATT_STAGE 32768
#define ATT_SMEM  (2 * ATT_STAGE)

__global__ __launch_bounds__(128)
void attn_tc_kernel(const __nv_bfloat16* __restrict__ qhi, const __nv_bfloat16* __restrict__ qlo,
                    const __nv_bfloat16* __restrict__ khi, const __nv_bfloat16* __restrict__ klo,
                    const __nv_bfloat16* __restrict__ vhi, const __nv_bfloat16* __restrict__ vlo,
                    __nv_bfloat16* __restrict__ ohi, __nv_bfloat16* __restrict__ olo) {
    extern __shared__ char smem[];
    const uint32_t sb = smem_to_u32(smem);
    const int d = blockIdx.z, h = blockIdx.y;
    const int q0 = blockIdx.x << 6;
    const int tid = threadIdx.x;
    const int warp = tid >> 5, lane = tid & 31;
    const int wq = warp << 4;
    const int lr = lane & 15, lhf = lane >> 4;
    const int qr = lane >> 2, qc = (lane & 3) << 1;

    // --- prologue: borrow stage-0 smem for the Q hi/lo tiles ---
#pragma unroll
    for (int t = 0; t < 4; t++) {
        const int idx = tid + (t << 7);
        const int r = idx >> 3, ch = idx & 7;
        const int tok = dil2orig(d, q0 + r);
        const size_t go = (size_t)tok * DIMV + h * HD + (ch << 3);
        *(uint4*)(smem + att_off(r, ch)) = *(const uint4*)&qhi[go];
        *(uint4*)(smem + 8192 + att_off(r, ch)) = *(const uint4*)&qlo[go];
    }
    __syncthreads();

    uint32_t qh[4][4], ql[4][4];
#pragma unroll
    for (int s = 0; s < 4; s++) {
        ldsm4(qh[s], sb + att_off(wq + lr, (s << 1) + lhf));
        ldsm4(ql[s], sb + 8192 + att_off(wq + lr, (s << 1) + lhf));
    }
    __syncthreads();   // all warps done reading Q; stages may overwrite

    float m0 = -1e30f, m1 = -1e30f, l0 = 0.f, l1 = 0.f;
    float o[8][4];
#pragma unroll
    for (int j = 0; j < 8; j++)
#pragma unroll
        for (int k = 0; k < 4; k++) o[j][k] = 0.f;

    const int kt_lo = (q0 >= WIN) ? (q0 - WIN) : 0;
    const int kt_hi = min(SD, q0 + BQ + WIN);
    const int row0 = q0 + wq + qr, row1 = row0 + 8;

    auto stage_load = [&](int st, int kt) {
        const uint32_t stg = sb + st * ATT_STAGE;
#pragma unroll
        for (int t = 0; t < 16; t++) {
            const int cid = tid + (t << 7);
            const int buf = cid >> 9;
            const int idx = cid & 511;
            const int r = idx >> 3, ch = idx & 7;
            const int pk = kt + r;
            const int ok = pk < SREAL;
            const int tok = ok ? dil2orig(d, pk) : 0;
            const size_t go = (size_t)tok * DIMV + h * HD + (ch << 3);
            const __nv_bfloat16* src = (buf == 0) ? khi : (buf == 1) ? klo
                                      : (buf == 2) ? vhi : vlo;
            cp_async16z(stg + (buf << 13) + att_off(r, ch), src + go, ok ? 16 : 0);
        }
    };

    stage_load(0, kt_lo);
    CP_COMMIT();

    int st = 0;
    for (int kt = kt_lo; kt < kt_hi; kt += BK, st ^= 1) {
        CP_WAIT0();
        __syncthreads();
        if (kt + BK < kt_hi) { stage_load(st ^ 1, kt + BK); CP_COMMIT(); }

        const uint32_t sK  = sb + st * ATT_STAGE;
        const uint32_t sKl = sK + 8192, sV = sK + 16384, sVl = sK + 24576;

        // --- scores ---
        float c[8][4];
#pragma unroll
        for (int j = 0; j < 8; j++)
#pragma unroll
            for (int k = 0; k < 4; k++) c[j][k] = 0.f;

#pragma unroll
        for (int s = 0; s < 4; s++) {
#pragma unroll
            for (int g = 0; g < 4; g++) {
                uint32_t bh[4], bl[4];
                ldsm4(bh, sK + att_off((g << 4) + lr, (s << 1) + lhf));
                ldsm4(bl, sKl + att_off((g << 4) + lr, (s << 1) + lhf));
                mma16816(c[2 * g],     qh[s], bh[0], bh[2]);
                mma16816(c[2 * g + 1], qh[s], bh[1], bh[3]);
                mma16816(c[2 * g],     ql[s], bh[0], bh[2]);
                mma16816(c[2 * g + 1], ql[s], bh[1], bh[3]);
                mma16816(c[2 * g],     qh[s], bl[0], bl[2]);
                mma16816(c[2 * g + 1], qh[s], bl[1], bl[3]);
            }
        }

        // --- window mask (edge tiles only) ---
        const bool edge = (kt < q0 - WIN + BK) || (kt >= q0 + WIN);
        if (edge) {
#pragma unroll
            for (int j = 0; j < 8; j++) {
                const int pk = kt + (j << 3) + qc;
                if (abs(row0 - pk) > WIN)       c[j][0] = -1e9f;
                if (abs(row0 - pk - 1) > WIN)   c[j][1] = -1e9f;
                if (abs(row1 - pk) > WIN)       c[j][2] = -1e9f;
                if (abs(row1 - pk - 1) > WIN)   c[j][3] = -1e9f;
            }
        }

        // --- online softmax ---
        float tm0 = -1e30f, tm1 = -1e30f;
#pragma unroll
        for (int j = 0; j < 8; j++) {
            tm0 = fmaxf(tm0, fmaxf(c[j][0], c[j][1]));
            tm1 = fmaxf(tm1, fmaxf(c[j][2], c[j][3]));
        }
        tm0 = fmaxf(tm0, __shfl_xor_sync(0xffffffffu, tm0, 1));
        tm0 = fmaxf(tm0, __shfl_xor_sync(0xffffffffu, tm0, 2));
        tm1 = fmaxf(tm1, __shfl_xor_sync(0xffffffffu, tm1, 1));
        tm1 = fmaxf(tm1, __shfl_xor_sync(0xffffffffu, tm1, 2));

        const float mn0 = fmaxf(m0, tm0), mn1 = fmaxf(m1, tm1);
        const float cor0 = __expf(m0 - mn0), cor1 = __expf(m1 - mn1);
        m0 = mn0; m1 = mn1;

        float s0 = 0.f, s1 = 0.f;
#pragma unroll
        for (int j = 0; j < 8; j++) {
            c[j][0] = __expf(c[j][0] - mn0);
            c[j][1] = __expf(c[j][1] - mn0);
            c[j][2] = __expf(c[j][2] - mn1);
            c[j][3] = __expf(c[j][3] - mn1);
            s0 += c[j][0] + c[j][1];
            s1 += c[j][2] + c[j][3];
        }
        s0 += __shfl_xor_sync(0xffffffffu, s0, 1);
        s0 += __shfl_xor_sync(0xffffffffu, s0, 2);
        s1 += __shfl_xor_sync(0xffffffffu, s1, 1);
        s1 += __shfl_xor_sync(0xffffffffu, s1, 2);
        l0 = l0 * cor0 + s0;
        l1 = l1 * cor1 + s1;
#pragma unroll
        for (int j = 0; j < 8; j++) {
            o[j][0] *= cor0; o[j][1] *= cor0;
            o[j][2] *= cor1; o[j][3] *= cor1;
        }

        // --- PV ---
#pragma unroll
        for (int s = 0; s < 4; s++) {
            uint32_t ah[4], al[4];
#pragma unroll
            for (int half = 0; half < 2; half++) {
                const int j = 2 * s + half;
                const float p0 = c[j][0], p1 = c[j][1];
                const float p2 = c[j][2], p3 = c[j][3];
                const float h0 = __bfloat162float(__float2bfloat16(p0));
                const float h1 = __bfloat162float(__float2bfloat16(p1));
                const float h2 = __bfloat162float(__float2bfloat16(p2));
                const float h3 = __bfloat162float(__float2bfloat16(p3));
                ah[2 * half]     = pack_bf16x2(h0, h1);
                ah[2 * half + 1] = pack_bf16x2(h2, h3);
                al[2 * half]     = pack_bf16x2(p0 - h0, p1 - h1);
                al[2 * half + 1] = pack_bf16x2(p2 - h2, p3 - h3);
            }
#pragma unroll
            for (int g = 0; g < 4; g++) {
                uint32_t bh[4], bl[4];
                ldsm4t(bh, sV + att_off((s << 4) + lr, (g << 1) + lhf));
                ldsm4t(bl, sVl + att_off((s << 4) + lr, (g << 1) + lhf));
                mma16816(o[2 * g],     ah, bh[0], bh[1]);
                mma16816(o[2 * g + 1], ah, bh[2], bh[3]);
                mma16816(o[2 * g],     al, bh[0], bh[1]);
                mma16816(o[2 * g + 1], al, bh[2], bh[3]);
                mma16816(o[2 * g],     ah, bl[0], bl[1]);
                mma16816(o[2 * g + 1], ah, bl[2], bl[3]);
            }
        }
        // (no bottom sync: next iteration's CP_WAIT0 + __syncthreads protects
        //  stage reuse — prefetch into this stage is only issued after it)
    }

    // --- epilogue: normalize, split to bf16 hi/lo, store ---
    const float inv0 = 1.0f / l0, inv1 = 1.0f / l1;
    const int tok0 = dil2orig(d, row0);
    const int tok1 = dil2orig(d, row1);
#pragma unroll
    for (int j = 0; j < 8; j++) {
        const int col = h * HD + (j << 3) + qc;
        const float a0 = o[j][0] * inv0, a1 = o[j][1] * inv0;
        const float b0 = o[j][2] * inv1, b1 = o[j][3] * inv1;
        const float a0h = __bfloat162float(__float2bfloat16(a0));
        const float a1h = __bfloat162float(__float2bfloat16(a1));
        const float b0h = __bfloat162float(__float2bfloat16(b0));
        const float b1h = __bfloat162float(__float2bfloat16(b1));
        *(uint32_t*)&ohi[(size_t)tok0 * DIMV + col] = pack_bf16x2(a0h, a1h);
        *(uint32_t*)&olo[(size_t)tok0 * DIMV + col] = pack_bf16x2(a0 - a0h, a1 - a1h);
        *(uint32_t*)&ohi[(size_t)tok1 * DIMV + col] = pack_bf16x2(b0h, b1h);
        *(uint32_t*)&olo[(size_t)tok1 * DIMV + col] = pack_bf16x2(b0 - b0h, b1 - b1h);
    }
}

// ---------------------------------------------------------------------------
extern "C" void kernel_launch(void* const* d_in, const int* in_sizes, int n_in,
                              void* d_out, int out_size) {
    (void)in_sizes; (void)n_in; (void)out_size;
    const float* x  = (const float*)d_in[0];
    const float* fc = (const float*)d_in[1];
    const float* fs = (const float*)d_in[2];
    const float* wq = (const float*)d_in[3];
    const float* bq = (const float*)d_in[4];
    const float* wk = (const float*)d_in[5];
    const float* bk = (const float*)d_in[6];
    const float* wv = (const float*)d_in[7];
    const float* bv = (const float*)d_in[8];
    const float* wo = (const float*)d_in[9];
    const float* bo = (const float*)d_in[10];
    const float* gq = (const float*)d_in[11];
    const float* gk = (const float*)d_in[12];
    float* out = (float*)d_out;

    float *qb, *kb;
    cudaGetSymbolAddress((void**)&qb, g_q);
    cudaGetSymbolAddress((void**)&kb, g_k);
    __nv_bfloat16 *ahi, *alo, *qhi, *qlo, *khi, *klo, *vhi, *vlo;
    cudaGetSymbolAddress((void**)&ahi, g_ahi);
    cudaGetSymbolAddress((void**)&alo, g_alo);
    cudaGetSymbolAddress((void**)&qhi, g_qhi);
    cudaGetSymbolAddress((void**)&qlo, g_qlo);
    cudaGetSymbolAddress((void**)&khi, g_khi);
    cudaGetSymbolAddress((void**)&klo, g_klo);
    cudaGetSymbolAddress((void**)&vhi, g_vhi);
    cudaGetSymbolAddress((void**)&vlo, g_vlo);

    cudaFuncSetAttribute(gemm_qkv_kernel,
                         cudaFuncAttributeMaxDynamicSharedMemorySize, GEMM_SMEM_REQ);
    cudaFuncSetAttribute(gemm_out_kernel,
                         cudaFuncAttributeMaxDynamicSharedMemorySize, GEMM_SMEM_REQ);
    cudaFuncSetAttribute(attn_tc_kernel,
                         cudaFuncAttributeMaxDynamicSharedMemorySize, ATT_SMEM);

    wsplit_all_kernel<<<dim3(32, 32, 4), 256>>>(wq, wk, wv, wo);
    split_kernel<<<(S_LEN * DIMV) / 1024, 256>>>(x, ahi, alo);
    gemm_qkv_kernel<<<dim3(DIMV / 128, S_LEN / 128, 3), 256, GEMM_SMEM_REQ>>>(
        ahi, alo, bq, bk, bv);
    normrope_split_kernel<<<S_LEN, 256>>>(qb, gq, fc, fs, qhi, qlo, 0.125f);
    normrope_split_kernel<<<S_LEN, 256>>>(kb, gk, fc, fs, khi, klo, 1.0f);
    attn_tc_kernel<<<dim3(SREAL / BQ, NH, 2), 128, ATT_SMEM>>>(
        qhi, qlo, khi, klo, vhi, vlo, ahi, alo);
    gemm_out_kernel<<<dim3(DIMV / 128, S_LEN / 128), 256, GEMM_SMEM_REQ>>>(
        ahi, alo, bo, out);
}

// round 9
// speedup vs baseline: 1.3748x; 1.2013x over previous
#include <cuda_runtime.h>
#include <cuda_bf16.h>
#include <cuda_fp16.h>
#include <math.h>
#include <stdint.h>

#define S_LEN 8704
#define DIMV  1024
#define NH    16
#define HD    64
#define SD    4608
#define SREAL 4352
#define WIN   512
#define BQ    64
#define BK    64

// fp32 activation buffers
__device__ float g_q[S_LEN * DIMV];
__device__ float g_k[S_LEN * DIMV];

// fp16 split activations (GEMM A operands: x, attention output)
__device__ __half g_ahi[S_LEN * DIMV];
__device__ __half g_alo[S_LEN * DIMV];

// bf16 split attention operands
__device__ __nv_bfloat16 g_qhi[S_LEN * DIMV];
__device__ __nv_bfloat16 g_qlo[S_LEN * DIMV];
__device__ __nv_bfloat16 g_khi[S_LEN * DIMV];
__device__ __nv_bfloat16 g_klo[S_LEN * DIMV];
__device__ __nv_bfloat16 g_vhi[S_LEN * DIMV];
__device__ __nv_bfloat16 g_vlo[S_LEN * DIMV];

// fp16 transposed weights [N][K] (hi only — 2-pass scheme)
__device__ __half g_wqT[DIMV * DIMV];
__device__ __half g_wkT[DIMV * DIMV];
__device__ __half g_wvT[DIMV * DIMV];
__device__ __half g_woT[DIMV * DIMV];

__device__ __forceinline__ int dil2orig(int d, int p) {
    return ((p >> 8) << 9) + (d << 8) + (p & 255);
}

__device__ __forceinline__ uint32_t smem_to_u32(const void* smem_ptr) {
    uint32_t addr;
    asm("{ .reg .u64 tmp; cvta.to.shared.u64 tmp, %1; cvt.u32.u64 %0, tmp; }"
        : "=r"(addr) : "l"(smem_ptr));
    return addr;
}

// ===========================================================================
// family-generic tensor-core primitives
// ===========================================================================
__device__ __forceinline__ void ldsm4(uint32_t* r, uint32_t addr) {
    asm volatile("ldmatrix.sync.aligned.m8n8.x4.shared.b16 {%0,%1,%2,%3}, [%4];\n"
                 : "=r"(r[0]), "=r"(r[1]), "=r"(r[2]), "=r"(r[3]) : "r"(addr));
}
__device__ __forceinline__ void ldsm4t(uint32_t* r, uint32_t addr) {
    asm volatile("ldmatrix.sync.aligned.m8n8.x4.trans.shared.b16 {%0,%1,%2,%3}, [%4];\n"
                 : "=r"(r[0]), "=r"(r[1]), "=r"(r[2]), "=r"(r[3]) : "r"(addr));
}
// bf16 mma
__device__ __forceinline__ void mma16816(float* c, const uint32_t* a,
                                         uint32_t b0, uint32_t b1) {
    asm volatile(
        "mma.sync.aligned.m16n8k16.row.col.f32.bf16.bf16.f32 "
        "{%0,%1,%2,%3}, {%4,%5,%6,%7}, {%8,%9}, {%0,%1,%2,%3};\n"
        : "+f"(c[0]), "+f"(c[1]), "+f"(c[2]), "+f"(c[3])
        : "r"(a[0]), "r"(a[1]), "r"(a[2]), "r"(a[3]), "r"(b0), "r"(b1));
}
// fp16 mma (fp32 accumulate)
__device__ __forceinline__ void mma16816h(float* c, const uint32_t* a,
                                          uint32_t b0, uint32_t b1) {
    asm volatile(
        "mma.sync.aligned.m16n8k16.row.col.f32.f16.f16.f32 "
        "{%0,%1,%2,%3}, {%4,%5,%6,%7}, {%8,%9}, {%0,%1,%2,%3};\n"
        : "+f"(c[0]), "+f"(c[1]), "+f"(c[2]), "+f"(c[3])
        : "r"(a[0]), "r"(a[1]), "r"(a[2]), "r"(a[3]), "r"(b0), "r"(b1));
}
__device__ __forceinline__ void cp_async16(uint32_t saddr, const void* gptr) {
    asm volatile("cp.async.cg.shared.global [%0], [%1], 16;\n"
                 :: "r"(saddr), "l"(gptr));
}
__device__ __forceinline__ void cp_async16z(uint32_t saddr, const void* gptr, int srcbytes) {
    asm volatile("cp.async.cg.shared.global [%0], [%1], 16, %2;\n"
                 :: "r"(saddr), "l"(gptr), "r"(srcbytes));
}
#define CP_COMMIT() asm volatile("cp.async.commit_group;\n" ::: "memory")
#define CP_WAIT0()  asm volatile("cp.async.wait_group 0;\n" ::: "memory")

// gemm smem tile layout: 128 rows x 32 elem (4 x 16B chunks/row)
__device__ __forceinline__ uint32_t sw_off(int r, int c) {
    return (uint32_t)(((r >> 1) << 7) + ((r & 1) << 6) +
                      (((c ^ ((r >> 1) & 3)) & 3) << 4));
}
// attn smem tile layout: rows x 64 elem (8 x 16B chunks/row), xor swizzle
__device__ __forceinline__ uint32_t att_off(int r, int ch) {
    return (uint32_t)((r << 7) + (((ch ^ (r & 7)) & 7) << 4));
}

__device__ __forceinline__ uint32_t pack_bf16x2(float a, float b) {
    __nv_bfloat162 t = __floats2bfloat162_rn(a, b);
    return *(uint32_t*)&t;
}
__device__ __forceinline__ uint32_t pack_f16x2(float a, float b) {
    __half2 t = __floats2half2_rn(a, b);
    return *(uint32_t*)&t;
}

// ===========================================================================
// split helpers
// ===========================================================================
__device__ __forceinline__ void bsplit(float f, __nv_bfloat16& h, __nv_bfloat16& l) {
    h = __float2bfloat16(f);
    l = __float2bfloat16(f - __bfloat162float(h));
}
__device__ __forceinline__ void hsplit(float f, __half& h, __half& l) {
    h = __float2half(f);
    l = __float2half(f - __half2float(h));
}

struct __align__(8) H4 { __half v[4]; };

// elementwise fp16 split: x -> hi/lo
__global__ __launch_bounds__(256) void split_kernel(
    const float* __restrict__ src, __half* __restrict__ hi,
    __half* __restrict__ lo) {
    const int idx = blockIdx.x * 256 + threadIdx.x;
    float4 v = ((const float4*)src)[idx];
    H4 h, l;
    hsplit(v.x, h.v[0], l.v[0]);
    hsplit(v.y, h.v[1], l.v[1]);
    hsplit(v.z, h.v[2], l.v[2]);
    hsplit(v.w, h.v[3], l.v[3]);
    ((H4*)hi)[idx] = h;
    ((H4*)lo)[idx] = l;
}

// transpose + fp16 convert all 4 weights; blockIdx.z selects.
__global__ __launch_bounds__(256) void wsplit_all_kernel(
    const float* __restrict__ wq, const float* __restrict__ wk,
    const float* __restrict__ wv, const float* __restrict__ wo) {
    const int z = blockIdx.z;
    const float* w = (z == 0) ? wq : (z == 1) ? wk : (z == 2) ? wv : wo;
    __half* wT = (z == 0) ? g_wqT : (z == 1) ? g_wkT : (z == 2) ? g_wvT : g_woT;

    __shared__ float t[32][33];
    const int bx = blockIdx.x << 5;
    const int by = blockIdx.y << 5;
    const int tx = threadIdx.x & 31, ty = threadIdx.x >> 5;
#pragma unroll
    for (int i = 0; i < 32; i += 8)
        t[ty + i][tx] = w[(size_t)(by + ty + i) * DIMV + bx + tx];
    __syncthreads();
#pragma unroll
    for (int i = 0; i < 32; i += 8)
        wT[(size_t)(bx + ty + i) * DIMV + by + tx] = __float2half(t[tx][ty + i]);
}

// ===========================================================================
// fp16 2-pass GEMM: C = (Ah + Al) @ BhT + bias
// CTA 128x128, K-stage 32, 3 smem tiles/stage (Ah, Al, Bh) = 24KB.
// ===========================================================================
#define STAGE_BYTES 24576
#define GEMM_SMEM_REQ (2 * STAGE_BYTES)

__device__ __forceinline__ void load_stage(
    uint32_t sbase, const __half* __restrict__ Ahi,
    const __half* __restrict__ Alo, const __half* __restrict__ B,
    int bm, int bn, int k0, int tid) {
#pragma unroll
    for (int j = 0; j < 6; j++) {
        const int chunk = tid + (j << 8);
        const int tile = chunk >> 9;          // 0..2
        const int idx = chunk & 511;
        const int r = idx >> 2, c = idx & 3;
        const uint32_t saddr = sbase + (uint32_t)(tile << 13) + sw_off(r, c);
        const __half* gp;
        if (tile == 0)      gp = Ahi + (size_t)(bm + r) * DIMV + k0 + c * 8;
        else if (tile == 1) gp = Alo + (size_t)(bm + r) * DIMV + k0 + c * 8;
        else                gp = B + (size_t)(bn + r) * DIMV + k0 + c * 8;
        cp_async16(saddr, gp);
    }
}

__device__ __forceinline__ void gemm_core(
    const __half* __restrict__ Ahi, const __half* __restrict__ Alo,
    const __half* __restrict__ B,
    const float* __restrict__ bias, float* __restrict__ C,
    __nv_bfloat16* __restrict__ Chi, __nv_bfloat16* __restrict__ Clo,
    uint32_t sb, int bm, int bn) {
    const int tid = threadIdx.x;
    const int wid = tid >> 5, lane = tid & 31;
    const int wm = (wid & 1) << 6;
    const int wn = (wid >> 1) << 5;
    const int lr = lane & 15;
    const int lhalf = lane >> 4;

    float acc[4][4][4];
#pragma unroll
    for (int i = 0; i < 4; i++)
#pragma unroll
        for (int j = 0; j < 4; j++)
#pragma unroll
            for (int k = 0; k < 4; k++) acc[i][j][k] = 0.f;

    load_stage(sb, Ahi, Alo, B, bm, bn, 0, tid);
    CP_COMMIT();

    for (int s = 0; s < 32; s++) {
        CP_WAIT0();
        __syncthreads();
        if (s + 1 < 32) {
            load_stage(sb + ((s + 1) & 1) * STAGE_BYTES, Ahi, Alo, B,
                       bm, bn, (s + 1) << 5, tid);
            CP_COMMIT();
        }

        const uint32_t buf = sb + (s & 1) * STAGE_BYTES;
#pragma unroll
        for (int kk = 0; kk < 2; kk++) {
            const int cb = (kk << 1) + lhalf;
            uint32_t a[4][4], bh[2][4];
#pragma unroll
            for (int mi = 0; mi < 4; mi++)
                ldsm4(a[mi], buf + sw_off(wm + (mi << 4) + lr, cb));
#pragma unroll
            for (int np = 0; np < 2; np++)
                ldsm4(bh[np], buf + 16384 + sw_off(wn + (np << 4) + lr, cb));
            // pass 1: Ah x B
#pragma unroll
            for (int mi = 0; mi < 4; mi++) {
                mma16816h(acc[mi][0], a[mi], bh[0][0], bh[0][2]);
                mma16816h(acc[mi][1], a[mi], bh[0][1], bh[0][3]);
                mma16816h(acc[mi][2], a[mi], bh[1][0], bh[1][2]);
                mma16816h(acc[mi][3], a[mi], bh[1][1], bh[1][3]);
            }
            // pass 2: Al x B
#pragma unroll
            for (int mi = 0; mi < 4; mi++)
                ldsm4(a[mi], buf + 8192 + sw_off(wm + (mi << 4) + lr, cb));
#pragma unroll
            for (int mi = 0; mi < 4; mi++) {
                mma16816h(acc[mi][0], a[mi], bh[0][0], bh[0][2]);
                mma16816h(acc[mi][1], a[mi], bh[0][1], bh[0][3]);
                mma16816h(acc[mi][2], a[mi], bh[1][0], bh[1][2]);
                mma16816h(acc[mi][3], a[mi], bh[1][1], bh[1][3]);
            }
        }
        __syncthreads();
    }

    const int crow = lane >> 2;
    const int ccol = (lane & 3) << 1;
#pragma unroll
    for (int ni = 0; ni < 4; ni++) {
        const int col = bn + wn + (ni << 3) + ccol;
        const float2 bv = *(const float2*)&bias[col];
#pragma unroll
        for (int mi = 0; mi < 4; mi++) {
            const int row = bm + wm + (mi << 4) + crow;
            const float v00 = acc[mi][ni][0] + bv.x, v01 = acc[mi][ni][1] + bv.y;
            const float v10 = acc[mi][ni][2] + bv.x, v11 = acc[mi][ni][3] + bv.y;
            if (Chi) {
                const float h00 = __bfloat162float(__float2bfloat16(v00));
                const float h01 = __bfloat162float(__float2bfloat16(v01));
                const float h10 = __bfloat162float(__float2bfloat16(v10));
                const float h11 = __bfloat162float(__float2bfloat16(v11));
                *(uint32_t*)&Chi[(size_t)row * DIMV + col] = pack_bf16x2(h00, h01);
                *(uint32_t*)&Clo[(size_t)row * DIMV + col] = pack_bf16x2(v00 - h00, v01 - h01);
                *(uint32_t*)&Chi[(size_t)(row + 8) * DIMV + col] = pack_bf16x2(h10, h11);
                *(uint32_t*)&Clo[(size_t)(row + 8) * DIMV + col] = pack_bf16x2(v10 - h10, v11 - h11);
            } else {
                *(float2*)&C[(size_t)row * DIMV + col] = make_float2(v00, v01);
                *(float2*)&C[(size_t)(row + 8) * DIMV + col] = make_float2(v10, v11);
            }
        }
    }
}

// fused Q/K/V projection: grid (8, 68, 3)
__global__ __launch_bounds__(256, 2)
void gemm_qkv_kernel(const __half* __restrict__ Ahi,
                     const __half* __restrict__ Alo,
                     const float* __restrict__ bq,
                     const float* __restrict__ bk,
                     const float* __restrict__ bv) {
    extern __shared__ char smem[];
    const uint32_t sb = smem_to_u32(smem);
    const int z = blockIdx.z;
    const __half* B = (z == 0) ? g_wqT : (z == 1) ? g_wkT : g_wvT;
    const float* bias = (z == 0) ? bq : (z == 1) ? bk : bv;
    float* C = (z == 0) ? g_q : (z == 1) ? g_k : nullptr;
    __nv_bfloat16* Chi = (z == 2) ? g_vhi : nullptr;
    __nv_bfloat16* Clo = (z == 2) ? g_vlo : nullptr;
    gemm_core(Ahi, Alo, B, bias, C, Chi, Clo, sb,
              blockIdx.y << 7, blockIdx.x << 7);
}

// output projection
__global__ __launch_bounds__(256, 2)
void gemm_out_kernel(const __half* __restrict__ Ahi,
                     const __half* __restrict__ Alo,
                     const float* __restrict__ bias,
                     float* __restrict__ C) {
    extern __shared__ char smem[];
    const uint32_t sb = smem_to_u32(smem);
    gemm_core(Ahi, Alo, g_woT, bias, C, nullptr, nullptr, sb,
              blockIdx.y << 7, blockIdx.x << 7);
}

// ---------------------------------------------------------------------------
// Fused RMSNorm + RoPE + bf16 split, Q and K in one launch (blockIdx.y).
// ---------------------------------------------------------------------------
__global__ __launch_bounds__(256) void normrope_split_kernel(
    const float* __restrict__ srcq, const float* __restrict__ srck,
    const float* __restrict__ gq, const float* __restrict__ gk,
    const float* __restrict__ cs, const float* __restrict__ sn,
    __nv_bfloat16* __restrict__ qhi, __nv_bfloat16* __restrict__ qlo,
    __nv_bfloat16* __restrict__ khi, __nv_bfloat16* __restrict__ klo) {
    const int s = blockIdx.x;
    const int isq = (blockIdx.y == 0);
    const float* src = isq ? srcq : srck;
    const float* g = isq ? gq : gk;
    __nv_bfloat16* hi = isq ? qhi : khi;
    __nv_bfloat16* lo = isq ? qlo : klo;
    const float scale = isq ? 0.125f : 1.0f;
    const int tid = threadIdx.x;

    float4 v = *(const float4*)&src[(size_t)s * DIMV + (tid << 2)];
    float ss = v.x * v.x + v.y * v.y + v.z * v.z + v.w * v.w;
#pragma unroll
    for (int o = 16; o; o >>= 1) ss += __shfl_xor_sync(0xffffffffu, ss, o);

    __shared__ float red[8];
    __shared__ float rtot;
    if ((tid & 31) == 0) red[tid >> 5] = ss;
    __syncthreads();
    if (tid == 0) {
        float t = 0.f;
#pragma unroll
        for (int i = 0; i < 8; i++) t += red[i];
        rtot = rsqrtf(t * (1.0f / 1024.0f) + 1e-6f);
    }
    __syncthreads();
    const float r = rtot;

    float4 gv = *(const float4*)&g[tid << 2];
    const float a0 = v.x * r * gv.x, b0 = v.y * r * gv.y;
    const float a1 = v.z * r * gv.z, b1 = v.w * r * gv.w;

    const int p0 = tid << 1;
    const int r0 = p0 & 31, r1 = (p0 + 1) & 31;
    const float c0 = cs[s * 32 + r0], s0 = sn[s * 32 + r0];
    const float c1 = cs[s * 32 + r1], s1 = sn[s * 32 + r1];

    float o0 = (a0 * c0 - b0 * s0) * scale;
    float o1 = (a0 * s0 + b0 * c0) * scale;
    float o2 = (a1 * c1 - b1 * s1) * scale;
    float o3 = (a1 * s1 + b1 * c1) * scale;

    __nv_bfloat16 h0, l0_, h1, l1_, h2, l2_, h3, l3_;
    bsplit(o0, h0, l0_); bsplit(o1, h1, l1_);
    bsplit(o2, h2, l2_); bsplit(o3, h3, l3_);
    const size_t base = (size_t)s * DIMV + (tid << 2);
    *(uint32_t*)&hi[base] = pack_bf16x2(__bfloat162float(h0), __bfloat162float(h1));
    *(uint32_t*)&hi[base + 2] = pack_bf16x2(__bfloat162float(h2), __bfloat162float(h3));
    *(uint32_t*)&lo[base] = pack_bf16x2(__bfloat162float(l0_), __bfloat162float(l1_));
    *(uint32_t*)&lo[base + 2] = pack_bf16x2(__bfloat162float(l2_), __bfloat162float(l3_));
}

// ===========================================================================
// Tensor-core flash attention (bf16 3-pass, unchanged math); fp16 output.
// ===========================================================================
#define ATT_STAGE 32768
#define ATT_SMEM  (2 * ATT_STAGE)

__global__ __launch_bounds__(128)
void attn_tc_kernel(const __nv_bfloat16* __restrict__ qhi, const __nv_bfloat16* __restrict__ qlo,
                    const __nv_bfloat16* __restrict__ khi, const __nv_bfloat16* __restrict__ klo,
                    const __nv_bfloat16* __restrict__ vhi, const __nv_bfloat16* __restrict__ vlo,
                    __half* __restrict__ ohi, __half* __restrict__ olo) {
    extern __shared__ char smem[];
    const uint32_t sb = smem_to_u32(smem);
    const int d = blockIdx.z, h = blockIdx.y;
    const int q0 = blockIdx.x << 6;
    const int tid = threadIdx.x;
    const int warp = tid >> 5, lane = tid & 31;
    const int wq = warp << 4;
    const int lr = lane & 15, lhf = lane >> 4;
    const int qr = lane >> 2, qc = (lane & 3) << 1;

    // prologue: borrow stage-0 smem for Q hi/lo
#pragma unroll
    for (int t = 0; t < 4; t++) {
        const int idx = tid + (t << 7);
        const int r = idx >> 3, ch = idx & 7;
        const int tok = dil2orig(d, q0 + r);
        const size_t go = (size_t)tok * DIMV + h * HD + (ch << 3);
        *(uint4*)(smem + att_off(r, ch)) = *(const uint4*)&qhi[go];
        *(uint4*)(smem + 8192 + att_off(r, ch)) = *(const uint4*)&qlo[go];
    }
    __syncthreads();

    uint32_t qh[4][4], ql[4][4];
#pragma unroll
    for (int s = 0; s < 4; s++) {
        ldsm4(qh[s], sb + att_off(wq + lr, (s << 1) + lhf));
        ldsm4(ql[s], sb + 8192 + att_off(wq + lr, (s << 1) + lhf));
    }
    __syncthreads();

    float m0 = -1e30f, m1 = -1e30f, l0 = 0.f, l1 = 0.f;
    float o[8][4];
#pragma unroll
    for (int j = 0; j < 8; j++)
#pragma unroll
        for (int k = 0; k < 4; k++) o[j][k] = 0.f;

    const int kt_lo = (q0 >= WIN) ? (q0 - WIN) : 0;
    const int kt_hi = min(SD, q0 + BQ + WIN);
    const int row0 = q0 + wq + qr, row1 = row0 + 8;

    auto stage_load = [&](int st, int kt) {
        const uint32_t stg = sb + st * ATT_STAGE;
#pragma unroll
        for (int t = 0; t < 16; t++) {
            const int cid = tid + (t << 7);
            const int buf = cid >> 9;
            const int idx = cid & 511;
            const int r = idx >> 3, ch = idx & 7;
            const int pk = kt + r;
            const int ok = pk < SREAL;
            const int tok = ok ? dil2orig(d, pk) : 0;
            const size_t go = (size_t)tok * DIMV + h * HD + (ch << 3);
            const __nv_bfloat16* src = (buf == 0) ? khi : (buf == 1) ? klo
                                      : (buf == 2) ? vhi : vlo;
            cp_async16z(stg + (buf << 13) + att_off(r, ch), src + go, ok ? 16 : 0);
        }
    };

    stage_load(0, kt_lo);
    CP_COMMIT();

    int st = 0;
    for (int kt = kt_lo; kt < kt_hi; kt += BK, st ^= 1) {
        CP_WAIT0();
        __syncthreads();
        if (kt + BK < kt_hi) { stage_load(st ^ 1, kt + BK); CP_COMMIT(); }

        const uint32_t sK  = sb + st * ATT_STAGE;
        const uint32_t sKl = sK + 8192, sV = sK + 16384, sVl = sK + 24576;

        float c[8][4];
#pragma unroll
        for (int j = 0; j < 8; j++)
#pragma unroll
            for (int k = 0; k < 4; k++) c[j][k] = 0.f;

#pragma unroll
        for (int s = 0; s < 4; s++) {
#pragma unroll
            for (int g = 0; g < 4; g++) {
                uint32_t bh[4], bl[4];
                ldsm4(bh, sK + att_off((g << 4) + lr, (s << 1) + lhf));
                ldsm4(bl, sKl + att_off((g << 4) + lr, (s << 1) + lhf));
                mma16816(c[2 * g],     qh[s], bh[0], bh[2]);
                mma16816(c[2 * g + 1], qh[s], bh[1], bh[3]);
                mma16816(c[2 * g],     ql[s], bh[0], bh[2]);
                mma16816(c[2 * g + 1], ql[s], bh[1], bh[3]);
                mma16816(c[2 * g],     qh[s], bl[0], bl[2]);
                mma16816(c[2 * g + 1], qh[s], bl[1], bl[3]);
            }
        }

        const bool edge = (kt < q0 - WIN + BK) || (kt >= q0 + WIN);
        if (edge) {
#pragma unroll
            for (int j = 0; j < 8; j++) {
                const int pk = kt + (j << 3) + qc;
                if (abs(row0 - pk) > WIN)       c[j][0] = -1e9f;
                if (abs(row0 - pk - 1) > WIN)   c[j][1] = -1e9f;
                if (abs(row1 - pk) > WIN)       c[j][2] = -1e9f;
                if (abs(row1 - pk - 1) > WIN)   c[j][3] = -1e9f;
            }
        }

        float tm0 = -1e30f, tm1 = -1e30f;
#pragma unroll
        for (int j = 0; j < 8; j++) {
            tm0 = fmaxf(tm0, fmaxf(c[j][0], c[j][1]));
            tm1 = fmaxf(tm1, fmaxf(c[j][2], c[j][3]));
        }
        tm0 = fmaxf(tm0, __shfl_xor_sync(0xffffffffu, tm0, 1));
        tm0 = fmaxf(tm0, __shfl_xor_sync(0xffffffffu, tm0, 2));
        tm1 = fmaxf(tm1, __shfl_xor_sync(0xffffffffu, tm1, 1));
        tm1 = fmaxf(tm1, __shfl_xor_sync(0xffffffffu, tm1, 2));

        const float mn0 = fmaxf(m0, tm0), mn1 = fmaxf(m1, tm1);
        const float cor0 = __expf(m0 - mn0), cor1 = __expf(m1 - mn1);
        m0 = mn0; m1 = mn1;

        float s0 = 0.f, s1 = 0.f;
#pragma unroll
        for (int j = 0; j < 8; j++) {
            c[j][0] = __expf(c[j][0] - mn0);
            c[j][1] = __expf(c[j][1] - mn0);
            c[j][2] = __expf(c[j][2] - mn1);
            c[j][3] = __expf(c[j][3] - mn1);
            s0 += c[j][0] + c[j][1];
            s1 += c[j][2] + c[j][3];
        }
        s0 += __shfl_xor_sync(0xffffffffu, s0, 1);
        s0 += __shfl_xor_sync(0xffffffffu, s0, 2);
        s1 += __shfl_xor_sync(0xffffffffu, s1, 1);
        s1 += __shfl_xor_sync(0xffffffffu, s1, 2);
        l0 = l0 * cor0 + s0;
        l1 = l1 * cor1 + s1;
#pragma unroll
        for (int j = 0; j < 8; j++) {
            o[j][0] *= cor0; o[j][1] *= cor0;
            o[j][2] *= cor1; o[j][3] *= cor1;
        }

#pragma unroll
        for (int s = 0; s < 4; s++) {
            uint32_t ah[4], al[4];
#pragma unroll
            for (int half = 0; half < 2; half++) {
                const int j = 2 * s + half;
                const float p0 = c[j][0], p1 = c[j][1];
                const float p2 = c[j][2], p3 = c[j][3];
                const float h0 = __bfloat162float(__float2bfloat16(p0));
                const float h1 = __bfloat162float(__float2bfloat16(p1));
                const float h2 = __bfloat162float(__float2bfloat16(p2));
                const float h3 = __bfloat162float(__float2bfloat16(p3));
                ah[2 * half]     = pack_bf16x2(h0, h1);
                ah[2 * half + 1] = pack_bf16x2(h2, h3);
                al[2 * half]     = pack_bf16x2(p0 - h0, p1 - h1);
                al[2 * half + 1] = pack_bf16x2(p2 - h2, p3 - h3);
            }
#pragma unroll
            for (int g = 0; g < 4; g++) {
                uint32_t bh[4], bl[4];
                ldsm4t(bh, sV + att_off((s << 4) + lr, (g << 1) + lhf));
                ldsm4t(bl, sVl + att_off((s << 4) + lr, (g << 1) + lhf));
                mma16816(o[2 * g],     ah, bh[0], bh[1]);
                mma16816(o[2 * g + 1], ah, bh[2], bh[3]);
                mma16816(o[2 * g],     al, bh[0], bh[1]);
                mma16816(o[2 * g + 1], al, bh[2], bh[3]);
                mma16816(o[2 * g],     ah, bl[0], bl[1]);
                mma16816(o[2 * g + 1], ah, bl[2], bl[3]);
            }
        }
    }

    // epilogue: normalize, fp16 split, store (feeds fp16 out-GEMM)
    const float inv0 = 1.0f / l0, inv1 = 1.0f / l1;
    const int tok0 = dil2orig(d, row0);
    const int tok1 = dil2orig(d, row1);
#pragma unroll
    for (int j = 0; j < 8; j++) {
        const int col = h * HD + (j << 3) + qc;
        const float a0 = o[j][0] * inv0, a1 = o[j][1] * inv0;
        const float b0 = o[j][2] * inv1, b1 = o[j][3] * inv1;
        const float a0h = __half2float(__float2half(a0));
        const float a1h = __half2float(__float2half(a1));
        const float b0h = __half2float(__float2half(b0));
        const float b1h = __half2float(__float2half(b1));
        *(uint32_t*)&ohi[(size_t)tok0 * DIMV + col] = pack_f16x2(a0h, a1h);
        *(uint32_t*)&olo[(size_t)tok0 * DIMV + col] = pack_f16x2(a0 - a0h, a1 - a1h);
        *(uint32_t*)&ohi[(size_t)tok1 * DIMV + col] = pack_f16x2(b0h, b1h);
        *(uint32_t*)&olo[(size_t)tok1 * DIMV + col] = pack_f16x2(b0 - b0h, b1 - b1h);
    }
}

// ---------------------------------------------------------------------------
extern "C" void kernel_launch(void* const* d_in, const int* in_sizes, int n_in,
                              void* d_out, int out_size) {
    (void)in_sizes; (void)n_in; (void)out_size;
    const float* x  = (const float*)d_in[0];
    const float* fc = (const float*)d_in[1];
    const float* fs = (const float*)d_in[2];
    const float* wq = (const float*)d_in[3];
    const float* bq = (const float*)d_in[4];
    const float* wk = (const float*)d_in[5];
    const float* bk = (const float*)d_in[6];
    const float* wv = (const float*)d_in[7];
    const float* bv = (const float*)d_in[8];
    const float* wo = (const float*)d_in[9];
    const float* bo = (const float*)d_in[10];
    const float* gq = (const float*)d_in[11];
    const float* gk = (const float*)d_in[12];
    float* out = (float*)d_out;

    float *qb, *kb;
    cudaGetSymbolAddress((void**)&qb, g_q);
    cudaGetSymbolAddress((void**)&kb, g_k);
    __half *ahi, *alo;
    cudaGetSymbolAddress((void**)&ahi, g_ahi);
    cudaGetSymbolAddress((void**)&alo, g_alo);
    __nv_bfloat16 *qhi, *qlo, *khi, *klo, *vhi, *vlo;
    cudaGetSymbolAddress((void**)&qhi, g_qhi);
    cudaGetSymbolAddress((void**)&qlo, g_qlo);
    cudaGetSymbolAddress((void**)&khi, g_khi);
    cudaGetSymbolAddress((void**)&klo, g_klo);
    cudaGetSymbolAddress((void**)&vhi, g_vhi);
    cudaGetSymbolAddress((void**)&vlo, g_vlo);

    cudaFuncSetAttribute(gemm_qkv_kernel,
                         cudaFuncAttributeMaxDynamicSharedMemorySize, GEMM_SMEM_REQ);
    cudaFuncSetAttribute(gemm_out_kernel,
                         cudaFuncAttributeMaxDynamicSharedMemorySize, GEMM_SMEM_REQ);
    cudaFuncSetAttribute(attn_tc_kernel,
                         cudaFuncAttributeMaxDynamicSharedMemorySize, ATT_SMEM);

    wsplit_all_kernel<<<dim3(32, 32, 4), 256>>>(wq, wk, wv, wo);
    split_kernel<<<(S_LEN * DIMV) / 1024, 256>>>(x, ahi, alo);
    gemm_qkv_kernel<<<dim3(DIMV / 128, S_LEN / 128, 3), 256, GEMM_SMEM_REQ>>>(
        ahi, alo, bq, bk, bv);
    normrope_split_kernel<<<dim3(S_LEN, 2), 256>>>(qb, kb, gq, gk, fc, fs,
                                                   qhi, qlo, khi, klo);
    attn_tc_kernel<<<dim3(SREAL / BQ, NH, 2), 128, ATT_SMEM>>>(
        qhi, qlo, khi, klo, vhi, vlo, ahi, alo);
    gemm_out_kernel<<<dim3(DIMV / 128, S_LEN / 128), 256, GEMM_SMEM_REQ>>>(
        ahi, alo, bo, out);
}

// round 11
// speedup vs baseline: 1.5265x; 1.1104x over previous
#include <cuda_runtime.h>
#include <cuda_bf16.h>
#include <cuda_fp16.h>
#include <math.h>
#include <stdint.h>

#define S_LEN 8704
#define DIMV  1024
#define NH    16
#define HD    64
#define SD    4608
#define SREAL 4352
#define WIN   512
#define BQ    64
#define BK    64

// fp32 activation buffers
__device__ float g_q[S_LEN * DIMV];
__device__ float g_k[S_LEN * DIMV];

// fp16 split activations (GEMM A operands: x, attention output)
__device__ __half g_ahi[S_LEN * DIMV];
__device__ __half g_alo[S_LEN * DIMV];

// bf16 split attention Q/K operands
__device__ __nv_bfloat16 g_qhi[S_LEN * DIMV];
__device__ __nv_bfloat16 g_qlo[S_LEN * DIMV];
__device__ __nv_bfloat16 g_khi[S_LEN * DIMV];
__device__ __nv_bfloat16 g_klo[S_LEN * DIMV];
// fp16 split V (PV runs fp16)
__device__ __half g_vhi[S_LEN * DIMV];
__device__ __half g_vlo[S_LEN * DIMV];

// fp16 transposed weights [N][K]
__device__ __half g_wqT[DIMV * DIMV];
__device__ __half g_wkT[DIMV * DIMV];
__device__ __half g_wvT[DIMV * DIMV];
__device__ __half g_woT[DIMV * DIMV];

__device__ __forceinline__ int dil2orig(int d, int p) {
    return ((p >> 8) << 9) + (d << 8) + (p & 255);
}

__device__ __forceinline__ uint32_t smem_to_u32(const void* smem_ptr) {
    uint32_t addr;
    asm("{ .reg .u64 tmp; cvta.to.shared.u64 tmp, %1; cvt.u32.u64 %0, tmp; }"
        : "=r"(addr) : "l"(smem_ptr));
    return addr;
}

// ===========================================================================
// family-generic tensor-core primitives
// ===========================================================================
__device__ __forceinline__ void ldsm4(uint32_t* r, uint32_t addr) {
    asm volatile("ldmatrix.sync.aligned.m8n8.x4.shared.b16 {%0,%1,%2,%3}, [%4];\n"
                 : "=r"(r[0]), "=r"(r[1]), "=r"(r[2]), "=r"(r[3]) : "r"(addr));
}
__device__ __forceinline__ void ldsm4t(uint32_t* r, uint32_t addr) {
    asm volatile("ldmatrix.sync.aligned.m8n8.x4.trans.shared.b16 {%0,%1,%2,%3}, [%4];\n"
                 : "=r"(r[0]), "=r"(r[1]), "=r"(r[2]), "=r"(r[3]) : "r"(addr));
}
// bf16 mma
__device__ __forceinline__ void mma16816(float* c, const uint32_t* a,
                                         uint32_t b0, uint32_t b1) {
    asm volatile(
        "mma.sync.aligned.m16n8k16.row.col.f32.bf16.bf16.f32 "
        "{%0,%1,%2,%3}, {%4,%5,%6,%7}, {%8,%9}, {%0,%1,%2,%3};\n"
        : "+f"(c[0]), "+f"(c[1]), "+f"(c[2]), "+f"(c[3])
        : "r"(a[0]), "r"(a[1]), "r"(a[2]), "r"(a[3]), "r"(b0), "r"(b1));
}
// fp16 mma (fp32 accumulate)
__device__ __forceinline__ void mma16816h(float* c, const uint32_t* a,
                                          uint32_t b0, uint32_t b1) {
    asm volatile(
        "mma.sync.aligned.m16n8k16.row.col.f32.f16.f16.f32 "
        "{%0,%1,%2,%3}, {%4,%5,%6,%7}, {%8,%9}, {%0,%1,%2,%3};\n"
        : "+f"(c[0]), "+f"(c[1]), "+f"(c[2]), "+f"(c[3])
        : "r"(a[0]), "r"(a[1]), "r"(a[2]), "r"(a[3]), "r"(b0), "r"(b1));
}
__device__ __forceinline__ void cp_async16(uint32_t saddr, const void* gptr) {
    asm volatile("cp.async.cg.shared.global [%0], [%1], 16;\n"
                 :: "r"(saddr), "l"(gptr));
}
__device__ __forceinline__ void cp_async16z(uint32_t saddr, const void* gptr, int srcbytes) {
    asm volatile("cp.async.cg.shared.global [%0], [%1], 16, %2;\n"
                 :: "r"(saddr), "l"(gptr), "r"(srcbytes));
}
#define CP_COMMIT() asm volatile("cp.async.commit_group;\n" ::: "memory")
#define CP_WAIT0()  asm volatile("cp.async.wait_group 0;\n" ::: "memory")
#define CP_WAIT1()  asm volatile("cp.async.wait_group 1;\n" ::: "memory")

// gemm smem tile layout: 128 rows x 32 elem (4 x 16B chunks/row)
__device__ __forceinline__ uint32_t sw_off(int r, int c) {
    return (uint32_t)(((r >> 1) << 7) + ((r & 1) << 6) +
                      (((c ^ ((r >> 1) & 3)) & 3) << 4));
}
// attn smem tile layout: rows x 64 elem (8 x 16B chunks/row), xor swizzle
__device__ __forceinline__ uint32_t att_off(int r, int ch) {
    return (uint32_t)((r << 7) + (((ch ^ (r & 7)) & 7) << 4));
}

__device__ __forceinline__ uint32_t pack_bf16x2(float a, float b) {
    __nv_bfloat162 t = __floats2bfloat162_rn(a, b);
    return *(uint32_t*)&t;
}
__device__ __forceinline__ uint32_t pack_f16x2(float a, float b) {
    __half2 t = __floats2half2_rn(a, b);
    return *(uint32_t*)&t;
}

// ===========================================================================
// split helpers
// ===========================================================================
__device__ __forceinline__ void bsplit(float f, __nv_bfloat16& h, __nv_bfloat16& l) {
    h = __float2bfloat16(f);
    l = __float2bfloat16(f - __bfloat162float(h));
}
__device__ __forceinline__ void hsplit(float f, __half& h, __half& l) {
    h = __float2half(f);
    l = __float2half(f - __half2float(h));
}

struct __align__(8) H4 { __half v[4]; };

// elementwise fp16 split: x -> hi/lo
__global__ __launch_bounds__(256) void split_kernel(
    const float* __restrict__ src, __half* __restrict__ hi,
    __half* __restrict__ lo) {
    const int idx = blockIdx.x * 256 + threadIdx.x;
    float4 v = ((const float4*)src)[idx];
    H4 h, l;
    hsplit(v.x, h.v[0], l.v[0]);
    hsplit(v.y, h.v[1], l.v[1]);
    hsplit(v.z, h.v[2], l.v[2]);
    hsplit(v.w, h.v[3], l.v[3]);
    ((H4*)hi)[idx] = h;
    ((H4*)lo)[idx] = l;
}

// transpose + fp16 convert all 4 weights; blockIdx.z selects.
__global__ __launch_bounds__(256) void wsplit_all_kernel(
    const float* __restrict__ wq, const float* __restrict__ wk,
    const float* __restrict__ wv, const float* __restrict__ wo) {
    const int z = blockIdx.z;
    const float* w = (z == 0) ? wq : (z == 1) ? wk : (z == 2) ? wv : wo;
    __half* wT = (z == 0) ? g_wqT : (z == 1) ? g_wkT : (z == 2) ? g_wvT : g_woT;

    __shared__ float t[32][33];
    const int bx = blockIdx.x << 5;
    const int by = blockIdx.y << 5;
    const int tx = threadIdx.x & 31, ty = threadIdx.x >> 5;
#pragma unroll
    for (int i = 0; i < 32; i += 8)
        t[ty + i][tx] = w[(size_t)(by + ty + i) * DIMV + bx + tx];
    __syncthreads();
#pragma unroll
    for (int i = 0; i < 32; i += 8)
        wT[(size_t)(bx + ty + i) * DIMV + by + tx] = __float2half(t[tx][ty + i]);
}

// ===========================================================================
// fp16 2-pass GEMM: C = (Ah + Al) @ BhT + bias
// CTA 128x128, K-stage 32, 3-stage cp.async ring (3 x 24KB smem).
// ===========================================================================
#define STAGE_BYTES 24576
#define GEMM_SMEM_REQ (3 * STAGE_BYTES)

__device__ __forceinline__ void load_stage(
    uint32_t sbase, const __half* __restrict__ Ahi,
    const __half* __restrict__ Alo, const __half* __restrict__ B,
    int bm, int bn, int k0, int tid) {
#pragma unroll
    for (int j = 0; j < 6; j++) {
        const int chunk = tid + (j << 8);
        const int tile = chunk >> 9;          // 0..2
        const int idx = chunk & 511;
        const int r = idx >> 2, c = idx & 3;
        const uint32_t saddr = sbase + (uint32_t)(tile << 13) + sw_off(r, c);
        const __half* gp;
        if (tile == 0)      gp = Ahi + (size_t)(bm + r) * DIMV + k0 + c * 8;
        else if (tile == 1) gp = Alo + (size_t)(bm + r) * DIMV + k0 + c * 8;
        else                gp = B + (size_t)(bn + r) * DIMV + k0 + c * 8;
        cp_async16(saddr, gp);
    }
}

__device__ __forceinline__ void gemm_core(
    const __half* __restrict__ Ahi, const __half* __restrict__ Alo,
    const __half* __restrict__ B,
    const float* __restrict__ bias, float* __restrict__ C,
    __half* __restrict__ Chi, __half* __restrict__ Clo,
    uint32_t sb, int bm, int bn) {
    const int tid = threadIdx.x;
    const int wid = tid >> 5, lane = tid & 31;
    const int wm = (wid & 1) << 6;
    const int wn = (wid >> 1) << 5;
    const int lr = lane & 15;
    const int lhalf = lane >> 4;

    float acc[4][4][4];
#pragma unroll
    for (int i = 0; i < 4; i++)
#pragma unroll
        for (int j = 0; j < 4; j++)
#pragma unroll
            for (int k = 0; k < 4; k++) acc[i][j][k] = 0.f;

    load_stage(sb, Ahi, Alo, B, bm, bn, 0, tid);
    CP_COMMIT();
    load_stage(sb + STAGE_BYTES, Ahi, Alo, B, bm, bn, 32, tid);
    CP_COMMIT();

    int bufsel = 0;
    for (int s = 0; s < 32; s++) {
        if (s == 31) { CP_WAIT0(); } else { CP_WAIT1(); }
        __syncthreads();
        if (s + 2 < 32) {
            int nb = bufsel + 2;
            if (nb >= 3) nb -= 3;
            load_stage(sb + (uint32_t)nb * STAGE_BYTES, Ahi, Alo, B,
                       bm, bn, (s + 2) << 5, tid);
            CP_COMMIT();
        }

        const uint32_t buf = sb + (uint32_t)bufsel * STAGE_BYTES;
        bufsel = (bufsel == 2) ? 0 : bufsel + 1;
#pragma unroll
        for (int kk = 0; kk < 2; kk++) {
            const int cb = (kk << 1) + lhalf;
            uint32_t a[4][4], bh[2][4];
#pragma unroll
            for (int mi = 0; mi < 4; mi++)
                ldsm4(a[mi], buf + sw_off(wm + (mi << 4) + lr, cb));
#pragma unroll
            for (int np = 0; np < 2; np++)
                ldsm4(bh[np], buf + 16384 + sw_off(wn + (np << 4) + lr, cb));
            // pass 1: Ah x B
#pragma unroll
            for (int mi = 0; mi < 4; mi++) {
                mma16816h(acc[mi][0], a[mi], bh[0][0], bh[0][2]);
                mma16816h(acc[mi][1], a[mi], bh[0][1], bh[0][3]);
                mma16816h(acc[mi][2], a[mi], bh[1][0], bh[1][2]);
                mma16816h(acc[mi][3], a[mi], bh[1][1], bh[1][3]);
            }
            // pass 2: Al x B
#pragma unroll
            for (int mi = 0; mi < 4; mi++)
                ldsm4(a[mi], buf + 8192 + sw_off(wm + (mi << 4) + lr, cb));
#pragma unroll
            for (int mi = 0; mi < 4; mi++) {
                mma16816h(acc[mi][0], a[mi], bh[0][0], bh[0][2]);
                mma16816h(acc[mi][1], a[mi], bh[0][1], bh[0][3]);
                mma16816h(acc[mi][2], a[mi], bh[1][0], bh[1][2]);
                mma16816h(acc[mi][3], a[mi], bh[1][1], bh[1][3]);
            }
        }
        // no bottom sync: next iteration's wait+sync protects stage reuse
    }

    const int crow = lane >> 2;
    const int ccol = (lane & 3) << 1;
#pragma unroll
    for (int ni = 0; ni < 4; ni++) {
        const int col = bn + wn + (ni << 3) + ccol;
        const float2 bv = *(const float2*)&bias[col];
#pragma unroll
        for (int mi = 0; mi < 4; mi++) {
            const int row = bm + wm + (mi << 4) + crow;
            const float v00 = acc[mi][ni][0] + bv.x, v01 = acc[mi][ni][1] + bv.y;
            const float v10 = acc[mi][ni][2] + bv.x, v11 = acc[mi][ni][3] + bv.y;
            if (Chi) {
                const float h00 = __half2float(__float2half(v00));
                const float h01 = __half2float(__float2half(v01));
                const float h10 = __half2float(__float2half(v10));
                const float h11 = __half2float(__float2half(v11));
                *(uint32_t*)&Chi[(size_t)row * DIMV + col] = pack_f16x2(h00, h01);
                *(uint32_t*)&Clo[(size_t)row * DIMV + col] = pack_f16x2(v00 - h00, v01 - h01);
                *(uint32_t*)&Chi[(size_t)(row + 8) * DIMV + col] = pack_f16x2(h10, h11);
                *(uint32_t*)&Clo[(size_t)(row + 8) * DIMV + col] = pack_f16x2(v10 - h10, v11 - h11);
            } else {
                *(float2*)&C[(size_t)row * DIMV + col] = make_float2(v00, v01);
                *(float2*)&C[(size_t)(row + 8) * DIMV + col] = make_float2(v10, v11);
            }
        }
    }
}

// fused Q/K/V projection: grid (8, 68, 3)
__global__ __launch_bounds__(256, 2)
void gemm_qkv_kernel(const __half* __restrict__ Ahi,
                     const __half* __restrict__ Alo,
                     const float* __restrict__ bq,
                     const float* __restrict__ bk,
                     const float* __restrict__ bv) {
    extern __shared__ char smem[];
    const uint32_t sb = smem_to_u32(smem);
    const int z = blockIdx.z;
    const __half* B = (z == 0) ? g_wqT : (z == 1) ? g_wkT : g_wvT;
    const float* bias = (z == 0) ? bq : (z == 1) ? bk : bv;
    float* C = (z == 0) ? g_q : (z == 1) ? g_k : nullptr;
    __half* Chi = (z == 2) ? g_vhi : nullptr;
    __half* Clo = (z == 2) ? g_vlo : nullptr;
    gemm_core(Ahi, Alo, B, bias, C, Chi, Clo, sb,
              blockIdx.y << 7, blockIdx.x << 7);
}

// output projection
__global__ __launch_bounds__(256, 2)
void gemm_out_kernel(const __half* __restrict__ Ahi,
                     const __half* __restrict__ Alo,
                     const float* __restrict__ bias,
                     float* __restrict__ C) {
    extern __shared__ char smem[];
    const uint32_t sb = smem_to_u32(smem);
    gemm_core(Ahi, Alo, g_woT, bias, C, nullptr, nullptr, sb,
              blockIdx.y << 7, blockIdx.x << 7);
}

// ---------------------------------------------------------------------------
// Fused RMSNorm + RoPE + bf16 split, Q and K in one launch (blockIdx.y).
// ---------------------------------------------------------------------------
__global__ __launch_bounds__(256) void normrope_split_kernel(
    const float* __restrict__ srcq, const float* __restrict__ srck,
    const float* __restrict__ gq, const float* __restrict__ gk,
    const float* __restrict__ cs, const float* __restrict__ sn,
    __nv_bfloat16* __restrict__ qhi, __nv_bfloat16* __restrict__ qlo,
    __nv_bfloat16* __restrict__ khi, __nv_bfloat16* __restrict__ klo) {
    const int s = blockIdx.x;
    const int isq = (blockIdx.y == 0);
    const float* src = isq ? srcq : srck;
    const float* g = isq ? gq : gk;
    __nv_bfloat16* hi = isq ? qhi : khi;
    __nv_bfloat16* lo = isq ? qlo : klo;
    const float scale = isq ? 0.125f : 1.0f;
    const int tid = threadIdx.x;

    float4 v = *(const float4*)&src[(size_t)s * DIMV + (tid << 2)];
    float ss = v.x * v.x + v.y * v.y + v.z * v.z + v.w * v.w;
#pragma unroll
    for (int o = 16; o; o >>= 1) ss += __shfl_xor_sync(0xffffffffu, ss, o);

    __shared__ float red[8];
    __shared__ float rtot;
    if ((tid & 31) == 0) red[tid >> 5] = ss;
    __syncthreads();
    if (tid == 0) {
        float t = 0.f;
#pragma unroll
        for (int i = 0; i < 8; i++) t += red[i];
        rtot = rsqrtf(t * (1.0f / 1024.0f) + 1e-6f);
    }
    __syncthreads();
    const float r = rtot;

    float4 gv = *(const float4*)&g[tid << 2];
    const float a0 = v.x * r * gv.x, b0 = v.y * r * gv.y;
    const float a1 = v.z * r * gv.z, b1 = v.w * r * gv.w;

    const int p0 = tid << 1;
    const int r0 = p0 & 31, r1 = (p0 + 1) & 31;
    const float c0 = cs[s * 32 + r0], s0 = sn[s * 32 + r0];
    const float c1 = cs[s * 32 + r1], s1 = sn[s * 32 + r1];

    float o0 = (a0 * c0 - b0 * s0) * scale;
    float o1 = (a0 * s0 + b0 * c0) * scale;
    float o2 = (a1 * c1 - b1 * s1) * scale;
    float o3 = (a1 * s1 + b1 * c1) * scale;

    __nv_bfloat16 h0, l0_, h1, l1_, h2, l2_, h3, l3_;
    bsplit(o0, h0, l0_); bsplit(o1, h1, l1_);
    bsplit(o2, h2, l2_); bsplit(o3, h3, l3_);
    const size_t base = (size_t)s * DIMV + (tid << 2);
    *(uint32_t*)&hi[base] = pack_bf16x2(__bfloat162float(h0), __bfloat162float(h1));
    *(uint32_t*)&hi[base + 2] = pack_bf16x2(__bfloat162float(h2), __bfloat162float(h3));
    *(uint32_t*)&lo[base] = pack_bf16x2(__bfloat162float(l0_), __bfloat162float(l1_));
    *(uint32_t*)&lo[base + 2] = pack_bf16x2(__bfloat162float(l2_), __bfloat162float(l3_));
}

// ===========================================================================
// Tensor-core flash attention. QK: bf16 3-pass; PV: fp16 2-pass, P unsplit.
// ===========================================================================
#define ATT_STAGE 32768
#define ATT_SMEM  (2 * ATT_STAGE)

__global__ __launch_bounds__(128)
void attn_tc_kernel(const __nv_bfloat16* __restrict__ qhi, const __nv_bfloat16* __restrict__ qlo,
                    const __nv_bfloat16* __restrict__ khi, const __nv_bfloat16* __restrict__ klo,
                    const __half* __restrict__ vhi, const __half* __restrict__ vlo,
                    __half* __restrict__ ohi, __half* __restrict__ olo) {
    extern __shared__ char smem[];
    const uint32_t sb = smem_to_u32(smem);
    const int d = blockIdx.z, h = blockIdx.y;
    const int q0 = blockIdx.x << 6;
    const int tid = threadIdx.x;
    const int warp = tid >> 5, lane = tid & 31;
    const int wq = warp << 4;
    const int lr = lane & 15, lhf = lane >> 4;
    const int qr = lane >> 2, qc = (lane & 3) << 1;

    // prologue: borrow stage-0 smem for Q hi/lo
#pragma unroll
    for (int t = 0; t < 4; t++) {
        const int idx = tid + (t << 7);
        const int r = idx >> 3, ch = idx & 7;
        const int tok = dil2orig(d, q0 + r);
        const size_t go = (size_t)tok * DIMV + h * HD + (ch << 3);
        *(uint4*)(smem + att_off(r, ch)) = *(const uint4*)&qhi[go];
        *(uint4*)(smem + 8192 + att_off(r, ch)) = *(const uint4*)&qlo[go];
    }
    __syncthreads();

    uint32_t qh[4][4], ql[4][4];
#pragma unroll
    for (int s = 0; s < 4; s++) {
        ldsm4(qh[s], sb + att_off(wq + lr, (s << 1) + lhf));
        ldsm4(ql[s], sb + 8192 + att_off(wq + lr, (s << 1) + lhf));
    }
    __syncthreads();

    float m0 = -1e30f, m1 = -1e30f, l0 = 0.f, l1 = 0.f;
    float o[8][4];
#pragma unroll
    for (int j = 0; j < 8; j++)
#pragma unroll
        for (int k = 0; k < 4; k++) o[j][k] = 0.f;

    const int kt_lo = (q0 >= WIN) ? (q0 - WIN) : 0;
    const int kt_hi = min(SD, q0 + BQ + WIN);
    const int row0 = q0 + wq + qr, row1 = row0 + 8;

    auto stage_load = [&](int st, int kt) {
        const uint32_t stg = sb + st * ATT_STAGE;
#pragma unroll
        for (int t = 0; t < 16; t++) {
            const int cid = tid + (t << 7);
            const int buf = cid >> 9;
            const int idx = cid & 511;
            const int r = idx >> 3, ch = idx & 7;
            const int pk = kt + r;
            const int ok = pk < SREAL;
            const int tok = ok ? dil2orig(d, pk) : 0;
            const size_t go = ((size_t)tok * DIMV + h * HD + (ch << 3)) * 2;
            const char* src = (buf == 0) ? (const char*)khi : (buf == 1) ? (const char*)klo
                             : (buf == 2) ? (const char*)vhi : (const char*)vlo;
            cp_async16z(stg + (buf << 13) + att_off(r, ch), src + go, ok ? 16 : 0);
        }
    };

    stage_load(0, kt_lo);
    CP_COMMIT();

    int st = 0;
    for (int kt = kt_lo; kt < kt_hi; kt += BK, st ^= 1) {
        CP_WAIT0();
        __syncthreads();
        if (kt + BK < kt_hi) { stage_load(st ^ 1, kt + BK); CP_COMMIT(); }

        const uint32_t sK  = sb + st * ATT_STAGE;
        const uint32_t sKl = sK + 8192, sV = sK + 16384, sVl = sK + 24576;

        // --- scores: bf16 3-pass ---
        float c[8][4];
#pragma unroll
        for (int j = 0; j < 8; j++)
#pragma unroll
            for (int k = 0; k < 4; k++) c[j][k] = 0.f;

#pragma unroll
        for (int s = 0; s < 4; s++) {
#pragma unroll
            for (int g = 0; g < 4; g++) {
                uint32_t bh[4], bl[4];
                ldsm4(bh, sK + att_off((g << 4) + lr, (s << 1) + lhf));
                ldsm4(bl, sKl + att_off((g << 4) + lr, (s << 1) + lhf));
                mma16816(c[2 * g],     qh[s], bh[0], bh[2]);
                mma16816(c[2 * g + 1], qh[s], bh[1], bh[3]);
                mma16816(c[2 * g],     ql[s], bh[0], bh[2]);
                mma16816(c[2 * g + 1], ql[s], bh[1], bh[3]);
                mma16816(c[2 * g],     qh[s], bl[0], bl[2]);
                mma16816(c[2 * g + 1], qh[s], bl[1], bl[3]);
            }
        }

        const bool edge = (kt < q0 - WIN + BK) || (kt >= q0 + WIN);
        if (edge) {
#pragma unroll
            for (int j = 0; j < 8; j++) {
                const int pk = kt + (j << 3) + qc;
                if (abs(row0 - pk) > WIN)       c[j][0] = -1e9f;
                if (abs(row0 - pk - 1) > WIN)   c[j][1] = -1e9f;
                if (abs(row1 - pk) > WIN)       c[j][2] = -1e9f;
                if (abs(row1 - pk - 1) > WIN)   c[j][3] = -1e9f;
            }
        }

        // --- online softmax ---
        float tm0 = -1e30f, tm1 = -1e30f;
#pragma unroll
        for (int j = 0; j < 8; j++) {
            tm0 = fmaxf(tm0, fmaxf(c[j][0], c[j][1]));
            tm1 = fmaxf(tm1, fmaxf(c[j][2], c[j][3]));
        }
        tm0 = fmaxf(tm0, __shfl_xor_sync(0xffffffffu, tm0, 1));
        tm0 = fmaxf(tm0, __shfl_xor_sync(0xffffffffu, tm0, 2));
        tm1 = fmaxf(tm1, __shfl_xor_sync(0xffffffffu, tm1, 1));
        tm1 = fmaxf(tm1, __shfl_xor_sync(0xffffffffu, tm1, 2));

        const float mn0 = fmaxf(m0, tm0), mn1 = fmaxf(m1, tm1);
        const float cor0 = __expf(m0 - mn0), cor1 = __expf(m1 - mn1);
        m0 = mn0; m1 = mn1;

        float s0 = 0.f, s1 = 0.f;
#pragma unroll
        for (int j = 0; j < 8; j++) {
            c[j][0] = __expf(c[j][0] - mn0);
            c[j][1] = __expf(c[j][1] - mn0);
            c[j][2] = __expf(c[j][2] - mn1);
            c[j][3] = __expf(c[j][3] - mn1);
            s0 += c[j][0] + c[j][1];
            s1 += c[j][2] + c[j][3];
        }
        s0 += __shfl_xor_sync(0xffffffffu, s0, 1);
        s0 += __shfl_xor_sync(0xffffffffu, s0, 2);
        s1 += __shfl_xor_sync(0xffffffffu, s1, 1);
        s1 += __shfl_xor_sync(0xffffffffu, s1, 2);
        l0 = l0 * cor0 + s0;
        l1 = l1 * cor1 + s1;
#pragma unroll
        for (int j = 0; j < 8; j++) {
            o[j][0] *= cor0; o[j][1] *= cor0;
            o[j][2] *= cor1; o[j][3] *= cor1;
        }

        // --- PV: fp16 2-pass, P packed directly (no hi/lo split) ---
#pragma unroll
        for (int s = 0; s < 4; s++) {
            uint32_t ap[4];
            ap[0] = pack_f16x2(c[2 * s][0],     c[2 * s][1]);
            ap[1] = pack_f16x2(c[2 * s][2],     c[2 * s][3]);
            ap[2] = pack_f16x2(c[2 * s + 1][0], c[2 * s + 1][1]);
            ap[3] = pack_f16x2(c[2 * s + 1][2], c[2 * s + 1][3]);
#pragma unroll
            for (int g = 0; g < 4; g++) {
                uint32_t bh[4], bl[4];
                ldsm4t(bh, sV + att_off((s << 4) + lr, (g << 1) + lhf));
                ldsm4t(bl, sVl + att_off((s << 4) + lr, (g << 1) + lhf));
                mma16816h(o[2 * g],     ap, bh[0], bh[1]);
                mma16816h(o[2 * g + 1], ap, bh[2], bh[3]);
                mma16816h(o[2 * g],     ap, bl[0], bl[1]);
                mma16816h(o[2 * g + 1], ap, bl[2], bl[3]);
            }
        }
    }

    // epilogue: normalize, fp16 split, store (feeds fp16 out-GEMM)
    const float inv0 = 1.0f / l0, inv1 = 1.0f / l1;
    const int tok0 = dil2orig(d, row0);
    const int tok1 = dil2orig(d, row1);
#pragma unroll
    for (int j = 0; j < 8; j++) {
        const int col = h * HD + (j << 3) + qc;
        const float a0 = o[j][0] * inv0, a1 = o[j][1] * inv0;
        const float b0 = o[j][2] * inv1, b1 = o[j][3] * inv1;
        const float a0h = __half2float(__float2half(a0));
        const float a1h = __half2float(__float2half(a1));
        const float b0h = __half2float(__float2half(b0));
        const float b1h = __half2float(__float2half(b1));
        *(uint32_t*)&ohi[(size_t)tok0 * DIMV + col] = pack_f16x2(a0h, a1h);
        *(uint32_t*)&olo[(size_t)tok0 * DIMV + col] = pack_f16x2(a0 - a0h, a1 - a1h);
        *(uint32_t*)&ohi[(size_t)tok1 * DIMV + col] = pack_f16x2(b0h, b1h);
        *(uint32_t*)&olo[(size_t)tok1 * DIMV + col] = pack_f16x2(b0 - b0h, b1 - b1h);
    }
}

// ---------------------------------------------------------------------------
extern "C" void kernel_launch(void* const* d_in, const int* in_sizes, int n_in,
                              void* d_out, int out_size) {
    (void)in_sizes; (void)n_in; (void)out_size;
    const float* x  = (const float*)d_in[0];
    const float* fc = (const float*)d_in[1];
    const float* fs = (const float*)d_in[2];
    const float* wq = (const float*)d_in[3];
    const float* bq = (const float*)d_in[4];
    const float* wk = (const float*)d_in[5];
    const float* bk = (const float*)d_in[6];
    const float* wv = (const float*)d_in[7];
    const float* bv = (const float*)d_in[8];
    const float* wo = (const float*)d_in[9];
    const float* bo = (const float*)d_in[10];
    const float* gq = (const float*)d_in[11];
    const float* gk = (const float*)d_in[12];
    float* out = (float*)d_out;

    float *qb, *kb;
    cudaGetSymbolAddress((void**)&qb, g_q);
    cudaGetSymbolAddress((void**)&kb, g_k);
    __half *ahi, *alo, *vhi, *vlo;
    cudaGetSymbolAddress((void**)&ahi, g_ahi);
    cudaGetSymbolAddress((void**)&alo, g_alo);
    cudaGetSymbolAddress((void**)&vhi, g_vhi);
    cudaGetSymbolAddress((void**)&vlo, g_vlo);
    __nv_bfloat16 *qhi, *qlo, *khi, *klo;
    cudaGetSymbolAddress((void**)&qhi, g_qhi);
    cudaGetSymbolAddress((void**)&qlo, g_qlo);
    cudaGetSymbolAddress((void**)&khi, g_khi);
    cudaGetSymbolAddress((void**)&klo, g_klo);

    cudaFuncSetAttribute(gemm_qkv_kernel,
                         cudaFuncAttributeMaxDynamicSharedMemorySize, GEMM_SMEM_REQ);
    cudaFuncSetAttribute(gemm_out_kernel,
                         cudaFuncAttributeMaxDynamicSharedMemorySize, GEMM_SMEM_REQ);
    cudaFuncSetAttribute(attn_tc_kernel,
                         cudaFuncAttributeMaxDynamicSharedMemorySize, ATT_SMEM);

    wsplit_all_kernel<<<dim3(32, 32, 4), 256>>>(wq, wk, wv, wo);
    split_kernel<<<(S_LEN * DIMV) / 1024, 256>>>(x, ahi, alo);
    gemm_qkv_kernel<<<dim3(DIMV / 128, S_LEN / 128, 3), 256, GEMM_SMEM_REQ>>>(
        ahi, alo, bq, bk, bv);
    normrope_split_kernel<<<dim3(S_LEN, 2), 256>>>(qb, kb, gq, gk, fc, fs,
                                                   qhi, qlo, khi, klo);
    attn_tc_kernel<<<dim3(SREAL / BQ, NH, 2), 128, ATT_SMEM>>>(
        qhi, qlo, khi, klo, vhi, vlo, ahi, alo);
    gemm_out_kernel<<<dim3(DIMV / 128, S_LEN / 128), 256, GEMM_SMEM_REQ>>>(
        ahi, alo, bo, out);
}

// round 12
// speedup vs baseline: 1.6516x; 1.0820x over previous
#include <cuda_runtime.h>
#include <cuda_bf16.h>
#include <cuda_fp16.h>
#include <math.h>
#include <stdint.h>

#define S_LEN 8704
#define DIMV  1024
#define NH    16
#define HD    64
#define SD    4608
#define SREAL 4352
#define WIN   512
#define BQ    64
#define BK    64

// fp32 activation buffers
__device__ float g_q[S_LEN * DIMV];
__device__ float g_k[S_LEN * DIMV];

// fp16 split activations (GEMM A operands: x, attention output)
__device__ __half g_ahi[S_LEN * DIMV];
__device__ __half g_alo[S_LEN * DIMV];

// fp16 attention operands: Q split hi/lo, K single, V split hi/lo
__device__ __half g_qhi[S_LEN * DIMV];
__device__ __half g_qlo[S_LEN * DIMV];
__device__ __half g_kh[S_LEN * DIMV];
__device__ __half g_vhi[S_LEN * DIMV];
__device__ __half g_vlo[S_LEN * DIMV];

// fp16 transposed weights [N][K]
__device__ __half g_wqT[DIMV * DIMV];
__device__ __half g_wkT[DIMV * DIMV];
__device__ __half g_wvT[DIMV * DIMV];
__device__ __half g_woT[DIMV * DIMV];

__device__ __forceinline__ int dil2orig(int d, int p) {
    return ((p >> 8) << 9) + (d << 8) + (p & 255);
}

__device__ __forceinline__ uint32_t smem_to_u32(const void* smem_ptr) {
    uint32_t addr;
    asm("{ .reg .u64 tmp; cvta.to.shared.u64 tmp, %1; cvt.u32.u64 %0, tmp; }"
        : "=r"(addr) : "l"(smem_ptr));
    return addr;
}

// ===========================================================================
// family-generic tensor-core primitives
// ===========================================================================
__device__ __forceinline__ void ldsm4(uint32_t* r, uint32_t addr) {
    asm volatile("ldmatrix.sync.aligned.m8n8.x4.shared.b16 {%0,%1,%2,%3}, [%4];\n"
                 : "=r"(r[0]), "=r"(r[1]), "=r"(r[2]), "=r"(r[3]) : "r"(addr));
}
__device__ __forceinline__ void ldsm4t(uint32_t* r, uint32_t addr) {
    asm volatile("ldmatrix.sync.aligned.m8n8.x4.trans.shared.b16 {%0,%1,%2,%3}, [%4];\n"
                 : "=r"(r[0]), "=r"(r[1]), "=r"(r[2]), "=r"(r[3]) : "r"(addr));
}
// fp16 mma (fp32 accumulate)
__device__ __forceinline__ void mma16816h(float* c, const uint32_t* a,
                                          uint32_t b0, uint32_t b1) {
    asm volatile(
        "mma.sync.aligned.m16n8k16.row.col.f32.f16.f16.f32 "
        "{%0,%1,%2,%3}, {%4,%5,%6,%7}, {%8,%9}, {%0,%1,%2,%3};\n"
        : "+f"(c[0]), "+f"(c[1]), "+f"(c[2]), "+f"(c[3])
        : "r"(a[0]), "r"(a[1]), "r"(a[2]), "r"(a[3]), "r"(b0), "r"(b1));
}
__device__ __forceinline__ void cp_async16(uint32_t saddr, const void* gptr) {
    asm volatile("cp.async.cg.shared.global [%0], [%1], 16;\n"
                 :: "r"(saddr), "l"(gptr));
}
__device__ __forceinline__ void cp_async16z(uint32_t saddr, const void* gptr, int srcbytes) {
    asm volatile("cp.async.cg.shared.global [%0], [%1], 16, %2;\n"
                 :: "r"(saddr), "l"(gptr), "r"(srcbytes));
}
#define CP_COMMIT() asm volatile("cp.async.commit_group;\n" ::: "memory")
#define CP_WAIT0()  asm volatile("cp.async.wait_group 0;\n" ::: "memory")
#define CP_WAIT1()  asm volatile("cp.async.wait_group 1;\n" ::: "memory")

// gemm smem tile layout: 128 rows x 32 elem (4 x 16B chunks/row)
__device__ __forceinline__ uint32_t sw_off(int r, int c) {
    return (uint32_t)(((r >> 1) << 7) + ((r & 1) << 6) +
                      (((c ^ ((r >> 1) & 3)) & 3) << 4));
}
// attn smem tile layout: rows x 64 elem (8 x 16B chunks/row), xor swizzle
__device__ __forceinline__ uint32_t att_off(int r, int ch) {
    return (uint32_t)((r << 7) + (((ch ^ (r & 7)) & 7) << 4));
}

__device__ __forceinline__ uint32_t pack_f16x2(float a, float b) {
    __half2 t = __floats2half2_rn(a, b);
    return *(uint32_t*)&t;
}

// ===========================================================================
// split helpers
// ===========================================================================
__device__ __forceinline__ void hsplit(float f, __half& h, __half& l) {
    h = __float2half(f);
    l = __float2half(f - __half2float(h));
}

struct __align__(8) H4 { __half v[4]; };

// elementwise fp16 split: x -> hi/lo
__global__ __launch_bounds__(256) void split_kernel(
    const float* __restrict__ src, __half* __restrict__ hi,
    __half* __restrict__ lo) {
    const int idx = blockIdx.x * 256 + threadIdx.x;
    float4 v = ((const float4*)src)[idx];
    H4 h, l;
    hsplit(v.x, h.v[0], l.v[0]);
    hsplit(v.y, h.v[1], l.v[1]);
    hsplit(v.z, h.v[2], l.v[2]);
    hsplit(v.w, h.v[3], l.v[3]);
    ((H4*)hi)[idx] = h;
    ((H4*)lo)[idx] = l;
}

// transpose + fp16 convert all 4 weights; blockIdx.z selects.
__global__ __launch_bounds__(256) void wsplit_all_kernel(
    const float* __restrict__ wq, const float* __restrict__ wk,
    const float* __restrict__ wv, const float* __restrict__ wo) {
    const int z = blockIdx.z;
    const float* w = (z == 0) ? wq : (z == 1) ? wk : (z == 2) ? wv : wo;
    __half* wT = (z == 0) ? g_wqT : (z == 1) ? g_wkT : (z == 2) ? g_wvT : g_woT;

    __shared__ float t[32][33];
    const int bx = blockIdx.x << 5;
    const int by = blockIdx.y << 5;
    const int tx = threadIdx.x & 31, ty = threadIdx.x >> 5;
#pragma unroll
    for (int i = 0; i < 32; i += 8)
        t[ty + i][tx] = w[(size_t)(by + ty + i) * DIMV + bx + tx];
    __syncthreads();
#pragma unroll
    for (int i = 0; i < 32; i += 8)
        wT[(size_t)(bx + ty + i) * DIMV + by + tx] = __float2half(t[tx][ty + i]);
}

// ===========================================================================
// fp16 2-pass GEMM: C = (Ah + Al) @ BhT + bias
// CTA 128x128, K-stage 32, 3-stage cp.async ring (3 x 24KB smem).
// ===========================================================================
#define STAGE_BYTES 24576
#define GEMM_SMEM_REQ (3 * STAGE_BYTES)

__device__ __forceinline__ void load_stage(
    uint32_t sbase, const __half* __restrict__ Ahi,
    const __half* __restrict__ Alo, const __half* __restrict__ B,
    int bm, int bn, int k0, int tid) {
#pragma unroll
    for (int j = 0; j < 6; j++) {
        const int chunk = tid + (j << 8);
        const int tile = chunk >> 9;          // 0..2
        const int idx = chunk & 511;
        const int r = idx >> 2, c = idx & 3;
        const uint32_t saddr = sbase + (uint32_t)(tile << 13) + sw_off(r, c);
        const __half* gp;
        if (tile == 0)      gp = Ahi + (size_t)(bm + r) * DIMV + k0 + c * 8;
        else if (tile == 1) gp = Alo + (size_t)(bm + r) * DIMV + k0 + c * 8;
        else                gp = B + (size_t)(bn + r) * DIMV + k0 + c * 8;
        cp_async16(saddr, gp);
    }
}

__device__ __forceinline__ void gemm_core(
    const __half* __restrict__ Ahi, const __half* __restrict__ Alo,
    const __half* __restrict__ B,
    const float* __restrict__ bias, float* __restrict__ C,
    __half* __restrict__ Chi, __half* __restrict__ Clo,
    uint32_t sb, int bm, int bn) {
    const int tid = threadIdx.x;
    const int wid = tid >> 5, lane = tid & 31;
    const int wm = (wid & 1) << 6;
    const int wn = (wid >> 1) << 5;
    const int lr = lane & 15;
    const int lhalf = lane >> 4;

    float acc[4][4][4];
#pragma unroll
    for (int i = 0; i < 4; i++)
#pragma unroll
        for (int j = 0; j < 4; j++)
#pragma unroll
            for (int k = 0; k < 4; k++) acc[i][j][k] = 0.f;

    load_stage(sb, Ahi, Alo, B, bm, bn, 0, tid);
    CP_COMMIT();
    load_stage(sb + STAGE_BYTES, Ahi, Alo, B, bm, bn, 32, tid);
    CP_COMMIT();

    int bufsel = 0;
    for (int s = 0; s < 32; s++) {
        if (s == 31) { CP_WAIT0(); } else { CP_WAIT1(); }
        __syncthreads();
        if (s + 2 < 32) {
            int nb = bufsel + 2;
            if (nb >= 3) nb -= 3;
            load_stage(sb + (uint32_t)nb * STAGE_BYTES, Ahi, Alo, B,
                       bm, bn, (s + 2) << 5, tid);
            CP_COMMIT();
        }

        const uint32_t buf = sb + (uint32_t)bufsel * STAGE_BYTES;
        bufsel = (bufsel == 2) ? 0 : bufsel + 1;
#pragma unroll
        for (int kk = 0; kk < 2; kk++) {
            const int cb = (kk << 1) + lhalf;
            uint32_t a[4][4], bh[2][4];
#pragma unroll
            for (int mi = 0; mi < 4; mi++)
                ldsm4(a[mi], buf + sw_off(wm + (mi << 4) + lr, cb));
#pragma unroll
            for (int np = 0; np < 2; np++)
                ldsm4(bh[np], buf + 16384 + sw_off(wn + (np << 4) + lr, cb));
            // pass 1: Ah x B
#pragma unroll
            for (int mi = 0; mi < 4; mi++) {
                mma16816h(acc[mi][0], a[mi], bh[0][0], bh[0][2]);
                mma16816h(acc[mi][1], a[mi], bh[0][1], bh[0][3]);
                mma16816h(acc[mi][2], a[mi], bh[1][0], bh[1][2]);
                mma16816h(acc[mi][3], a[mi], bh[1][1], bh[1][3]);
            }
            // pass 2: Al x B
#pragma unroll
            for (int mi = 0; mi < 4; mi++)
                ldsm4(a[mi], buf + 8192 + sw_off(wm + (mi << 4) + lr, cb));
#pragma unroll
            for (int mi = 0; mi < 4; mi++) {
                mma16816h(acc[mi][0], a[mi], bh[0][0], bh[0][2]);
                mma16816h(acc[mi][1], a[mi], bh[0][1], bh[0][3]);
                mma16816h(acc[mi][2], a[mi], bh[1][0], bh[1][2]);
                mma16816h(acc[mi][3], a[mi], bh[1][1], bh[1][3]);
            }
        }
        // no bottom sync: next iteration's wait+sync protects stage reuse
    }

    const int crow = lane >> 2;
    const int ccol = (lane & 3) << 1;
#pragma unroll
    for (int ni = 0; ni < 4; ni++) {
        const int col = bn + wn + (ni << 3) + ccol;
        const float2 bv = *(const float2*)&bias[col];
#pragma unroll
        for (int mi = 0; mi < 4; mi++) {
            const int row = bm + wm + (mi << 4) + crow;
            const float v00 = acc[mi][ni][0] + bv.x, v01 = acc[mi][ni][1] + bv.y;
            const float v10 = acc[mi][ni][2] + bv.x, v11 = acc[mi][ni][3] + bv.y;
            if (Chi) {
                const float h00 = __half2float(__float2half(v00));
                const float h01 = __half2float(__float2half(v01));
                const float h10 = __half2float(__float2half(v10));
                const float h11 = __half2float(__float2half(v11));
                *(uint32_t*)&Chi[(size_t)row * DIMV + col] = pack_f16x2(h00, h01);
                *(uint32_t*)&Clo[(size_t)row * DIMV + col] = pack_f16x2(v00 - h00, v01 - h01);
                *(uint32_t*)&Chi[(size_t)(row + 8) * DIMV + col] = pack_f16x2(h10, h11);
                *(uint32_t*)&Clo[(size_t)(row + 8) * DIMV + col] = pack_f16x2(v10 - h10, v11 - h11);
            } else {
                *(float2*)&C[(size_t)row * DIMV + col] = make_float2(v00, v01);
                *(float2*)&C[(size_t)(row + 8) * DIMV + col] = make_float2(v10, v11);
            }
        }
    }
}

// fused Q/K/V projection: grid (8, 68, 3)
__global__ __launch_bounds__(256, 2)
void gemm_qkv_kernel(const __half* __restrict__ Ahi,
                     const __half* __restrict__ Alo,
                     const float* __restrict__ bq,
                     const float* __restrict__ bk,
                     const float* __restrict__ bv) {
    extern __shared__ char smem[];
    const uint32_t sb = smem_to_u32(smem);
    const int z = blockIdx.z;
    const __half* B = (z == 0) ? g_wqT : (z == 1) ? g_wkT : g_wvT;
    const float* bias = (z == 0) ? bq : (z == 1) ? bk : bv;
    float* C = (z == 0) ? g_q : (z == 1) ? g_k : nullptr;
    __half* Chi = (z == 2) ? g_vhi : nullptr;
    __half* Clo = (z == 2) ? g_vlo : nullptr;
    gemm_core(Ahi, Alo, B, bias, C, Chi, Clo, sb,
              blockIdx.y << 7, blockIdx.x << 7);
}

// output projection
__global__ __launch_bounds__(256, 2)
void gemm_out_kernel(const __half* __restrict__ Ahi,
                     const __half* __restrict__ Alo,
                     const float* __restrict__ bias,
                     float* __restrict__ C) {
    extern __shared__ char smem[];
    const uint32_t sb = smem_to_u32(smem);
    gemm_core(Ahi, Alo, g_woT, bias, C, nullptr, nullptr, sb,
              blockIdx.y << 7, blockIdx.x << 7);
}

// ---------------------------------------------------------------------------
// Fused RMSNorm + RoPE + fp16 emit. blockIdx.y: 0 = Q (split hi/lo, scaled),
// 1 = K (single fp16).
// ---------------------------------------------------------------------------
__global__ __launch_bounds__(256) void normrope_split_kernel(
    const float* __restrict__ srcq, const float* __restrict__ srck,
    const float* __restrict__ gq, const float* __restrict__ gk,
    const float* __restrict__ cs, const float* __restrict__ sn,
    __half* __restrict__ qhi, __half* __restrict__ qlo,
    __half* __restrict__ kh) {
    const int s = blockIdx.x;
    const int isq = (blockIdx.y == 0);
    const float* src = isq ? srcq : srck;
    const float* g = isq ? gq : gk;
    const float scale = isq ? 0.125f : 1.0f;
    const int tid = threadIdx.x;

    float4 v = *(const float4*)&src[(size_t)s * DIMV + (tid << 2)];
    float ss = v.x * v.x + v.y * v.y + v.z * v.z + v.w * v.w;
#pragma unroll
    for (int o = 16; o; o >>= 1) ss += __shfl_xor_sync(0xffffffffu, ss, o);

    __shared__ float red[8];
    __shared__ float rtot;
    if ((tid & 31) == 0) red[tid >> 5] = ss;
    __syncthreads();
    if (tid == 0) {
        float t = 0.f;
#pragma unroll
        for (int i = 0; i < 8; i++) t += red[i];
        rtot = rsqrtf(t * (1.0f / 1024.0f) + 1e-6f);
    }
    __syncthreads();
    const float r = rtot;

    float4 gv = *(const float4*)&g[tid << 2];
    const float a0 = v.x * r * gv.x, b0 = v.y * r * gv.y;
    const float a1 = v.z * r * gv.z, b1 = v.w * r * gv.w;

    const int p0 = tid << 1;
    const int r0 = p0 & 31, r1 = (p0 + 1) & 31;
    const float c0 = cs[s * 32 + r0], s0 = sn[s * 32 + r0];
    const float c1 = cs[s * 32 + r1], s1 = sn[s * 32 + r1];

    float o0 = (a0 * c0 - b0 * s0) * scale;
    float o1 = (a0 * s0 + b0 * c0) * scale;
    float o2 = (a1 * c1 - b1 * s1) * scale;
    float o3 = (a1 * s1 + b1 * c1) * scale;

    const size_t base = (size_t)s * DIMV + (tid << 2);
    if (isq) {
        __half h0, l0, h1, l1, h2, l2, h3, l3;
        hsplit(o0, h0, l0); hsplit(o1, h1, l1);
        hsplit(o2, h2, l2); hsplit(o3, h3, l3);
        *(uint32_t*)&qhi[base] = pack_f16x2(__half2float(h0), __half2float(h1));
        *(uint32_t*)&qhi[base + 2] = pack_f16x2(__half2float(h2), __half2float(h3));
        *(uint32_t*)&qlo[base] = pack_f16x2(__half2float(l0), __half2float(l1));
        *(uint32_t*)&qlo[base + 2] = pack_f16x2(__half2float(l2), __half2float(l3));
    } else {
        *(uint32_t*)&kh[base] = pack_f16x2(o0, o1);
        *(uint32_t*)&kh[base + 2] = pack_f16x2(o2, o3);
    }
}

// ===========================================================================
// Tensor-core flash attention. QK: fp16 2-pass (Qh+Ql)·K; PV: fp16 2-pass
// P·(Vh+Vl). Stage = K 8KB + Vh 8KB + Vl 8KB = 24KB; 2 stages = 48KB.
// ===========================================================================
#define ATT_STAGE 24576
#define ATT_SMEM  (2 * ATT_STAGE)

__global__ __launch_bounds__(128)
void attn_tc_kernel(const __half* __restrict__ qhi, const __half* __restrict__ qlo,
                    const __half* __restrict__ kh,
                    const __half* __restrict__ vhi, const __half* __restrict__ vlo,
                    __half* __restrict__ ohi, __half* __restrict__ olo) {
    extern __shared__ char smem[];
    const uint32_t sb = smem_to_u32(smem);
    const int d = blockIdx.z, h = blockIdx.y;
    const int q0 = blockIdx.x << 6;
    const int tid = threadIdx.x;
    const int warp = tid >> 5, lane = tid & 31;
    const int wq = warp << 4;
    const int lr = lane & 15, lhf = lane >> 4;
    const int qr = lane >> 2, qc = (lane & 3) << 1;

    // prologue: borrow stage smem for Q hi/lo
#pragma unroll
    for (int t = 0; t < 4; t++) {
        const int idx = tid + (t << 7);
        const int r = idx >> 3, ch = idx & 7;
        const int tok = dil2orig(d, q0 + r);
        const size_t go = (size_t)tok * DIMV + h * HD + (ch << 3);
        *(uint4*)(smem + att_off(r, ch)) = *(const uint4*)&qhi[go];
        *(uint4*)(smem + 8192 + att_off(r, ch)) = *(const uint4*)&qlo[go];
    }
    __syncthreads();

    uint32_t qh[4][4], ql[4][4];
#pragma unroll
    for (int s = 0; s < 4; s++) {
        ldsm4(qh[s], sb + att_off(wq + lr, (s << 1) + lhf));
        ldsm4(ql[s], sb + 8192 + att_off(wq + lr, (s << 1) + lhf));
    }
    __syncthreads();

    float m0 = -1e30f, m1 = -1e30f, l0 = 0.f, l1 = 0.f;
    float o[8][4];
#pragma unroll
    for (int j = 0; j < 8; j++)
#pragma unroll
        for (int k = 0; k < 4; k++) o[j][k] = 0.f;

    const int kt_lo = (q0 >= WIN) ? (q0 - WIN) : 0;
    const int kt_hi = min(SD, q0 + BQ + WIN);
    const int row0 = q0 + wq + qr, row1 = row0 + 8;

    auto stage_load = [&](int st, int kt) {
        const uint32_t stg = sb + st * ATT_STAGE;
#pragma unroll
        for (int t = 0; t < 12; t++) {
            const int cid = tid + (t << 7);
            const int buf = cid >> 9;          // 0..2
            const int idx = cid & 511;
            const int r = idx >> 3, ch = idx & 7;
            const int pk = kt + r;
            const int ok = pk < SREAL;
            const int tok = ok ? dil2orig(d, pk) : 0;
            const size_t go = ((size_t)tok * DIMV + h * HD + (ch << 3)) * 2;
            const char* src = (buf == 0) ? (const char*)kh
                             : (buf == 1) ? (const char*)vhi : (const char*)vlo;
            cp_async16z(stg + (buf << 13) + att_off(r, ch), src + go, ok ? 16 : 0);
        }
    };

    stage_load(0, kt_lo);
    CP_COMMIT();

    int st = 0;
    for (int kt = kt_lo; kt < kt_hi; kt += BK, st ^= 1) {
        CP_WAIT0();
        __syncthreads();
        if (kt + BK < kt_hi) { stage_load(st ^ 1, kt + BK); CP_COMMIT(); }

        const uint32_t sK = sb + st * ATT_STAGE;
        const uint32_t sV = sK + 8192, sVl = sK + 16384;

        // --- scores: fp16 2-pass ---
        float c[8][4];
#pragma unroll
        for (int j = 0; j < 8; j++)
#pragma unroll
            for (int k = 0; k < 4; k++) c[j][k] = 0.f;

#pragma unroll
        for (int s = 0; s < 4; s++) {
#pragma unroll
            for (int g = 0; g < 4; g++) {
                uint32_t bh[4];
                ldsm4(bh, sK + att_off((g << 4) + lr, (s << 1) + lhf));
                mma16816h(c[2 * g],     qh[s], bh[0], bh[2]);
                mma16816h(c[2 * g + 1], qh[s], bh[1], bh[3]);
                mma16816h(c[2 * g],     ql[s], bh[0], bh[2]);
                mma16816h(c[2 * g + 1], ql[s], bh[1], bh[3]);
            }
        }

        const bool edge = (kt < q0 - WIN + BK) || (kt >= q0 + WIN);
        if (edge) {
#pragma unroll
            for (int j = 0; j < 8; j++) {
                const int pk = kt + (j << 3) + qc;
                if (abs(row0 - pk) > WIN)       c[j][0] = -1e9f;
                if (abs(row0 - pk - 1) > WIN)   c[j][1] = -1e9f;
                if (abs(row1 - pk) > WIN)       c[j][2] = -1e9f;
                if (abs(row1 - pk - 1) > WIN)   c[j][3] = -1e9f;
            }
        }

        // --- online softmax ---
        float tm0 = -1e30f, tm1 = -1e30f;
#pragma unroll
        for (int j = 0; j < 8; j++) {
            tm0 = fmaxf(tm0, fmaxf(c[j][0], c[j][1]));
            tm1 = fmaxf(tm1, fmaxf(c[j][2], c[j][3]));
        }
        tm0 = fmaxf(tm0, __shfl_xor_sync(0xffffffffu, tm0, 1));
        tm0 = fmaxf(tm0, __shfl_xor_sync(0xffffffffu, tm0, 2));
        tm1 = fmaxf(tm1, __shfl_xor_sync(0xffffffffu, tm1, 1));
        tm1 = fmaxf(tm1, __shfl_xor_sync(0xffffffffu, tm1, 2));

        const float mn0 = fmaxf(m0, tm0), mn1 = fmaxf(m1, tm1);
        const float cor0 = __expf(m0 - mn0), cor1 = __expf(m1 - mn1);
        m0 = mn0; m1 = mn1;

        float s0 = 0.f, s1 = 0.f;
#pragma unroll
        for (int j = 0; j < 8; j++) {
            c[j][0] = __expf(c[j][0] - mn0);
            c[j][1] = __expf(c[j][1] - mn0);
            c[j][2] = __expf(c[j][2] - mn1);
            c[j][3] = __expf(c[j][3] - mn1);
            s0 += c[j][0] + c[j][1];
            s1 += c[j][2] + c[j][3];
        }
        s0 += __shfl_xor_sync(0xffffffffu, s0, 1);
        s0 += __shfl_xor_sync(0xffffffffu, s0, 2);
        s1 += __shfl_xor_sync(0xffffffffu, s1, 1);
        s1 += __shfl_xor_sync(0xffffffffu, s1, 2);
        l0 = l0 * cor0 + s0;
        l1 = l1 * cor1 + s1;
#pragma unroll
        for (int j = 0; j < 8; j++) {
            o[j][0] *= cor0; o[j][1] *= cor0;
            o[j][2] *= cor1; o[j][3] *= cor1;
        }

        // --- PV: fp16 2-pass, P packed directly ---
#pragma unroll
        for (int s = 0; s < 4; s++) {
            uint32_t ap[4];
            ap[0] = pack_f16x2(c[2 * s][0],     c[2 * s][1]);
            ap[1] = pack_f16x2(c[2 * s][2],     c[2 * s][3]);
            ap[2] = pack_f16x2(c[2 * s + 1][0], c[2 * s + 1][1]);
            ap[3] = pack_f16x2(c[2 * s + 1][2], c[2 * s + 1][3]);
#pragma unroll
            for (int g = 0; g < 4; g++) {
                uint32_t bh[4], bl[4];
                ldsm4t(bh, sV + att_off((s << 4) + lr, (g << 1) + lhf));
                ldsm4t(bl, sVl + att_off((s << 4) + lr, (g << 1) + lhf));
                mma16816h(o[2 * g],     ap, bh[0], bh[1]);
                mma16816h(o[2 * g + 1], ap, bh[2], bh[3]);
                mma16816h(o[2 * g],     ap, bl[0], bl[1]);
                mma16816h(o[2 * g + 1], ap, bl[2], bl[3]);
            }
        }
    }

    // epilogue: normalize, fp16 split, store (feeds fp16 out-GEMM)
    const float inv0 = 1.0f / l0, inv1 = 1.0f / l1;
    const int tok0 = dil2orig(d, row0);
    const int tok1 = dil2orig(d, row1);
#pragma unroll
    for (int j = 0; j < 8; j++) {
        const int col = h * HD + (j << 3) + qc;
        const float a0 = o[j][0] * inv0, a1 = o[j][1] * inv0;
        const float b0 = o[j][2] * inv1, b1 = o[j][3] * inv1;
        const float a0h = __half2float(__float2half(a0));
        const float a1h = __half2float(__float2half(a1));
        const float b0h = __half2float(__float2half(b0));
        const float b1h = __half2float(__float2half(b1));
        *(uint32_t*)&ohi[(size_t)tok0 * DIMV + col] = pack_f16x2(a0h, a1h);
        *(uint32_t*)&olo[(size_t)tok0 * DIMV + col] = pack_f16x2(a0 - a0h, a1 - a1h);
        *(uint32_t*)&ohi[(size_t)tok1 * DIMV + col] = pack_f16x2(b0h, b1h);
        *(uint32_t*)&olo[(size_t)tok1 * DIMV + col] = pack_f16x2(b0 - b0h, b1 - b1h);
    }
}

// ---------------------------------------------------------------------------
extern "C" void kernel_launch(void* const* d_in, const int* in_sizes, int n_in,
                              void* d_out, int out_size) {
    (void)in_sizes; (void)n_in; (void)out_size;
    const float* x  = (const float*)d_in[0];
    const float* fc = (const float*)d_in[1];
    const float* fs = (const float*)d_in[2];
    const float* wq = (const float*)d_in[3];
    const float* bq = (const float*)d_in[4];
    const float* wk = (const float*)d_in[5];
    const float* bk = (const float*)d_in[6];
    const float* wv = (const float*)d_in[7];
    const float* bv = (const float*)d_in[8];
    const float* wo = (const float*)d_in[9];
    const float* bo = (const float*)d_in[10];
    const float* gq = (const float*)d_in[11];
    const float* gk = (const float*)d_in[12];
    float* out = (float*)d_out;

    float *qb, *kb;
    cudaGetSymbolAddress((void**)&qb, g_q);
    cudaGetSymbolAddress((void**)&kb, g_k);
    __half *ahi, *alo, *vhi, *vlo, *qhi, *qlo, *kh;
    cudaGetSymbolAddress((void**)&ahi, g_ahi);
    cudaGetSymbolAddress((void**)&alo, g_alo);
    cudaGetSymbolAddress((void**)&vhi, g_vhi);
    cudaGetSymbolAddress((void**)&vlo, g_vlo);
    cudaGetSymbolAddress((void**)&qhi, g_qhi);
    cudaGetSymbolAddress((void**)&qlo, g_qlo);
    cudaGetSymbolAddress((void**)&kh, g_kh);

    cudaFuncSetAttribute(gemm_qkv_kernel,
                         cudaFuncAttributeMaxDynamicSharedMemorySize, GEMM_SMEM_REQ);
    cudaFuncSetAttribute(gemm_out_kernel,
                         cudaFuncAttributeMaxDynamicSharedMemorySize, GEMM_SMEM_REQ);
    cudaFuncSetAttribute(attn_tc_kernel,
                         cudaFuncAttributeMaxDynamicSharedMemorySize, ATT_SMEM);

    wsplit_all_kernel<<<dim3(32, 32, 4), 256>>>(wq, wk, wv, wo);
    split_kernel<<<(S_LEN * DIMV) / 1024, 256>>>(x, ahi, alo);
    gemm_qkv_kernel<<<dim3(DIMV / 128, S_LEN / 128, 3), 256, GEMM_SMEM_REQ>>>(
        ahi, alo, bq, bk, bv);
    normrope_split_kernel<<<dim3(S_LEN, 2), 256>>>(qb, kb, gq, gk, fc, fs,
                                                   qhi, qlo, kh);
    attn_tc_kernel<<<dim3(SREAL / BQ, NH, 2), 128, ATT_SMEM>>>(
        qhi, qlo, kh, vhi, vlo, ahi, alo);
    gemm_out_kernel<<<dim3(DIMV / 128, S_LEN / 128), 256, GEMM_SMEM_REQ>>>(
        ahi, alo, bo, out);
}

// round 13
// speedup vs baseline: 1.7798x; 1.0776x over previous
#include <cuda_runtime.h>
#include <cuda_bf16.h>
#include <cuda_fp16.h>
#include <math.h>
#include <stdint.h>

#define S_LEN 8704
#define DIMV  1024
#define NH    16
#define HD    64
#define SD    4608
#define SREAL 4352
#define WIN   512
#define BQ    64
#define BK    64

// fp32 activation buffers
__device__ float g_q[S_LEN * DIMV];
__device__ float g_k[S_LEN * DIMV];

// fp16 split activations (x hi/lo for QKV GEMM); g_ahi reused for attn output
__device__ __half g_ahi[S_LEN * DIMV];
__device__ __half g_alo[S_LEN * DIMV];

// fp16 attention operands: Q split hi/lo, K single, V single
__device__ __half g_qhi[S_LEN * DIMV];
__device__ __half g_qlo[S_LEN * DIMV];
__device__ __half g_kh[S_LEN * DIMV];
__device__ __half g_vh[S_LEN * DIMV];

// fp16 transposed weights [N][K]
__device__ __half g_wqT[DIMV * DIMV];
__device__ __half g_wkT[DIMV * DIMV];
__device__ __half g_wvT[DIMV * DIMV];
__device__ __half g_woT[DIMV * DIMV];

__device__ __forceinline__ int dil2orig(int d, int p) {
    return ((p >> 8) << 9) + (d << 8) + (p & 255);
}

__device__ __forceinline__ uint32_t smem_to_u32(const void* smem_ptr) {
    uint32_t addr;
    asm("{ .reg .u64 tmp; cvta.to.shared.u64 tmp, %1; cvt.u32.u64 %0, tmp; }"
        : "=r"(addr) : "l"(smem_ptr));
    return addr;
}

// ===========================================================================
// family-generic tensor-core primitives
// ===========================================================================
__device__ __forceinline__ void ldsm4(uint32_t* r, uint32_t addr) {
    asm volatile("ldmatrix.sync.aligned.m8n8.x4.shared.b16 {%0,%1,%2,%3}, [%4];\n"
                 : "=r"(r[0]), "=r"(r[1]), "=r"(r[2]), "=r"(r[3]) : "r"(addr));
}
__device__ __forceinline__ void ldsm4t(uint32_t* r, uint32_t addr) {
    asm volatile("ldmatrix.sync.aligned.m8n8.x4.trans.shared.b16 {%0,%1,%2,%3}, [%4];\n"
                 : "=r"(r[0]), "=r"(r[1]), "=r"(r[2]), "=r"(r[3]) : "r"(addr));
}
// fp16 mma (fp32 accumulate)
__device__ __forceinline__ void mma16816h(float* c, const uint32_t* a,
                                          uint32_t b0, uint32_t b1) {
    asm volatile(
        "mma.sync.aligned.m16n8k16.row.col.f32.f16.f16.f32 "
        "{%0,%1,%2,%3}, {%4,%5,%6,%7}, {%8,%9}, {%0,%1,%2,%3};\n"
        : "+f"(c[0]), "+f"(c[1]), "+f"(c[2]), "+f"(c[3])
        : "r"(a[0]), "r"(a[1]), "r"(a[2]), "r"(a[3]), "r"(b0), "r"(b1));
}
__device__ __forceinline__ void cp_async16(uint32_t saddr, const void* gptr) {
    asm volatile("cp.async.cg.shared.global [%0], [%1], 16;\n"
                 :: "r"(saddr), "l"(gptr));
}
__device__ __forceinline__ void cp_async16z(uint32_t saddr, const void* gptr, int srcbytes) {
    asm volatile("cp.async.cg.shared.global [%0], [%1], 16, %2;\n"
                 :: "r"(saddr), "l"(gptr), "r"(srcbytes));
}
#define CP_COMMIT() asm volatile("cp.async.commit_group;\n" ::: "memory")
#define CP_WAIT0()  asm volatile("cp.async.wait_group 0;\n" ::: "memory")
#define CP_WAIT1()  asm volatile("cp.async.wait_group 1;\n" ::: "memory")

// gemm smem tile layout: 128 rows x 32 elem (4 x 16B chunks/row)
__device__ __forceinline__ uint32_t sw_off(int r, int c) {
    return (uint32_t)(((r >> 1) << 7) + ((r & 1) << 6) +
                      (((c ^ ((r >> 1) & 3)) & 3) << 4));
}
// attn smem tile layout: rows x 64 elem (8 x 16B chunks/row), xor swizzle
__device__ __forceinline__ uint32_t att_off(int r, int ch) {
    return (uint32_t)((r << 7) + (((ch ^ (r & 7)) & 7) << 4));
}

__device__ __forceinline__ uint32_t pack_f16x2(float a, float b) {
    __half2 t = __floats2half2_rn(a, b);
    return *(uint32_t*)&t;
}

// ===========================================================================
// split helpers
// ===========================================================================
__device__ __forceinline__ void hsplit(float f, __half& h, __half& l) {
    h = __float2half(f);
    l = __float2half(f - __half2float(h));
}

struct __align__(8) H4 { __half v[4]; };

// elementwise fp16 split: x -> hi/lo
__global__ __launch_bounds__(256) void split_kernel(
    const float* __restrict__ src, __half* __restrict__ hi,
    __half* __restrict__ lo) {
    const int idx = blockIdx.x * 256 + threadIdx.x;
    float4 v = ((const float4*)src)[idx];
    H4 h, l;
    hsplit(v.x, h.v[0], l.v[0]);
    hsplit(v.y, h.v[1], l.v[1]);
    hsplit(v.z, h.v[2], l.v[2]);
    hsplit(v.w, h.v[3], l.v[3]);
    ((H4*)hi)[idx] = h;
    ((H4*)lo)[idx] = l;
}

// transpose + fp16 convert all 4 weights; blockIdx.z selects.
__global__ __launch_bounds__(256) void wsplit_all_kernel(
    const float* __restrict__ wq, const float* __restrict__ wk,
    const float* __restrict__ wv, const float* __restrict__ wo) {
    const int z = blockIdx.z;
    const float* w = (z == 0) ? wq : (z == 1) ? wk : (z == 2) ? wv : wo;
    __half* wT = (z == 0) ? g_wqT : (z == 1) ? g_wkT : (z == 2) ? g_wvT : g_woT;

    __shared__ float t[32][33];
    const int bx = blockIdx.x << 5;
    const int by = blockIdx.y << 5;
    const int tx = threadIdx.x & 31, ty = threadIdx.x >> 5;
#pragma unroll
    for (int i = 0; i < 32; i += 8)
        t[ty + i][tx] = w[(size_t)(by + ty + i) * DIMV + bx + tx];
    __syncthreads();
#pragma unroll
    for (int i = 0; i < 32; i += 8)
        wT[(size_t)(bx + ty + i) * DIMV + by + tx] = __float2half(t[tx][ty + i]);
}

// ===========================================================================
// fp16 GEMM: C = (Ah [+ Al]) @ BhT + bias  (Alo == nullptr -> 1-pass)
// CTA 128x128, K-stage 32, 3-stage cp.async ring (3 x 24KB smem).
// Output: fp32 C, or fp16 Chi (+ optional fp16 Clo residual).
// ===========================================================================
#define STAGE_BYTES 24576
#define GEMM_SMEM_REQ (3 * STAGE_BYTES)

__device__ __forceinline__ void load_stage(
    uint32_t sbase, const __half* __restrict__ Ahi,
    const __half* __restrict__ Alo, const __half* __restrict__ B,
    int bm, int bn, int k0, int tid) {
#pragma unroll
    for (int j = 0; j < 6; j++) {
        const int chunk = tid + (j << 8);
        const int tile = chunk >> 9;          // 0..2
        const int idx = chunk & 511;
        const int r = idx >> 2, c = idx & 3;
        const uint32_t saddr = sbase + (uint32_t)(tile << 13) + sw_off(r, c);
        const __half* gp;
        if (tile == 0)      gp = Ahi + (size_t)(bm + r) * DIMV + k0 + c * 8;
        else if (tile == 1) {
            if (!Alo) continue;
            gp = Alo + (size_t)(bm + r) * DIMV + k0 + c * 8;
        }
        else                gp = B + (size_t)(bn + r) * DIMV + k0 + c * 8;
        cp_async16(saddr, gp);
    }
}

__device__ __forceinline__ void gemm_core(
    const __half* __restrict__ Ahi, const __half* __restrict__ Alo,
    const __half* __restrict__ B,
    const float* __restrict__ bias, float* __restrict__ C,
    __half* __restrict__ Chi, __half* __restrict__ Clo,
    uint32_t sb, int bm, int bn) {
    const int tid = threadIdx.x;
    const int wid = tid >> 5, lane = tid & 31;
    const int wm = (wid & 1) << 6;
    const int wn = (wid >> 1) << 5;
    const int lr = lane & 15;
    const int lhalf = lane >> 4;

    float acc[4][4][4];
#pragma unroll
    for (int i = 0; i < 4; i++)
#pragma unroll
        for (int j = 0; j < 4; j++)
#pragma unroll
            for (int k = 0; k < 4; k++) acc[i][j][k] = 0.f;

    load_stage(sb, Ahi, Alo, B, bm, bn, 0, tid);
    CP_COMMIT();
    load_stage(sb + STAGE_BYTES, Ahi, Alo, B, bm, bn, 32, tid);
    CP_COMMIT();

    int bufsel = 0;
    for (int s = 0; s < 32; s++) {
        if (s == 31) { CP_WAIT0(); } else { CP_WAIT1(); }
        __syncthreads();
        if (s + 2 < 32) {
            int nb = bufsel + 2;
            if (nb >= 3) nb -= 3;
            load_stage(sb + (uint32_t)nb * STAGE_BYTES, Ahi, Alo, B,
                       bm, bn, (s + 2) << 5, tid);
            CP_COMMIT();
        }

        const uint32_t buf = sb + (uint32_t)bufsel * STAGE_BYTES;
        bufsel = (bufsel == 2) ? 0 : bufsel + 1;
#pragma unroll
        for (int kk = 0; kk < 2; kk++) {
            const int cb = (kk << 1) + lhalf;
            uint32_t a[4][4], bh[2][4];
#pragma unroll
            for (int mi = 0; mi < 4; mi++)
                ldsm4(a[mi], buf + sw_off(wm + (mi << 4) + lr, cb));
#pragma unroll
            for (int np = 0; np < 2; np++)
                ldsm4(bh[np], buf + 16384 + sw_off(wn + (np << 4) + lr, cb));
            // pass 1: Ah x B
#pragma unroll
            for (int mi = 0; mi < 4; mi++) {
                mma16816h(acc[mi][0], a[mi], bh[0][0], bh[0][2]);
                mma16816h(acc[mi][1], a[mi], bh[0][1], bh[0][3]);
                mma16816h(acc[mi][2], a[mi], bh[1][0], bh[1][2]);
                mma16816h(acc[mi][3], a[mi], bh[1][1], bh[1][3]);
            }
            // pass 2: Al x B (skipped when Alo == nullptr)
            if (Alo) {
#pragma unroll
                for (int mi = 0; mi < 4; mi++)
                    ldsm4(a[mi], buf + 8192 + sw_off(wm + (mi << 4) + lr, cb));
#pragma unroll
                for (int mi = 0; mi < 4; mi++) {
                    mma16816h(acc[mi][0], a[mi], bh[0][0], bh[0][2]);
                    mma16816h(acc[mi][1], a[mi], bh[0][1], bh[0][3]);
                    mma16816h(acc[mi][2], a[mi], bh[1][0], bh[1][2]);
                    mma16816h(acc[mi][3], a[mi], bh[1][1], bh[1][3]);
                }
            }
        }
        // no bottom sync: next iteration's wait+sync protects stage reuse
    }

    const int crow = lane >> 2;
    const int ccol = (lane & 3) << 1;
#pragma unroll
    for (int ni = 0; ni < 4; ni++) {
        const int col = bn + wn + (ni << 3) + ccol;
        const float2 bv = *(const float2*)&bias[col];
#pragma unroll
        for (int mi = 0; mi < 4; mi++) {
            const int row = bm + wm + (mi << 4) + crow;
            const float v00 = acc[mi][ni][0] + bv.x, v01 = acc[mi][ni][1] + bv.y;
            const float v10 = acc[mi][ni][2] + bv.x, v11 = acc[mi][ni][3] + bv.y;
            if (Chi && Clo) {
                const float h00 = __half2float(__float2half(v00));
                const float h01 = __half2float(__float2half(v01));
                const float h10 = __half2float(__float2half(v10));
                const float h11 = __half2float(__float2half(v11));
                *(uint32_t*)&Chi[(size_t)row * DIMV + col] = pack_f16x2(h00, h01);
                *(uint32_t*)&Clo[(size_t)row * DIMV + col] = pack_f16x2(v00 - h00, v01 - h01);
                *(uint32_t*)&Chi[(size_t)(row + 8) * DIMV + col] = pack_f16x2(h10, h11);
                *(uint32_t*)&Clo[(size_t)(row + 8) * DIMV + col] = pack_f16x2(v10 - h10, v11 - h11);
            } else if (Chi) {
                *(uint32_t*)&Chi[(size_t)row * DIMV + col] = pack_f16x2(v00, v01);
                *(uint32_t*)&Chi[(size_t)(row + 8) * DIMV + col] = pack_f16x2(v10, v11);
            } else {
                *(float2*)&C[(size_t)row * DIMV + col] = make_float2(v00, v01);
                *(float2*)&C[(size_t)(row + 8) * DIMV + col] = make_float2(v10, v11);
            }
        }
    }
}

// fused Q/K/V projection: grid (8, 68, 3). V emitted as single fp16.
__global__ __launch_bounds__(256, 2)
void gemm_qkv_kernel(const __half* __restrict__ Ahi,
                     const __half* __restrict__ Alo,
                     const float* __restrict__ bq,
                     const float* __restrict__ bk,
                     const float* __restrict__ bv) {
    extern __shared__ char smem[];
    const uint32_t sb = smem_to_u32(smem);
    const int z = blockIdx.z;
    const __half* B = (z == 0) ? g_wqT : (z == 1) ? g_wkT : g_wvT;
    const float* bias = (z == 0) ? bq : (z == 1) ? bk : bv;
    float* C = (z == 0) ? g_q : (z == 1) ? g_k : nullptr;
    __half* Chi = (z == 2) ? g_vh : nullptr;
    gemm_core(Ahi, Alo, B, bias, C, Chi, nullptr, sb,
              blockIdx.y << 7, blockIdx.x << 7);
}

// output projection: A is single fp16 (attention output) -> 1-pass
__global__ __launch_bounds__(256, 2)
void gemm_out_kernel(const __half* __restrict__ Ahi,
                     const float* __restrict__ bias,
                     float* __restrict__ C) {
    extern __shared__ char smem[];
    const uint32_t sb = smem_to_u32(smem);
    gemm_core(Ahi, nullptr, g_woT, bias, C, nullptr, nullptr, sb,
              blockIdx.y << 7, blockIdx.x << 7);
}

// ---------------------------------------------------------------------------
// Fused RMSNorm + RoPE + fp16 emit. blockIdx.y: 0 = Q (split hi/lo, scaled),
// 1 = K (single fp16).
// ---------------------------------------------------------------------------
__global__ __launch_bounds__(256) void normrope_split_kernel(
    const float* __restrict__ srcq, const float* __restrict__ srck,
    const float* __restrict__ gq, const float* __restrict__ gk,
    const float* __restrict__ cs, const float* __restrict__ sn,
    __half* __restrict__ qhi, __half* __restrict__ qlo,
    __half* __restrict__ kh) {
    const int s = blockIdx.x;
    const int isq = (blockIdx.y == 0);
    const float* src = isq ? srcq : srck;
    const float* g = isq ? gq : gk;
    const float scale = isq ? 0.125f : 1.0f;
    const int tid = threadIdx.x;

    float4 v = *(const float4*)&src[(size_t)s * DIMV + (tid << 2)];
    float ss = v.x * v.x + v.y * v.y + v.z * v.z + v.w * v.w;
#pragma unroll
    for (int o = 16; o; o >>= 1) ss += __shfl_xor_sync(0xffffffffu, ss, o);

    __shared__ float red[8];
    __shared__ float rtot;
    if ((tid & 31) == 0) red[tid >> 5] = ss;
    __syncthreads();
    if (tid == 0) {
        float t = 0.f;
#pragma unroll
        for (int i = 0; i < 8; i++) t += red[i];
        rtot = rsqrtf(t * (1.0f / 1024.0f) + 1e-6f);
    }
    __syncthreads();
    const float r = rtot;

    float4 gv = *(const float4*)&g[tid << 2];
    const float a0 = v.x * r * gv.x, b0 = v.y * r * gv.y;
    const float a1 = v.z * r * gv.z, b1 = v.w * r * gv.w;

    const int p0 = tid << 1;
    const int r0 = p0 & 31, r1 = (p0 + 1) & 31;
    const float c0 = cs[s * 32 + r0], s0 = sn[s * 32 + r0];
    const float c1 = cs[s * 32 + r1], s1 = sn[s * 32 + r1];

    float o0 = (a0 * c0 - b0 * s0) * scale;
    float o1 = (a0 * s0 + b0 * c0) * scale;
    float o2 = (a1 * c1 - b1 * s1) * scale;
    float o3 = (a1 * s1 + b1 * c1) * scale;

    const size_t base = (size_t)s * DIMV + (tid << 2);
    if (isq) {
        __half h0, l0, h1, l1, h2, l2, h3, l3;
        hsplit(o0, h0, l0); hsplit(o1, h1, l1);
        hsplit(o2, h2, l2); hsplit(o3, h3, l3);
        *(uint32_t*)&qhi[base] = pack_f16x2(__half2float(h0), __half2float(h1));
        *(uint32_t*)&qhi[base + 2] = pack_f16x2(__half2float(h2), __half2float(h3));
        *(uint32_t*)&qlo[base] = pack_f16x2(__half2float(l0), __half2float(l1));
        *(uint32_t*)&qlo[base + 2] = pack_f16x2(__half2float(l2), __half2float(l3));
    } else {
        *(uint32_t*)&kh[base] = pack_f16x2(o0, o1);
        *(uint32_t*)&kh[base + 2] = pack_f16x2(o2, o3);
    }
}

// ===========================================================================
// Tensor-core flash attention. QK: fp16 2-pass (Qh+Ql)·K; PV: fp16 1-pass.
// Stage = K 8KB + V 8KB = 16KB; 2 stages = 32KB.
// ===========================================================================
#define ATT_STAGE 16384
#define ATT_SMEM  (2 * ATT_STAGE)

__global__ __launch_bounds__(128)
void attn_tc_kernel(const __half* __restrict__ qhi, const __half* __restrict__ qlo,
                    const __half* __restrict__ kh, const __half* __restrict__ vh,
                    __half* __restrict__ oh) {
    extern __shared__ char smem[];
    const uint32_t sb = smem_to_u32(smem);
    const int d = blockIdx.z, h = blockIdx.y;
    const int q0 = blockIdx.x << 6;
    const int tid = threadIdx.x;
    const int warp = tid >> 5, lane = tid & 31;
    const int wq = warp << 4;
    const int lr = lane & 15, lhf = lane >> 4;
    const int qr = lane >> 2, qc = (lane & 3) << 1;

    // prologue: borrow stage smem for Q hi/lo (16KB fits in 2 stages)
#pragma unroll
    for (int t = 0; t < 4; t++) {
        const int idx = tid + (t << 7);
        const int r = idx >> 3, ch = idx & 7;
        const int tok = dil2orig(d, q0 + r);
        const size_t go = (size_t)tok * DIMV + h * HD + (ch << 3);
        *(uint4*)(smem + att_off(r, ch)) = *(const uint4*)&qhi[go];
        *(uint4*)(smem + 8192 + att_off(r, ch)) = *(const uint4*)&qlo[go];
    }
    __syncthreads();

    uint32_t qh[4][4], ql[4][4];
#pragma unroll
    for (int s = 0; s < 4; s++) {
        ldsm4(qh[s], sb + att_off(wq + lr, (s << 1) + lhf));
        ldsm4(ql[s], sb + 8192 + att_off(wq + lr, (s << 1) + lhf));
    }
    __syncthreads();

    float m0 = -1e30f, m1 = -1e30f, l0 = 0.f, l1 = 0.f;
    float o[8][4];
#pragma unroll
    for (int j = 0; j < 8; j++)
#pragma unroll
        for (int k = 0; k < 4; k++) o[j][k] = 0.f;

    const int kt_lo = (q0 >= WIN) ? (q0 - WIN) : 0;
    const int kt_hi = min(SD, q0 + BQ + WIN);
    const int row0 = q0 + wq + qr, row1 = row0 + 8;

    auto stage_load = [&](int st, int kt) {
        const uint32_t stg = sb + st * ATT_STAGE;
#pragma unroll
        for (int t = 0; t < 8; t++) {
            const int cid = tid + (t << 7);
            const int buf = cid >> 9;          // 0..1
            const int idx = cid & 511;
            const int r = idx >> 3, ch = idx & 7;
            const int pk = kt + r;
            const int ok = pk < SREAL;
            const int tok = ok ? dil2orig(d, pk) : 0;
            const size_t go = ((size_t)tok * DIMV + h * HD + (ch << 3)) * 2;
            const char* src = (buf == 0) ? (const char*)kh : (const char*)vh;
            cp_async16z(stg + (buf << 13) + att_off(r, ch), src + go, ok ? 16 : 0);
        }
    };

    stage_load(0, kt_lo);
    CP_COMMIT();

    int st = 0;
    for (int kt = kt_lo; kt < kt_hi; kt += BK, st ^= 1) {
        CP_WAIT0();
        __syncthreads();
        if (kt + BK < kt_hi) { stage_load(st ^ 1, kt + BK); CP_COMMIT(); }

        const uint32_t sK = sb + st * ATT_STAGE;
        const uint32_t sV = sK + 8192;

        // --- scores: fp16 2-pass ---
        float c[8][4];
#pragma unroll
        for (int j = 0; j < 8; j++)
#pragma unroll
            for (int k = 0; k < 4; k++) c[j][k] = 0.f;

#pragma unroll
        for (int s = 0; s < 4; s++) {
#pragma unroll
            for (int g = 0; g < 4; g++) {
                uint32_t bh[4];
                ldsm4(bh, sK + att_off((g << 4) + lr, (s << 1) + lhf));
                mma16816h(c[2 * g],     qh[s], bh[0], bh[2]);
                mma16816h(c[2 * g + 1], qh[s], bh[1], bh[3]);
                mma16816h(c[2 * g],     ql[s], bh[0], bh[2]);
                mma16816h(c[2 * g + 1], ql[s], bh[1], bh[3]);
            }
        }

        const bool edge = (kt < q0 - WIN + BK) || (kt >= q0 + WIN);
        if (edge) {
#pragma unroll
            for (int j = 0; j < 8; j++) {
                const int pk = kt + (j << 3) + qc;
                if (abs(row0 - pk) > WIN)       c[j][0] = -1e9f;
                if (abs(row0 - pk - 1) > WIN)   c[j][1] = -1e9f;
                if (abs(row1 - pk) > WIN)       c[j][2] = -1e9f;
                if (abs(row1 - pk - 1) > WIN)   c[j][3] = -1e9f;
            }
        }

        // --- online softmax ---
        float tm0 = -1e30f, tm1 = -1e30f;
#pragma unroll
        for (int j = 0; j < 8; j++) {
            tm0 = fmaxf(tm0, fmaxf(c[j][0], c[j][1]));
            tm1 = fmaxf(tm1, fmaxf(c[j][2], c[j][3]));
        }
        tm0 = fmaxf(tm0, __shfl_xor_sync(0xffffffffu, tm0, 1));
        tm0 = fmaxf(tm0, __shfl_xor_sync(0xffffffffu, tm0, 2));
        tm1 = fmaxf(tm1, __shfl_xor_sync(0xffffffffu, tm1, 1));
        tm1 = fmaxf(tm1, __shfl_xor_sync(0xffffffffu, tm1, 2));

        const float mn0 = fmaxf(m0, tm0), mn1 = fmaxf(m1, tm1);
        const float cor0 = __expf(m0 - mn0), cor1 = __expf(m1 - mn1);
        m0 = mn0; m1 = mn1;

        float s0 = 0.f, s1 = 0.f;
#pragma unroll
        for (int j = 0; j < 8; j++) {
            c[j][0] = __expf(c[j][0] - mn0);
            c[j][1] = __expf(c[j][1] - mn0);
            c[j][2] = __expf(c[j][2] - mn1);
            c[j][3] = __expf(c[j][3] - mn1);
            s0 += c[j][0] + c[j][1];
            s1 += c[j][2] + c[j][3];
        }
        s0 += __shfl_xor_sync(0xffffffffu, s0, 1);
        s0 += __shfl_xor_sync(0xffffffffu, s0, 2);
        s1 += __shfl_xor_sync(0xffffffffu, s1, 1);
        s1 += __shfl_xor_sync(0xffffffffu, s1, 2);
        l0 = l0 * cor0 + s0;
        l1 = l1 * cor1 + s1;
#pragma unroll
        for (int j = 0; j < 8; j++) {
            o[j][0] *= cor0; o[j][1] *= cor0;
            o[j][2] *= cor1; o[j][3] *= cor1;
        }

        // --- PV: fp16 1-pass, P packed directly ---
#pragma unroll
        for (int s = 0; s < 4; s++) {
            uint32_t ap[4];
            ap[0] = pack_f16x2(c[2 * s][0],     c[2 * s][1]);
            ap[1] = pack_f16x2(c[2 * s][2],     c[2 * s][3]);
            ap[2] = pack_f16x2(c[2 * s + 1][0], c[2 * s + 1][1]);
            ap[3] = pack_f16x2(c[2 * s + 1][2], c[2 * s + 1][3]);
#pragma unroll
            for (int g = 0; g < 4; g++) {
                uint32_t bh[4];
                ldsm4t(bh, sV + att_off((s << 4) + lr, (g << 1) + lhf));
                mma16816h(o[2 * g],     ap, bh[0], bh[1]);
                mma16816h(o[2 * g + 1], ap, bh[2], bh[3]);
            }
        }
    }

    // epilogue: normalize, store single fp16 (feeds 1-pass out-GEMM)
    const float inv0 = 1.0f / l0, inv1 = 1.0f / l1;
    const int tok0 = dil2orig(d, row0);
    const int tok1 = dil2orig(d, row1);
#pragma unroll
    for (int j = 0; j < 8; j++) {
        const int col = h * HD + (j << 3) + qc;
        *(uint32_t*)&oh[(size_t)tok0 * DIMV + col] =
            pack_f16x2(o[j][0] * inv0, o[j][1] * inv0);
        *(uint32_t*)&oh[(size_t)tok1 * DIMV + col] =
            pack_f16x2(o[j][2] * inv1, o[j][3] * inv1);
    }
}

// ---------------------------------------------------------------------------
extern "C" void kernel_launch(void* const* d_in, const int* in_sizes, int n_in,
                              void* d_out, int out_size) {
    (void)in_sizes; (void)n_in; (void)out_size;
    const float* x  = (const float*)d_in[0];
    const float* fc = (const float*)d_in[1];
    const float* fs = (const float*)d_in[2];
    const float* wq = (const float*)d_in[3];
    const float* bq = (const float*)d_in[4];
    const float* wk = (const float*)d_in[5];
    const float* bk = (const float*)d_in[6];
    const float* wv = (const float*)d_in[7];
    const float* bv = (const float*)d_in[8];
    const float* wo = (const float*)d_in[9];
    const float* bo = (const float*)d_in[10];
    const float* gq = (const float*)d_in[11];
    const float* gk = (const float*)d_in[12];
    float* out = (float*)d_out;

    float *qb, *kb;
    cudaGetSymbolAddress((void**)&qb, g_q);
    cudaGetSymbolAddress((void**)&kb, g_k);
    __half *ahi, *alo, *vh, *qhi, *qlo, *kh;
    cudaGetSymbolAddress((void**)&ahi, g_ahi);
    cudaGetSymbolAddress((void**)&alo, g_alo);
    cudaGetSymbolAddress((void**)&vh, g_vh);
    cudaGetSymbolAddress((void**)&qhi, g_qhi);
    cudaGetSymbolAddress((void**)&qlo, g_qlo);
    cudaGetSymbolAddress((void**)&kh, g_kh);

    cudaFuncSetAttribute(gemm_qkv_kernel,
                         cudaFuncAttributeMaxDynamicSharedMemorySize, GEMM_SMEM_REQ);
    cudaFuncSetAttribute(gemm_out_kernel,
                         cudaFuncAttributeMaxDynamicSharedMemorySize, GEMM_SMEM_REQ);
    cudaFuncSetAttribute(attn_tc_kernel,
                         cudaFuncAttributeMaxDynamicSharedMemorySize, ATT_SMEM);

    wsplit_all_kernel<<<dim3(32, 32, 4), 256>>>(wq, wk, wv, wo);
    split_kernel<<<(S_LEN * DIMV) / 1024, 256>>>(x, ahi, alo);
    gemm_qkv_kernel<<<dim3(DIMV / 128, S_LEN / 128, 3), 256, GEMM_SMEM_REQ>>>(
        ahi, alo, bq, bk, bv);
    normrope_split_kernel<<<dim3(S_LEN, 2), 256>>>(qb, kb, gq, gk, fc, fs,
                                                   qhi, qlo, kh);
    attn_tc_kernel<<<dim3(SREAL / BQ, NH, 2), 128, ATT_SMEM>>>(
        qhi, qlo, kh, vh, ahi);
    gemm_out_kernel<<<dim3(DIMV / 128, S_LEN / 128), 256, GEMM_SMEM_REQ>>>(
        ahi, bo, out);
}